// round 11
// baseline (speedup 1.0000x reference)
#include <cuda_runtime.h>
#include <cuda_bf16.h>
#include <cstdint>

// ---------------------------------------------------------------------------
// MultiheadRelativeAttention: B=4, T=1024, E=1024, H=16, D=64, MAX_REL=128
// Round 11: revert to round-8 bf16 3-term pipeline (fp16 regressed); GEMM CTA
// tile 128x64 to cut wave-quantization tails (768->1536 / 256->512 CTAs).
// ---------------------------------------------------------------------------

#define MROWS 4096      // B*T
#define EDIM  1024
#define RSTR  260       // padded stride for 257 relative positions

typedef unsigned long long u64t;

__device__ float g_B [64 * 1024 * RSTR];   // bias table per source slot
__device__ float g_c1[MROWS * EDIM];
__device__ float g_c2[MROWS * EDIM];

// bf16 split buffers
__device__ __nv_bfloat16 g_Xh[MROWS * EDIM];
__device__ __nv_bfloat16 g_Xl[MROWS * EDIM];
__device__ __nv_bfloat16 g_Wqh[EDIM * EDIM], g_Wql[EDIM * EDIM];
__device__ __nv_bfloat16 g_Wkh[EDIM * EDIM], g_Wkl[EDIM * EDIM];
__device__ __nv_bfloat16 g_Wvh[EDIM * EDIM], g_Wvl[EDIM * EDIM];
__device__ __nv_bfloat16 g_Woh[EDIM * EDIM], g_Wol[EDIM * EDIM];
__device__ __nv_bfloat16 g_Qbh[MROWS * EDIM], g_Qbl[MROWS * EDIM];
__device__ __nv_bfloat16 g_Kbh[MROWS * EDIM], g_Kbl[MROWS * EDIM];
__device__ __nv_bfloat16 g_Vbh[MROWS * EDIM], g_Vbl[MROWS * EDIM];
__device__ __nv_bfloat16 g_Rkh[320 * 64], g_Rkl[320 * 64];  // relk split, zero-padded

// ---------------------------------------------------------------------------
// helpers
// ---------------------------------------------------------------------------
__device__ __forceinline__ uint32_t smem_to_u32(const void* p) {
    uint32_t a;
    asm("{ .reg .u64 t; cvta.to.shared.u64 t, %1; cvt.u32.u64 %0, t; }" : "=r"(a) : "l"(p));
    return a;
}
__device__ __forceinline__ void cpasync16(uint32_t dst, const void* src) {
    asm volatile("cp.async.cg.shared.global [%0], [%1], 16;" :: "r"(dst), "l"(src));
}
#define CP_COMMIT() asm volatile("cp.async.commit_group;" ::: "memory")
#define CP_WAIT(n)  asm volatile("cp.async.wait_group %0;" :: "n"(n) : "memory")

__device__ __forceinline__ void ldsm4(uint32_t* r, uint32_t addr) {
    asm volatile("ldmatrix.sync.aligned.m8n8.x4.shared.b16 {%0,%1,%2,%3}, [%4];"
                 : "=r"(r[0]), "=r"(r[1]), "=r"(r[2]), "=r"(r[3]) : "r"(addr));
}
__device__ __forceinline__ void ldsm4t(uint32_t* r, uint32_t addr) {
    asm volatile("ldmatrix.sync.aligned.m8n8.x4.trans.shared.b16 {%0,%1,%2,%3}, [%4];"
                 : "=r"(r[0]), "=r"(r[1]), "=r"(r[2]), "=r"(r[3]) : "r"(addr));
}
__device__ __forceinline__ void mma16816(float* c, const uint32_t* a, uint32_t b0, uint32_t b1) {
    asm volatile("mma.sync.aligned.m16n8k16.row.col.f32.bf16.bf16.f32 "
                 "{%0,%1,%2,%3}, {%4,%5,%6,%7}, {%8,%9}, {%0,%1,%2,%3};"
                 : "+f"(c[0]), "+f"(c[1]), "+f"(c[2]), "+f"(c[3])
                 : "r"(a[0]), "r"(a[1]), "r"(a[2]), "r"(a[3]), "r"(b0), "r"(b1));
}
__device__ __forceinline__ uint32_t pack_bf2(__nv_bfloat16 lo, __nv_bfloat16 hi) {
    return ((uint32_t)__bfloat16_as_ushort(hi) << 16) | (uint32_t)__bfloat16_as_ushort(lo);
}

// f32x2 packed helpers (w2 epilogue)
__device__ __forceinline__ u64t pk2(float x) {
    u64t r; asm("mov.b64 %0, {%1, %1};" : "=l"(r) : "f"(x)); return r;
}
__device__ __forceinline__ void fma2(u64t& d, u64t a, u64t b) {
    asm("fma.rn.f32x2 %0, %1, %2, %0;" : "+l"(d) : "l"(a), "l"(b));
}
__device__ __forceinline__ float2 unpk(u64t v) {
    float2 f; asm("mov.b64 {%0, %1}, %2;" : "=f"(f.x), "=f"(f.y) : "l"(v)); return f;
}

// ---------------------------------------------------------------------------
// conversions
// ---------------------------------------------------------------------------
__global__ __launch_bounds__(256)
void cvt_split(const float* __restrict__ src, __nv_bfloat16* __restrict__ hi,
               __nv_bfloat16* __restrict__ lo)
{
    const int i = (blockIdx.x * 256 + threadIdx.x) * 4;
    float4 v = *(const float4*)(src + i);
    __nv_bfloat16 h0 = __float2bfloat16(v.x), h1 = __float2bfloat16(v.y);
    __nv_bfloat16 h2 = __float2bfloat16(v.z), h3 = __float2bfloat16(v.w);
    ((uint32_t*)(hi + i))[0] = pack_bf2(h0, h1);
    ((uint32_t*)(hi + i))[1] = pack_bf2(h2, h3);
    ((uint32_t*)(lo + i))[0] = pack_bf2(__float2bfloat16(v.x - __bfloat162float(h0)),
                                        __float2bfloat16(v.y - __bfloat162float(h1)));
    ((uint32_t*)(lo + i))[1] = pack_bf2(__float2bfloat16(v.z - __bfloat162float(h2)),
                                        __float2bfloat16(v.w - __bfloat162float(h3)));
}

// merged 4-weight split: grid.y selects the matrix
__global__ __launch_bounds__(256)
void cvt_w4(const float* __restrict__ w0, const float* __restrict__ w1,
            const float* __restrict__ w2, const float* __restrict__ w3,
            __nv_bfloat16* __restrict__ h0p, __nv_bfloat16* __restrict__ l0p,
            __nv_bfloat16* __restrict__ h1p, __nv_bfloat16* __restrict__ l1p,
            __nv_bfloat16* __restrict__ h2p, __nv_bfloat16* __restrict__ l2p,
            __nv_bfloat16* __restrict__ h3p, __nv_bfloat16* __restrict__ l3p)
{
    const int y = blockIdx.y;
    const float* src = (y == 0) ? w0 : (y == 1) ? w1 : (y == 2) ? w2 : w3;
    __nv_bfloat16* hi = (y == 0) ? h0p : (y == 1) ? h1p : (y == 2) ? h2p : h3p;
    __nv_bfloat16* lo = (y == 0) ? l0p : (y == 1) ? l1p : (y == 2) ? l2p : l3p;
    const int i = (blockIdx.x * 256 + threadIdx.x) * 4;
    float4 v = *(const float4*)(src + i);
    __nv_bfloat16 h0 = __float2bfloat16(v.x), h1 = __float2bfloat16(v.y);
    __nv_bfloat16 h2 = __float2bfloat16(v.z), h3 = __float2bfloat16(v.w);
    ((uint32_t*)(hi + i))[0] = pack_bf2(h0, h1);
    ((uint32_t*)(hi + i))[1] = pack_bf2(h2, h3);
    ((uint32_t*)(lo + i))[0] = pack_bf2(__float2bfloat16(v.x - __bfloat162float(h0)),
                                        __float2bfloat16(v.y - __bfloat162float(h1)));
    ((uint32_t*)(lo + i))[1] = pack_bf2(__float2bfloat16(v.z - __bfloat162float(h2)),
                                        __float2bfloat16(v.w - __bfloat162float(h3)));
}

__global__ __launch_bounds__(256)
void cvt_add_split(const float* __restrict__ a, const float* __restrict__ b,
                   __nv_bfloat16* __restrict__ hi, __nv_bfloat16* __restrict__ lo)
{
    const int i = (blockIdx.x * 256 + threadIdx.x) * 4;
    float4 va = *(const float4*)(a + i);
    float4 vb = *(const float4*)(b + i);
    float4 v = make_float4(va.x + vb.x, va.y + vb.y, va.z + vb.z, va.w + vb.w);
    __nv_bfloat16 h0 = __float2bfloat16(v.x), h1 = __float2bfloat16(v.y);
    __nv_bfloat16 h2 = __float2bfloat16(v.z), h3 = __float2bfloat16(v.w);
    ((uint32_t*)(hi + i))[0] = pack_bf2(h0, h1);
    ((uint32_t*)(hi + i))[1] = pack_bf2(h2, h3);
    ((uint32_t*)(lo + i))[0] = pack_bf2(__float2bfloat16(v.x - __bfloat162float(h0)),
                                        __float2bfloat16(v.y - __bfloat162float(h1)));
    ((uint32_t*)(lo + i))[1] = pack_bf2(__float2bfloat16(v.z - __bfloat162float(h2)),
                                        __float2bfloat16(v.w - __bfloat162float(h3)));
}

// relk -> zero-padded [320][64] bf16 split
__global__ __launch_bounds__(256)
void cvt_relk(const float* __restrict__ relk, __nv_bfloat16* __restrict__ rh,
              __nv_bfloat16* __restrict__ rl)
{
    const int i = blockIdx.x * 256 + threadIdx.x;   // 0..20479
    if (i >= 320 * 64) return;
    const int r = i >> 6, d = i & 63;
    const float v = (r < 257) ? relk[r * 64 + d] : 0.f;
    const __nv_bfloat16 h = __float2bfloat16(v);
    rh[i] = h;
    rl[i] = __float2bfloat16(v - __bfloat162float(h));
}

// ---------------------------------------------------------------------------
// GEMM core: C = alpha*(Ah+Al)(Bh+Bl)^T + alpha*bias (C nullable); optional
// bf16 split of result. 128x64 CTA tile (8 warps, 4m x 2n, warp tile 32x32),
// K chunks of 64, 3-stage cp.async pipe.
// Stage layout (48KB): Ah[0,16K) Al[16K,32K) Bh[32K,40K) Bl[40K,48K)
// ---------------------------------------------------------------------------
#define GSTAGE 49152
#define GSMEM  (3 * GSTAGE)

__device__ __forceinline__ void gemm_core(
    const __nv_bfloat16* __restrict__ Ah, const __nv_bfloat16* __restrict__ Al,
    const __nv_bfloat16* __restrict__ Bh, const __nv_bfloat16* __restrict__ Bl,
    const float* __restrict__ bias, float* __restrict__ C, float alpha,
    __nv_bfloat16* __restrict__ ohi, __nv_bfloat16* __restrict__ olo)
{
    extern __shared__ char smem[];
    const uint32_t sb = smem_to_u32(smem);
    const int tid = threadIdx.x;
    const int wid = tid >> 5, lane = tid & 31;
    const int wm = wid >> 1, wn = wid & 1;           // 4(m) x 2(n) warp grid
    const int n0 = blockIdx.x * 64, m0 = blockIdx.y * 128;

    float acc[2][4][4];
#pragma unroll
    for (int f = 0; f < 2; f++)
#pragma unroll
        for (int nf = 0; nf < 4; nf++)
#pragma unroll
            for (int e = 0; e < 4; e++) acc[f][nf][e] = 0.f;

    auto issue = [&](int stage, int c) {
        const uint32_t tbs = sb + stage * GSTAGE;
        const int k0 = c * 64;
        // A: 128 rows x 128B (hi+lo)
#pragma unroll
        for (int g = 0; g < 4; g++) {
            const int gi = g * 256 + tid;            // 0..1023
            const int row = gi >> 3, gc = gi & 7;
            const uint32_t bo = row * 128 + gc * 16;
            const uint32_t sw = bo ^ ((bo >> 3) & 0x70);
            const size_t aoff = (size_t)(m0 + row) * EDIM + k0 + gc * 8;
            cpasync16(tbs + sw,         Ah + aoff);
            cpasync16(tbs + 16384 + sw, Al + aoff);
        }
        // B: 64 rows x 128B (hi+lo)
#pragma unroll
        for (int g = 0; g < 2; g++) {
            const int gi = g * 256 + tid;            // 0..511
            const int row = gi >> 3, gc = gi & 7;
            const uint32_t bo = row * 128 + gc * 16;
            const uint32_t sw = bo ^ ((bo >> 3) & 0x70);
            const size_t boff = (size_t)(n0 + row) * EDIM + k0 + gc * 8;
            cpasync16(tbs + 32768 + sw, Bh + boff);
            cpasync16(tbs + 40960 + sw, Bl + boff);
        }
        CP_COMMIT();
    };

    issue(0, 0);
    issue(1, 1);

    const int arow = lane & 15;
    const int achk = lane >> 4;

    for (int c = 0; c < 16; c++) {
        if (c + 2 < 16) issue((c + 2) % 3, c + 2);
        if (c <= 13)      { CP_WAIT(2); }
        else if (c == 14) { CP_WAIT(1); }
        else              { CP_WAIT(0); }
        __syncthreads();

        const uint32_t st = sb + (c % 3) * GSTAGE;
#pragma unroll
        for (int kk = 0; kk < 4; kk++) {
            const int chS = (kk * 2 + achk) ^ (arow & 7);
            uint32_t ah[2][4], al[2][4], bh[2][4], bl[2][4];
#pragma unroll
            for (int f = 0; f < 2; f++) {
                const uint32_t ra = st + (uint32_t)(wm * 32 + f * 16 + arow) * 128 + chS * 16;
                ldsm4(ah[f], ra);
                ldsm4(al[f], ra + 16384);
            }
#pragma unroll
            for (int nb = 0; nb < 2; nb++) {
                const uint32_t rb = st + 32768 + (uint32_t)(wn * 32 + nb * 16 + arow) * 128 + chS * 16;
                ldsm4(bh[nb], rb);
                ldsm4(bl[nb], rb + 8192);
            }
#pragma unroll
            for (int f = 0; f < 2; f++)
#pragma unroll
                for (int nb = 0; nb < 2; nb++)
#pragma unroll
                    for (int h = 0; h < 2; h++) {
                        float* cc = acc[f][nb * 2 + h];
                        mma16816(cc, ah[f], bh[nb][h], bh[nb][h + 2]);
                        mma16816(cc, ah[f], bl[nb][h], bl[nb][h + 2]);
                        mma16816(cc, al[f], bh[nb][h], bh[nb][h + 2]);
                    }
        }
        __syncthreads();
    }

    const int gid = lane >> 2, tig = lane & 3;
#pragma unroll
    for (int f = 0; f < 2; f++) {
        const int m = m0 + wm * 32 + f * 16 + gid;
#pragma unroll
        for (int nb = 0; nb < 2; nb++)
#pragma unroll
            for (int h = 0; h < 2; h++) {
                const int n = n0 + wn * 32 + nb * 16 + h * 8 + tig * 2;
                const float* cc = acc[f][nb * 2 + h];
                const float b0 = __ldg(&bias[n]), b1 = __ldg(&bias[n + 1]);
                float2 v0 = make_float2(alpha * (cc[0] + b0), alpha * (cc[1] + b1));
                float2 v1 = make_float2(alpha * (cc[2] + b0), alpha * (cc[3] + b1));
                if (C) {
                    *(float2*)&C[(size_t)m * EDIM + n]       = v0;
                    *(float2*)&C[(size_t)(m + 8) * EDIM + n] = v1;
                }
                if (ohi) {
                    __nv_bfloat16 h00 = __float2bfloat16(v0.x), h01 = __float2bfloat16(v0.y);
                    __nv_bfloat16 h10 = __float2bfloat16(v1.x), h11 = __float2bfloat16(v1.y);
                    *(uint32_t*)(ohi + (size_t)m * EDIM + n)       = pack_bf2(h00, h01);
                    *(uint32_t*)(ohi + (size_t)(m + 8) * EDIM + n) = pack_bf2(h10, h11);
                    *(uint32_t*)(olo + (size_t)m * EDIM + n) =
                        pack_bf2(__float2bfloat16(v0.x - __bfloat162float(h00)),
                                 __float2bfloat16(v0.y - __bfloat162float(h01)));
                    *(uint32_t*)(olo + (size_t)(m + 8) * EDIM + n) =
                        pack_bf2(__float2bfloat16(v1.x - __bfloat162float(h10)),
                                 __float2bfloat16(v1.y - __bfloat162float(h11)));
                }
            }
    }
}

__global__ __launch_bounds__(256, 1)
void mma_gemm(const __nv_bfloat16* __restrict__ Ah, const __nv_bfloat16* __restrict__ Al,
              const __nv_bfloat16* __restrict__ Bh, const __nv_bfloat16* __restrict__ Bl,
              const float* __restrict__ bias, float* __restrict__ C, float alpha,
              __nv_bfloat16* __restrict__ ohi, __nv_bfloat16* __restrict__ olo)
{
    gemm_core(Ah, Al, Bh, Bl, bias, C, alpha, ohi, olo);
}

// merged QKV: grid.z selects the weight/bias/output set
struct G3Params {
    const __nv_bfloat16* Bh[3]; const __nv_bfloat16* Bl[3];
    const float* bias[3];
    __nv_bfloat16* oh[3]; __nv_bfloat16* ol[3];
    float alpha[3];
};
__global__ __launch_bounds__(256, 1)
void mma_gemm3(const __nv_bfloat16* __restrict__ Ah, const __nv_bfloat16* __restrict__ Al,
               G3Params p)
{
    const int z = blockIdx.z;
    gemm_core(Ah, Al, p.Bh[z], p.Bl[z], p.bias[z], nullptr, p.alpha[z], p.oh[z], p.ol[z]);
}

// ---------------------------------------------------------------------------
// Bias table via mma: Bt[j][q][r] = Qs[j,q,:] . relk[r,:]  (Q already *0.125)
// ---------------------------------------------------------------------------
#define BIAS_SMEM 32768
__global__ __launch_bounds__(128, 1)
void bias_mma(const __nv_bfloat16* __restrict__ Qbh, const __nv_bfloat16* __restrict__ Qbl,
              const __nv_bfloat16* __restrict__ Rh, const __nv_bfloat16* __restrict__ Rl,
              float* __restrict__ Bt)
{
    extern __shared__ char smem[];
    const uint32_t sb = smem_to_u32(smem);
    const int jslot = blockIdx.z;
    const int bb = jslot >> 4, hh = jslot & 15;
    const int q0 = blockIdx.y * 64;
    const int r0 = blockIdx.x * 64;
    const int tid = threadIdx.x, wid = tid >> 5, lane = tid & 31;
    const int wm = wid >> 1, wn = wid & 1;
    const int arow = lane & 15, ahalf = lane >> 4;

#pragma unroll
    for (int g = 0; g < 4; g++) {
        const int i = g * 128 + tid;             // 0..511
        const int row = i >> 3, c = i & 7;
        const uint32_t sw = (uint32_t)row * 128 + (uint32_t)((c ^ (row & 7)) * 16);
        const size_t qo = (size_t)(bb * 1024 + q0 + row) * EDIM + hh * 64 + c * 8;
        const size_t ro = (size_t)(r0 + row) * 64 + c * 8;
        cpasync16(sb + sw,         Qbh + qo);
        cpasync16(sb + 8192 + sw,  Qbl + qo);
        cpasync16(sb + 16384 + sw, Rh + ro);
        cpasync16(sb + 24576 + sw, Rl + ro);
    }
    CP_COMMIT();
    CP_WAIT(0);
    __syncthreads();

    float s[2][4][4];
#pragma unroll
    for (int mf = 0; mf < 2; mf++)
#pragma unroll
        for (int nf = 0; nf < 4; nf++)
#pragma unroll
            for (int e = 0; e < 4; e++) s[mf][nf][e] = 0.f;

#pragma unroll
    for (int dd = 0; dd < 4; dd++) {
        uint32_t ah[2][4], al[2][4], bh[2][4], bl[2][4];
#pragma unroll
        for (int mf = 0; mf < 2; mf++) {
            const int row = wm * 32 + mf * 16 + arow;
            const uint32_t addr = sb + (uint32_t)row * 128 +
                                  (uint32_t)(((dd * 2 + ahalf) ^ (row & 7)) * 16);
            ldsm4(ah[mf], addr);
            ldsm4(al[mf], addr + 8192);
        }
#pragma unroll
        for (int ng = 0; ng < 2; ng++) {
            const int row = wn * 32 + ng * 16 + arow;
            const uint32_t addr = sb + 16384 + (uint32_t)row * 128 +
                                  (uint32_t)(((dd * 2 + ahalf) ^ (row & 7)) * 16);
            ldsm4(bh[ng], addr);
            ldsm4(bl[ng], addr + 8192);
        }
#pragma unroll
        for (int mf = 0; mf < 2; mf++)
#pragma unroll
            for (int ng = 0; ng < 2; ng++)
#pragma unroll
                for (int h = 0; h < 2; h++) {
                    float* cc = s[mf][ng * 2 + h];
                    mma16816(cc, ah[mf], bh[ng][h], bh[ng][h + 2]);
                    mma16816(cc, ah[mf], bl[ng][h], bl[ng][h + 2]);
                    mma16816(cc, al[mf], bh[ng][h], bh[ng][h + 2]);
                }
    }

    const int gid = lane >> 2, tig = lane & 3;
    float* btj = Bt + (size_t)jslot * 1024 * RSTR;
#pragma unroll
    for (int mf = 0; mf < 2; mf++) {
        const int q = q0 + wm * 32 + mf * 16 + gid;
#pragma unroll
        for (int nf = 0; nf < 4; nf++) {
            const int r = r0 + wn * 32 + nf * 8 + tig * 2;
            const float* cc = s[mf][nf];
            if (r < 257) {
                btj[(size_t)q * RSTR + r]       = cc[0];
                btj[(size_t)(q + 8) * RSTR + r] = cc[2];
            }
            if (r + 1 < 257) {
                btj[(size_t)q * RSTR + r + 1]       = cc[1];
                btj[(size_t)(q + 8) * RSTR + r + 1] = cc[3];
            }
        }
    }
}

// ---------------------------------------------------------------------------
// MMA-based fused relative attention (round-8 proven version).
// ---------------------------------------------------------------------------
#define ASTG 32768
#define ATT_SMEM (115712 + 64 * RSTR * 4)   // 182272

__global__ __launch_bounds__(256, 1)
void attn2(const __nv_bfloat16* __restrict__ Qh_, const __nv_bfloat16* __restrict__ Ql_,
           const __nv_bfloat16* __restrict__ Kh_, const __nv_bfloat16* __restrict__ Kl_,
           const __nv_bfloat16* __restrict__ Vh_, const __nv_bfloat16* __restrict__ Vl_,
           const float* __restrict__ Bt, const float* __restrict__ relv,
           float* __restrict__ c1, float* __restrict__ c2)
{
    extern __shared__ char smem[];
    const uint32_t sb = smem_to_u32(smem);
    float* lsum = (float*)(smem + 114688);
    float* Aa   = (float*)(smem + 115712);

    const int slot = blockIdx.y;
    const int q0 = blockIdx.x * 64;
    const int bb = slot >> 4, hh = slot & 15;
    const int jsrc = ((slot & 15) << 2) | (slot >> 4);   // sigma(slot)
    const int tid = threadIdx.x, wid = tid >> 5, lane = tid & 31;
    const int wm = wid >> 1, wn = wid & 1;
    const int gid = lane >> 2, tig = lane & 3;
    const int arow = lane & 15, ahalf = lane >> 4;

    for (int f = tid; f < 64 * RSTR; f += 256) Aa[f] = 0.f;
    if (tid < 64) lsum[tid] = 0.f;

    auto issueKV = [&](int stg, int kt) {
        const uint32_t base = sb + 16384 + stg * ASTG;
        const int k0 = kt * 64;
#pragma unroll
        for (int g = 0; g < 2; g++) {
            const int i = g * 256 + tid;
            const int row = i >> 3, c = i & 7;
            const uint32_t sw = (uint32_t)row * 128 + (uint32_t)((c ^ (row & 7)) * 16);
            const size_t go = (size_t)(bb * 1024 + k0 + row) * EDIM + hh * 64 + c * 8;
            cpasync16(base + sw,         Kh_ + go);
            cpasync16(base + 8192 + sw,  Kl_ + go);
            cpasync16(base + 16384 + sw, Vh_ + go);
            cpasync16(base + 24576 + sw, Vl_ + go);
        }
    };

    // group 0: Q + KV0 ; group 1: KV1
#pragma unroll
    for (int g = 0; g < 2; g++) {
        const int i = g * 256 + tid;
        const int row = i >> 3, c = i & 7;
        const uint32_t sw = (uint32_t)row * 128 + (uint32_t)((c ^ (row & 7)) * 16);
        const size_t go = (size_t)(bb * 1024 + q0 + row) * EDIM + hh * 64 + c * 8;
        cpasync16(sb + sw,        Qh_ + go);
        cpasync16(sb + 8192 + sw, Ql_ + go);
    }
    issueKV(0, 0);
    CP_COMMIT();
    issueKV(1, 1);
    CP_COMMIT();

    uint32_t qfh[4][4], qfl[4][4];
    float o[8][4];
#pragma unroll
    for (int nf = 0; nf < 8; nf++)
#pragma unroll
        for (int e = 0; e < 4; e++) o[nf][e] = 0.f;

    const float* btq = Bt + (size_t)jsrc * 1024 * RSTR + (size_t)q0 * RSTR;
    const int row0l = wm * 16 + gid, row1l = row0l + 8;

    // tile-invariant clamped-bias values (bias row at r=0 / r=256)
    const float bc0_lo = __ldg(&btq[(size_t)row0l * RSTR + 0]);
    const float bc0_hi = __ldg(&btq[(size_t)row0l * RSTR + 256]);
    const float bc1_lo = __ldg(&btq[(size_t)row1l * RSTR + 0]);
    const float bc1_hi = __ldg(&btq[(size_t)row1l * RSTR + 256]);
    // deferred accumulators: row sums + clamped buckets
    float ls0 = 0.f, ls1 = 0.f, lo0 = 0.f, lo1 = 0.f, hi0 = 0.f, hi1 = 0.f;

    for (int kt = 0; kt < 16; kt++) {
        if (kt + 2 < 16) { issueKV((kt + 2) % 3, kt + 2); CP_COMMIT(); }
        if (kt <= 13)      { CP_WAIT(2); }
        else if (kt == 14) { CP_WAIT(1); }
        else               { CP_WAIT(0); }
        __syncthreads();
        if (kt == 0) {
#pragma unroll
            for (int dd = 0; dd < 4; dd++) {
                const int row = wm * 16 + arow;
                const uint32_t addr = sb + (uint32_t)row * 128 +
                                      (uint32_t)(((dd * 2 + ahalf) ^ (row & 7)) * 16);
                ldsm4(qfh[dd], addr);
                ldsm4(qfl[dd], addr + 8192);
            }
        }
        const uint32_t st = sb + 16384 + (kt % 3) * ASTG;
        const int k0 = kt * 64;
        const int delta = q0 - k0;

        // ---- S = Q K^T (bf16 split, 3 terms) ----
        float s[4][4];
#pragma unroll
        for (int nf = 0; nf < 4; nf++)
#pragma unroll
            for (int e = 0; e < 4; e++) s[nf][e] = 0.f;
#pragma unroll
        for (int dd = 0; dd < 4; dd++) {
            uint32_t kbh[2][4], kbl[2][4];
#pragma unroll
            for (int g = 0; g < 2; g++) {
                const int row = wn * 32 + g * 16 + arow;
                const uint32_t addr = st + (uint32_t)row * 128 +
                                      (uint32_t)(((dd * 2 + ahalf) ^ (row & 7)) * 16);
                ldsm4(kbh[g], addr);
                ldsm4(kbl[g], addr + 8192);
            }
#pragma unroll
            for (int g = 0; g < 2; g++)
#pragma unroll
                for (int h = 0; h < 2; h++) {
                    float* cc = s[g * 2 + h];
                    mma16816(cc, qfh[dd], kbh[g][h], kbh[g][h + 2]);
                    mma16816(cc, qfh[dd], kbl[g][h], kbl[g][h + 2]);
                    mma16816(cc, qfl[dd], kbh[g][h], kbh[g][h + 2]);
                }
        }

        // ---- bias + exp + row sums (+ buckets) ----
        float rs0 = 0.f, rs1 = 0.f;
        const bool clampHi = (delta >= 192), clampLo = (delta <= -192);
        if (clampHi || clampLo) {
            const float b0 = clampHi ? bc0_hi : bc0_lo;
            const float b1 = clampHi ? bc1_hi : bc1_lo;
#pragma unroll
            for (int nf = 0; nf < 4; nf++)
#pragma unroll
                for (int e = 0; e < 4; e++) {
                    const float p = __expf(s[nf][e] + ((e >= 2) ? b1 : b0));
                    s[nf][e] = p;
                    if (e >= 2) rs1 += p; else rs0 += p;
                }
            if (clampHi) { hi0 += rs0; hi1 += rs1; }
            else         { lo0 += rs0; lo1 += rs1; }
        } else {
#pragma unroll
            for (int nf = 0; nf < 4; nf++) {
                const int kg = k0 + wn * 32 + nf * 8 + tig * 2;
#pragma unroll
                for (int e = 0; e < 4; e++) {
                    const int ql = (e >= 2) ? row1l : row0l;
                    const int dist = (q0 + ql) - (kg + (e & 1));
                    const int r = dist < -128 ? 0 : (dist > 128 ? 256 : dist + 128);
                    const float p = __expf(s[nf][e] + __ldg(&btq[(size_t)ql * RSTR + r]));
                    s[nf][e] = p;
                    if (e >= 2) rs1 += p; else rs0 += p;
                    atomicAdd(&Aa[ql * RSTR + r], p);
                }
            }
        }
        ls0 += rs0; ls1 += rs1;

        // ---- P -> bf16 split A-frags ----
        uint32_t pah[2][4], pal[2][4];
#pragma unroll
        for (int b = 0; b < 2; b++)
#pragma unroll
            for (int a = 0; a < 4; a++) {
                const int nf = b * 2 + (a >> 1);
                const int eb = (a & 1) * 2;
                const float p0 = s[nf][eb], p1 = s[nf][eb + 1];
                const __nv_bfloat16 h0 = __float2bfloat16(p0), h1 = __float2bfloat16(p1);
                pah[b][a] = pack_bf2(h0, h1);
                pal[b][a] = pack_bf2(__float2bfloat16(p0 - __bfloat162float(h0)),
                                     __float2bfloat16(p1 - __bfloat162float(h1)));
            }

        // ---- O += P V ----
#pragma unroll
        for (int b = 0; b < 2; b++)
#pragma unroll
            for (int g = 0; g < 4; g++) {
                uint32_t vbh[4], vbl[4];
                const int krow = wn * 32 + b * 16 + arow;
                const uint32_t addr = st + 16384 + (uint32_t)krow * 128 +
                                      (uint32_t)(((g * 2 + ahalf) ^ (krow & 7)) * 16);
                ldsm4t(vbh, addr);
                ldsm4t(vbl, addr + 8192);
#pragma unroll
                for (int h = 0; h < 2; h++) {
                    float* cc = o[g * 2 + h];
                    mma16816(cc, pah[b], vbh[h * 2], vbh[h * 2 + 1]);
                    mma16816(cc, pah[b], vbl[h * 2], vbl[h * 2 + 1]);
                    mma16816(cc, pal[b], vbh[h * 2], vbh[h * 2 + 1]);
                }
            }
        __syncthreads();
    }

    // ---- flush deferred reductions (quad shfl + one atomic each) ----
    ls0 += __shfl_xor_sync(0xffffffffu, ls0, 1); ls0 += __shfl_xor_sync(0xffffffffu, ls0, 2);
    ls1 += __shfl_xor_sync(0xffffffffu, ls1, 1); ls1 += __shfl_xor_sync(0xffffffffu, ls1, 2);
    lo0 += __shfl_xor_sync(0xffffffffu, lo0, 1); lo0 += __shfl_xor_sync(0xffffffffu, lo0, 2);
    lo1 += __shfl_xor_sync(0xffffffffu, lo1, 1); lo1 += __shfl_xor_sync(0xffffffffu, lo1, 2);
    hi0 += __shfl_xor_sync(0xffffffffu, hi0, 1); hi0 += __shfl_xor_sync(0xffffffffu, hi0, 2);
    hi1 += __shfl_xor_sync(0xffffffffu, hi1, 1); hi1 += __shfl_xor_sync(0xffffffffu, hi1, 2);
    if (tig == 0) {
        atomicAdd(&lsum[row0l], ls0);
        atomicAdd(&lsum[row1l], ls1);
        atomicAdd(&Aa[row0l * RSTR + 0], lo0);
        atomicAdd(&Aa[row1l * RSTR + 0], lo1);
        atomicAdd(&Aa[row0l * RSTR + 256], hi0);
        atomicAdd(&Aa[row1l * RSTR + 256], hi1);
    }

    // ---- epilogue: reduce wn halves, normalize, write w1 ----
    float* red = (float*)(smem + 16384);   // reuses KV stage 0
    if (wn == 1) {
#pragma unroll
        for (int g = 0; g < 8; g++) {
            const int col = g * 8 + tig * 2;
            *(float2*)&red[row0l * 66 + col] = make_float2(o[g][0], o[g][1]);
            *(float2*)&red[row1l * 66 + col] = make_float2(o[g][2], o[g][3]);
        }
    }
    __syncthreads();
    if (wn == 0) {
        const float inv0 = 1.f / lsum[row0l];
        const float inv1 = 1.f / lsum[row1l];
#pragma unroll
        for (int g = 0; g < 8; g++) {
            const int col = g * 8 + tig * 2;
            const float2 r0 = *(const float2*)&red[row0l * 66 + col];
            const float2 r1 = *(const float2*)&red[row1l * 66 + col];
            float2 v0 = make_float2((o[g][0] + r0.x) * inv0, (o[g][1] + r0.y) * inv0);
            float2 v1 = make_float2((o[g][2] + r1.x) * inv1, (o[g][3] + r1.y) * inv1);
            *(float2*)&c1[(size_t)(bb * 1024 + q0 + row0l) * EDIM + hh * 64 + col] = v0;
            *(float2*)&c1[(size_t)(bb * 1024 + q0 + row1l) * EDIM + hh * 64 + col] = v1;
        }
    }

    // ---- w2 = (A/l) @ relv  -> sigma^-1 slot ----
    const int ty = tid >> 4, tx = tid & 15;
    u64t w2a[4][2];
#pragma unroll
    for (int i = 0; i < 4; i++) { w2a[i][0] = 0ull; w2a[i][1] = 0ull; }
    float invv[4];
#pragma unroll
    for (int i = 0; i < 4; i++) invv[i] = 1.f / lsum[ty * 4 + i];

    for (int r = 0; r < 257; r++) {
        const u64t bv0 = *(const u64t*)(relv + (size_t)r * 64 + tx * 4);
        const u64t bv1 = *(const u64t*)(relv + (size_t)r * 64 + tx * 4 + 2);
        float av[4];
#pragma unroll
        for (int i = 0; i < 4; i++) av[i] = Aa[(ty * 4 + i) * RSTR + r];
#pragma unroll
        for (int i = 0; i < 4; i++) {
            const u64t ad = pk2(av[i]);
            fma2(w2a[i][0], ad, bv0);
            fma2(w2a[i][1], ad, bv1);
        }
    }
    const int b2 = slot & 3, h2 = slot >> 2;   // sigma^-1(slot)
#pragma unroll
    for (int i = 0; i < 4; i++) {
        const int qg = q0 + ty * 4 + i;
        const float2 p0 = unpk(w2a[i][0]);
        const float2 p1 = unpk(w2a[i][1]);
        float4 v = make_float4(p0.x * invv[i], p0.y * invv[i], p1.x * invv[i], p1.y * invv[i]);
        *(float4*)&c2[(size_t)(b2 * 1024 + qg) * 1024 + h2 * 64 + tx * 4] = v;
    }
}

// ---------------------------------------------------------------------------
extern "C" void kernel_launch(void* const* d_in, const int* in_sizes, int n_in,
                              void* d_out, int out_size)
{
    const float* X    = (const float*)d_in[0];
    const float* Wq   = (const float*)d_in[1];
    const float* bq   = (const float*)d_in[2];
    const float* Wk   = (const float*)d_in[3];
    const float* bk   = (const float*)d_in[4];
    const float* Wv   = (const float*)d_in[5];
    const float* bv   = (const float*)d_in[6];
    const float* Wo   = (const float*)d_in[7];
    const float* bo   = (const float*)d_in[8];
    const float* relk = (const float*)d_in[9];
    const float* relv = (const float*)d_in[10];
    float* out = (float*)d_out;

    float *pB, *pc1, *pc2;
    cudaGetSymbolAddress((void**)&pB,  g_B);
    cudaGetSymbolAddress((void**)&pc1, g_c1);
    cudaGetSymbolAddress((void**)&pc2, g_c2);
    __nv_bfloat16 *pXh, *pXl, *pWqh, *pWql, *pWkh, *pWkl, *pWvh, *pWvl, *pWoh, *pWol;
    __nv_bfloat16 *pQbh, *pQbl, *pKbh, *pKbl, *pVbh, *pVbl, *pRkh, *pRkl;
    cudaGetSymbolAddress((void**)&pXh,  g_Xh);
    cudaGetSymbolAddress((void**)&pXl,  g_Xl);
    cudaGetSymbolAddress((void**)&pWqh, g_Wqh);
    cudaGetSymbolAddress((void**)&pWql, g_Wql);
    cudaGetSymbolAddress((void**)&pWkh, g_Wkh);
    cudaGetSymbolAddress((void**)&pWkl, g_Wkl);
    cudaGetSymbolAddress((void**)&pWvh, g_Wvh);
    cudaGetSymbolAddress((void**)&pWvl, g_Wvl);
    cudaGetSymbolAddress((void**)&pWoh, g_Woh);
    cudaGetSymbolAddress((void**)&pWol, g_Wol);
    cudaGetSymbolAddress((void**)&pQbh, g_Qbh);
    cudaGetSymbolAddress((void**)&pQbl, g_Qbl);
    cudaGetSymbolAddress((void**)&pKbh, g_Kbh);
    cudaGetSymbolAddress((void**)&pKbl, g_Kbl);
    cudaGetSymbolAddress((void**)&pVbh, g_Vbh);
    cudaGetSymbolAddress((void**)&pVbl, g_Vbl);
    cudaGetSymbolAddress((void**)&pRkh, g_Rkh);
    cudaGetSymbolAddress((void**)&pRkl, g_Rkl);

    cvt_split<<<MROWS * EDIM / 1024, 256>>>(X, pXh, pXl);
    cvt_w4<<<dim3(EDIM * EDIM / 1024, 4), 256>>>(Wq, Wk, Wv, Wo,
                                                 pWqh, pWql, pWkh, pWkl,
                                                 pWvh, pWvl, pWoh, pWol);
    cvt_relk<<<(320 * 64 + 255) / 256, 256>>>(relk, pRkh, pRkl);

    cudaFuncSetAttribute(mma_gemm,  cudaFuncAttributeMaxDynamicSharedMemorySize, GSMEM);
    cudaFuncSetAttribute(mma_gemm3, cudaFuncAttributeMaxDynamicSharedMemorySize, GSMEM);

    // merged QKV projections (grid.z selects weight set); 128x64 tiles
    G3Params p;
    p.Bh[0] = pWqh; p.Bl[0] = pWql; p.bias[0] = bq; p.oh[0] = pQbh; p.ol[0] = pQbl; p.alpha[0] = 0.125f;
    p.Bh[1] = pWkh; p.Bl[1] = pWkl; p.bias[1] = bk; p.oh[1] = pKbh; p.ol[1] = pKbl; p.alpha[1] = 1.0f;
    p.Bh[2] = pWvh; p.Bl[2] = pWvl; p.bias[2] = bv; p.oh[2] = pVbh; p.ol[2] = pVbl; p.alpha[2] = 1.0f;
    mma_gemm3<<<dim3(EDIM / 64, MROWS / 128, 3), 256, GSMEM>>>(pXh, pXl, p);

    cudaFuncSetAttribute(bias_mma, cudaFuncAttributeMaxDynamicSharedMemorySize, BIAS_SMEM);
    bias_mma<<<dim3(5, 16, 64), 128, BIAS_SMEM>>>(pQbh, pQbl, pRkh, pRkl, pB);

    cudaFuncSetAttribute(attn2, cudaFuncAttributeMaxDynamicSharedMemorySize, ATT_SMEM);
    attn2<<<dim3(16, 64), 256, ATT_SMEM>>>(pQbh, pQbl, pKbh, pKbl, pVbh, pVbl,
                                           pB, relv, pc1, pc2);

    cvt_add_split<<<MROWS * EDIM / 1024, 256>>>(pc1, pc2, pXh, pXl);
    mma_gemm<<<dim3(EDIM / 64, MROWS / 128), 256, GSMEM>>>(pXh, pXl, pWoh, pWol, bo, out,
                                                           1.0f, nullptr, nullptr);
}

// round 12
// speedup vs baseline: 1.1891x; 1.1891x over previous
#include <cuda_runtime.h>
#include <cuda_bf16.h>
#include <cstdint>

// ---------------------------------------------------------------------------
// MultiheadRelativeAttention: B=4, T=1024, E=1024, H=16, D=64, MAX_REL=128
// Round 12: round-8 pipeline (best known: 751.8us) + surgical cuts:
//  - bias_mma loops r-tiles in-CTA (Q loaded/ldsm'd once, relk double-buffered)
//  - input conversions merged into one launch
//  - exp2f with 1/ln2 folded into Q's projection alpha
// ---------------------------------------------------------------------------

#define MROWS 4096      // B*T
#define EDIM  1024
#define RSTR  260       // padded stride for 257 relative positions

typedef unsigned long long u64t;

__device__ float g_B [64 * 1024 * RSTR];   // bias table per source slot (log2 units)
__device__ float g_c1[MROWS * EDIM];
__device__ float g_c2[MROWS * EDIM];

// bf16 split buffers
__device__ __nv_bfloat16 g_Xh[MROWS * EDIM];
__device__ __nv_bfloat16 g_Xl[MROWS * EDIM];
__device__ __nv_bfloat16 g_Wqh[EDIM * EDIM], g_Wql[EDIM * EDIM];
__device__ __nv_bfloat16 g_Wkh[EDIM * EDIM], g_Wkl[EDIM * EDIM];
__device__ __nv_bfloat16 g_Wvh[EDIM * EDIM], g_Wvl[EDIM * EDIM];
__device__ __nv_bfloat16 g_Woh[EDIM * EDIM], g_Wol[EDIM * EDIM];
__device__ __nv_bfloat16 g_Qbh[MROWS * EDIM], g_Qbl[MROWS * EDIM];
__device__ __nv_bfloat16 g_Kbh[MROWS * EDIM], g_Kbl[MROWS * EDIM];
__device__ __nv_bfloat16 g_Vbh[MROWS * EDIM], g_Vbl[MROWS * EDIM];
__device__ __nv_bfloat16 g_Rkh[320 * 64], g_Rkl[320 * 64];  // relk split, zero-padded

// ---------------------------------------------------------------------------
// helpers
// ---------------------------------------------------------------------------
__device__ __forceinline__ uint32_t smem_to_u32(const void* p) {
    uint32_t a;
    asm("{ .reg .u64 t; cvta.to.shared.u64 t, %1; cvt.u32.u64 %0, t; }" : "=r"(a) : "l"(p));
    return a;
}
__device__ __forceinline__ void cpasync16(uint32_t dst, const void* src) {
    asm volatile("cp.async.cg.shared.global [%0], [%1], 16;" :: "r"(dst), "l"(src));
}
#define CP_COMMIT() asm volatile("cp.async.commit_group;" ::: "memory")
#define CP_WAIT(n)  asm volatile("cp.async.wait_group %0;" :: "n"(n) : "memory")

__device__ __forceinline__ void ldsm4(uint32_t* r, uint32_t addr) {
    asm volatile("ldmatrix.sync.aligned.m8n8.x4.shared.b16 {%0,%1,%2,%3}, [%4];"
                 : "=r"(r[0]), "=r"(r[1]), "=r"(r[2]), "=r"(r[3]) : "r"(addr));
}
__device__ __forceinline__ void ldsm4t(uint32_t* r, uint32_t addr) {
    asm volatile("ldmatrix.sync.aligned.m8n8.x4.trans.shared.b16 {%0,%1,%2,%3}, [%4];"
                 : "=r"(r[0]), "=r"(r[1]), "=r"(r[2]), "=r"(r[3]) : "r"(addr));
}
__device__ __forceinline__ void mma16816(float* c, const uint32_t* a, uint32_t b0, uint32_t b1) {
    asm volatile("mma.sync.aligned.m16n8k16.row.col.f32.bf16.bf16.f32 "
                 "{%0,%1,%2,%3}, {%4,%5,%6,%7}, {%8,%9}, {%0,%1,%2,%3};"
                 : "+f"(c[0]), "+f"(c[1]), "+f"(c[2]), "+f"(c[3])
                 : "r"(a[0]), "r"(a[1]), "r"(a[2]), "r"(a[3]), "r"(b0), "r"(b1));
}
__device__ __forceinline__ uint32_t pack_bf2(__nv_bfloat16 lo, __nv_bfloat16 hi) {
    return ((uint32_t)__bfloat16_as_ushort(hi) << 16) | (uint32_t)__bfloat16_as_ushort(lo);
}

// f32x2 packed helpers (w2 epilogue)
__device__ __forceinline__ u64t pk2(float x) {
    u64t r; asm("mov.b64 %0, {%1, %1};" : "=l"(r) : "f"(x)); return r;
}
__device__ __forceinline__ void fma2(u64t& d, u64t a, u64t b) {
    asm("fma.rn.f32x2 %0, %1, %2, %0;" : "+l"(d) : "l"(a), "l"(b));
}
__device__ __forceinline__ float2 unpk(u64t v) {
    float2 f; asm("mov.b64 {%0, %1}, %2;" : "=f"(f.x), "=f"(f.y) : "l"(v)); return f;
}

// ---------------------------------------------------------------------------
// merged input conversions: X split, 4 weight splits, relk split (one launch)
// block ranges: [0,4096) X | [4096,8192) weights (1024 each) | [8192,8212) relk
// ---------------------------------------------------------------------------
struct CvtParams {
    const float *X, *Wq, *Wk, *Wv, *Wo, *relk;
    __nv_bfloat16 *Xh, *Xl, *Wqh, *Wql, *Wkh, *Wkl, *Wvh, *Wvl, *Woh, *Wol, *Rkh, *Rkl;
};

__device__ __forceinline__ void split4(const float* __restrict__ src,
                                       __nv_bfloat16* __restrict__ hi,
                                       __nv_bfloat16* __restrict__ lo, int i)
{
    float4 v = *(const float4*)(src + i);
    __nv_bfloat16 h0 = __float2bfloat16(v.x), h1 = __float2bfloat16(v.y);
    __nv_bfloat16 h2 = __float2bfloat16(v.z), h3 = __float2bfloat16(v.w);
    ((uint32_t*)(hi + i))[0] = pack_bf2(h0, h1);
    ((uint32_t*)(hi + i))[1] = pack_bf2(h2, h3);
    ((uint32_t*)(lo + i))[0] = pack_bf2(__float2bfloat16(v.x - __bfloat162float(h0)),
                                        __float2bfloat16(v.y - __bfloat162float(h1)));
    ((uint32_t*)(lo + i))[1] = pack_bf2(__float2bfloat16(v.z - __bfloat162float(h2)),
                                        __float2bfloat16(v.w - __bfloat162float(h3)));
}

__global__ __launch_bounds__(256)
void cvt_all(CvtParams p)
{
    const int bid = blockIdx.x;
    if (bid < 4096) {
        split4(p.X, p.Xh, p.Xl, (bid * 256 + threadIdx.x) * 4);
    } else if (bid < 8192) {
        const int w = (bid - 4096) >> 10;           // 0..3
        const int lb = (bid - 4096) & 1023;
        const int i = (lb * 256 + threadIdx.x) * 4;
        if (w == 0)      split4(p.Wq, p.Wqh, p.Wql, i);
        else if (w == 1) split4(p.Wk, p.Wkh, p.Wkl, i);
        else if (w == 2) split4(p.Wv, p.Wvh, p.Wvl, i);
        else             split4(p.Wo, p.Woh, p.Wol, i);
    } else {
        // relk -> zero-padded [320][64] bf16 split (scalar, 1 elem/thread x4)
        const int base = (bid - 8192) * 1024 + threadIdx.x * 4;
#pragma unroll
        for (int k = 0; k < 4; k++) {
            const int i = base + k;
            if (i >= 320 * 64) break;
            const int r = i >> 6, d = i & 63;
            const float v = (r < 257) ? p.relk[r * 64 + d] : 0.f;
            const __nv_bfloat16 h = __float2bfloat16(v);
            p.Rkh[i] = h;
            p.Rkl[i] = __float2bfloat16(v - __bfloat162float(h));
        }
    }
}

__global__ __launch_bounds__(256)
void cvt_add_split(const float* __restrict__ a, const float* __restrict__ b,
                   __nv_bfloat16* __restrict__ hi, __nv_bfloat16* __restrict__ lo)
{
    const int i = (blockIdx.x * 256 + threadIdx.x) * 4;
    float4 va = *(const float4*)(a + i);
    float4 vb = *(const float4*)(b + i);
    float4 v = make_float4(va.x + vb.x, va.y + vb.y, va.z + vb.z, va.w + vb.w);
    __nv_bfloat16 h0 = __float2bfloat16(v.x), h1 = __float2bfloat16(v.y);
    __nv_bfloat16 h2 = __float2bfloat16(v.z), h3 = __float2bfloat16(v.w);
    ((uint32_t*)(hi + i))[0] = pack_bf2(h0, h1);
    ((uint32_t*)(hi + i))[1] = pack_bf2(h2, h3);
    ((uint32_t*)(lo + i))[0] = pack_bf2(__float2bfloat16(v.x - __bfloat162float(h0)),
                                        __float2bfloat16(v.y - __bfloat162float(h1)));
    ((uint32_t*)(lo + i))[1] = pack_bf2(__float2bfloat16(v.z - __bfloat162float(h2)),
                                        __float2bfloat16(v.w - __bfloat162float(h3)));
}

// ---------------------------------------------------------------------------
// GEMM core (round-8 proven): 128x128 tile, 256 thr, 3-stage cp.async,
// double-buffered register fragments, bf16 3-term split.
// ---------------------------------------------------------------------------
#define GSTAGE 65536
#define GSMEM  (3 * GSTAGE)

__device__ __forceinline__ void gemm_core(
    const __nv_bfloat16* __restrict__ Ah, const __nv_bfloat16* __restrict__ Al,
    const __nv_bfloat16* __restrict__ Bh, const __nv_bfloat16* __restrict__ Bl,
    const float* __restrict__ bias, float* __restrict__ C, float alpha,
    __nv_bfloat16* __restrict__ ohi, __nv_bfloat16* __restrict__ olo)
{
    extern __shared__ char smem[];
    const uint32_t sb = smem_to_u32(smem);
    const int tid = threadIdx.x;
    const int wid = tid >> 5, lane = tid & 31;
    const int wm = wid >> 1, wn = wid & 1;
    const int n0 = blockIdx.x * 128, m0 = blockIdx.y * 128;

    float acc[2][8][4];
#pragma unroll
    for (int f = 0; f < 2; f++)
#pragma unroll
        for (int nf = 0; nf < 8; nf++)
#pragma unroll
            for (int e = 0; e < 4; e++) acc[f][nf][e] = 0.f;

    auto issue = [&](int stage, int c) {
        const uint32_t tbs = sb + stage * GSTAGE;
        const int k0 = c * 64;
#pragma unroll
        for (int g = 0; g < 4; g++) {
            const int gi = g * 256 + tid;
            const int row = gi >> 3, gc = gi & 7;
            const uint32_t bo = row * 128 + gc * 16;
            const uint32_t sw = bo ^ ((bo >> 3) & 0x70);
            const size_t aoff = (size_t)(m0 + row) * EDIM + k0 + gc * 8;
            const size_t boff = (size_t)(n0 + row) * EDIM + k0 + gc * 8;
            cpasync16(tbs + sw,         Ah + aoff);
            cpasync16(tbs + 16384 + sw, Al + aoff);
            cpasync16(tbs + 32768 + sw, Bh + boff);
            cpasync16(tbs + 49152 + sw, Bl + boff);
        }
        CP_COMMIT();
    };

    issue(0, 0);
    issue(1, 1);

    const int arow = lane & 15;
    const int achk = lane >> 4;

    uint32_t fah[2][2][4], fal[2][2][4], fbh[2][4][4], fbl[2][4][4];
    auto ldfrag = [&](int buf, int kk, uint32_t st) {
        const int chS = (kk * 2 + achk) ^ (arow & 7);
#pragma unroll
        for (int f = 0; f < 2; f++) {
            const uint32_t ra = st + (uint32_t)(wm * 32 + f * 16 + arow) * 128 + chS * 16;
            ldsm4(fah[buf][f], ra);
            ldsm4(fal[buf][f], ra + 16384);
        }
#pragma unroll
        for (int nb = 0; nb < 4; nb++) {
            const uint32_t rb = st + 32768 + (uint32_t)(wn * 64 + nb * 16 + arow) * 128 + chS * 16;
            ldsm4(fbh[buf][nb], rb);
            ldsm4(fbl[buf][nb], rb + 16384);
        }
    };

    for (int c = 0; c < 16; c++) {
        if (c + 2 < 16) issue((c + 2) % 3, c + 2);
        if (c <= 13)      { CP_WAIT(2); }
        else if (c == 14) { CP_WAIT(1); }
        else              { CP_WAIT(0); }
        __syncthreads();

        const uint32_t st = sb + (c % 3) * GSTAGE;
        ldfrag(0, 0, st);
#pragma unroll
        for (int kk = 0; kk < 4; kk++) {
            const int cur = kk & 1;
            if (kk < 3) ldfrag(cur ^ 1, kk + 1, st);
#pragma unroll
            for (int f = 0; f < 2; f++)
#pragma unroll
                for (int nb = 0; nb < 4; nb++)
#pragma unroll
                    for (int h = 0; h < 2; h++) {
                        float* cc = acc[f][nb * 2 + h];
                        mma16816(cc, fah[cur][f], fbh[cur][nb][h], fbh[cur][nb][h + 2]);
                        mma16816(cc, fah[cur][f], fbl[cur][nb][h], fbl[cur][nb][h + 2]);
                        mma16816(cc, fal[cur][f], fbh[cur][nb][h], fbh[cur][nb][h + 2]);
                    }
        }
        __syncthreads();
    }

    const int gid = lane >> 2, tig = lane & 3;
#pragma unroll
    for (int f = 0; f < 2; f++) {
        const int m = m0 + wm * 32 + f * 16 + gid;
#pragma unroll
        for (int nb = 0; nb < 4; nb++)
#pragma unroll
            for (int h = 0; h < 2; h++) {
                const int n = n0 + wn * 64 + nb * 16 + h * 8 + tig * 2;
                const float* cc = acc[f][nb * 2 + h];
                const float b0 = __ldg(&bias[n]), b1 = __ldg(&bias[n + 1]);
                float2 v0 = make_float2(alpha * (cc[0] + b0), alpha * (cc[1] + b1));
                float2 v1 = make_float2(alpha * (cc[2] + b0), alpha * (cc[3] + b1));
                if (C) {
                    *(float2*)&C[(size_t)m * EDIM + n]       = v0;
                    *(float2*)&C[(size_t)(m + 8) * EDIM + n] = v1;
                }
                if (ohi) {
                    __nv_bfloat16 h00 = __float2bfloat16(v0.x), h01 = __float2bfloat16(v0.y);
                    __nv_bfloat16 h10 = __float2bfloat16(v1.x), h11 = __float2bfloat16(v1.y);
                    *(uint32_t*)(ohi + (size_t)m * EDIM + n)       = pack_bf2(h00, h01);
                    *(uint32_t*)(ohi + (size_t)(m + 8) * EDIM + n) = pack_bf2(h10, h11);
                    *(uint32_t*)(olo + (size_t)m * EDIM + n) =
                        pack_bf2(__float2bfloat16(v0.x - __bfloat162float(h00)),
                                 __float2bfloat16(v0.y - __bfloat162float(h01)));
                    *(uint32_t*)(olo + (size_t)(m + 8) * EDIM + n) =
                        pack_bf2(__float2bfloat16(v1.x - __bfloat162float(h10)),
                                 __float2bfloat16(v1.y - __bfloat162float(h11)));
                }
            }
    }
}

__global__ __launch_bounds__(256, 1)
void mma_gemm(const __nv_bfloat16* __restrict__ Ah, const __nv_bfloat16* __restrict__ Al,
              const __nv_bfloat16* __restrict__ Bh, const __nv_bfloat16* __restrict__ Bl,
              const float* __restrict__ bias, float* __restrict__ C, float alpha,
              __nv_bfloat16* __restrict__ ohi, __nv_bfloat16* __restrict__ olo)
{
    gemm_core(Ah, Al, Bh, Bl, bias, C, alpha, ohi, olo);
}

struct G3Params {
    const __nv_bfloat16* Bh[3]; const __nv_bfloat16* Bl[3];
    const float* bias[3];
    __nv_bfloat16* oh[3]; __nv_bfloat16* ol[3];
    float alpha[3];
};
__global__ __launch_bounds__(256, 1)
void mma_gemm3(const __nv_bfloat16* __restrict__ Ah, const __nv_bfloat16* __restrict__ Al,
               G3Params p)
{
    const int z = blockIdx.z;
    gemm_core(Ah, Al, p.Bh[z], p.Bl[z], p.bias[z], nullptr, p.alpha[z], p.oh[z], p.ol[z]);
}

// ---------------------------------------------------------------------------
// Bias table via mma, r-tiles looped in-CTA: Bt[j][q][r] = Qs[j,q,:].relk[r,:]
// (Q pre-scaled by 0.125/ln2 -> Bt in log2 units, matching attn2's exp2f)
// grid (16 q-tiles, 64 slots), 128 threads (4 warps: 2m x 2n).
// smem: Qh[0,8K) Ql[8K,16K) | 2 R stages @16K+s*16K {Rh 8K, Rl 8K}
// ---------------------------------------------------------------------------
#define BIAS_SMEM 49152
__global__ __launch_bounds__(128, 1)
void bias_mma(const __nv_bfloat16* __restrict__ Qbh, const __nv_bfloat16* __restrict__ Qbl,
              const __nv_bfloat16* __restrict__ Rh, const __nv_bfloat16* __restrict__ Rl,
              float* __restrict__ Bt)
{
    extern __shared__ char smem[];
    const uint32_t sb = smem_to_u32(smem);
    const int jslot = blockIdx.y;
    const int bb = jslot >> 4, hh = jslot & 15;
    const int q0 = blockIdx.x * 64;
    const int tid = threadIdx.x, wid = tid >> 5, lane = tid & 31;
    const int wm = wid >> 1, wn = wid & 1;
    const int arow = lane & 15, ahalf = lane >> 4;

    auto issueR = [&](int stg, int rt) {
        const uint32_t base = sb + 16384 + stg * 16384;
        const int r0 = rt * 64;
#pragma unroll
        for (int g = 0; g < 4; g++) {
            const int i = g * 128 + tid;             // 0..511
            const int row = i >> 3, c = i & 7;
            const uint32_t sw = (uint32_t)row * 128 + (uint32_t)((c ^ (row & 7)) * 16);
            const size_t ro = (size_t)(r0 + row) * 64 + c * 8;
            cpasync16(base + sw,        Rh + ro);
            cpasync16(base + 8192 + sw, Rl + ro);
        }
    };

    // group 0: Q + R0
#pragma unroll
    for (int g = 0; g < 4; g++) {
        const int i = g * 128 + tid;
        const int row = i >> 3, c = i & 7;
        const uint32_t sw = (uint32_t)row * 128 + (uint32_t)((c ^ (row & 7)) * 16);
        const size_t qo = (size_t)(bb * 1024 + q0 + row) * EDIM + hh * 64 + c * 8;
        cpasync16(sb + sw,        Qbh + qo);
        cpasync16(sb + 8192 + sw, Qbl + qo);
    }
    issueR(0, 0);
    CP_COMMIT();

    uint32_t qh[4][2][4], qlr[4][2][4];
    bool qloaded = false;
    const int gid = lane >> 2, tig = lane & 3;
    float* btj = Bt + (size_t)jslot * 1024 * RSTR;

    for (int rt = 0; rt < 5; rt++) {
        if (rt + 1 < 5) { issueR((rt + 1) & 1, rt + 1); CP_COMMIT(); }
        if (rt < 4) { CP_WAIT(1); } else { CP_WAIT(0); }
        __syncthreads();

        if (!qloaded) {
            qloaded = true;
#pragma unroll
            for (int dd = 0; dd < 4; dd++)
#pragma unroll
                for (int mf = 0; mf < 2; mf++) {
                    const int row = wm * 32 + mf * 16 + arow;
                    const uint32_t addr = sb + (uint32_t)row * 128 +
                                          (uint32_t)(((dd * 2 + ahalf) ^ (row & 7)) * 16);
                    ldsm4(qh[dd][mf], addr);
                    ldsm4(qlr[dd][mf], addr + 8192);
                }
        }

        const uint32_t rbuf = sb + 16384 + (rt & 1) * 16384;
        float s[2][4][4];
#pragma unroll
        for (int mf = 0; mf < 2; mf++)
#pragma unroll
            for (int nf = 0; nf < 4; nf++)
#pragma unroll
                for (int e = 0; e < 4; e++) s[mf][nf][e] = 0.f;

#pragma unroll
        for (int dd = 0; dd < 4; dd++) {
            uint32_t bh[2][4], bl[2][4];
#pragma unroll
            for (int ng = 0; ng < 2; ng++) {
                const int row = wn * 32 + ng * 16 + arow;
                const uint32_t addr = rbuf + (uint32_t)row * 128 +
                                      (uint32_t)(((dd * 2 + ahalf) ^ (row & 7)) * 16);
                ldsm4(bh[ng], addr);
                ldsm4(bl[ng], addr + 8192);
            }
#pragma unroll
            for (int mf = 0; mf < 2; mf++)
#pragma unroll
                for (int ng = 0; ng < 2; ng++)
#pragma unroll
                    for (int h = 0; h < 2; h++) {
                        float* cc = s[mf][ng * 2 + h];
                        mma16816(cc, qh[dd][mf], bh[ng][h], bh[ng][h + 2]);
                        mma16816(cc, qh[dd][mf], bl[ng][h], bl[ng][h + 2]);
                        mma16816(cc, qlr[dd][mf], bh[ng][h], bh[ng][h + 2]);
                    }
        }
        __syncthreads();   // all warps done reading rbuf before next prefetch lands

        const int r0 = rt * 64;
#pragma unroll
        for (int mf = 0; mf < 2; mf++) {
            const int q = q0 + wm * 32 + mf * 16 + gid;
#pragma unroll
            for (int nf = 0; nf < 4; nf++) {
                const int r = r0 + wn * 32 + nf * 8 + tig * 2;
                const float* cc = s[mf][nf];
                if (r < 257) {
                    btj[(size_t)q * RSTR + r]       = cc[0];
                    btj[(size_t)(q + 8) * RSTR + r] = cc[2];
                }
                if (r + 1 < 257) {
                    btj[(size_t)q * RSTR + r + 1]       = cc[1];
                    btj[(size_t)(q + 8) * RSTR + r + 1] = cc[3];
                }
            }
        }
    }
}

// ---------------------------------------------------------------------------
// MMA-based fused relative attention (round-8 proven; exp2f instead of expf).
// ---------------------------------------------------------------------------
#define ASTG 32768
#define ATT_SMEM (115712 + 64 * RSTR * 4)   // 182272

__global__ __launch_bounds__(256, 1)
void attn2(const __nv_bfloat16* __restrict__ Qh_, const __nv_bfloat16* __restrict__ Ql_,
           const __nv_bfloat16* __restrict__ Kh_, const __nv_bfloat16* __restrict__ Kl_,
           const __nv_bfloat16* __restrict__ Vh_, const __nv_bfloat16* __restrict__ Vl_,
           const float* __restrict__ Bt, const float* __restrict__ relv,
           float* __restrict__ c1, float* __restrict__ c2)
{
    extern __shared__ char smem[];
    const uint32_t sb = smem_to_u32(smem);
    float* lsum = (float*)(smem + 114688);
    float* Aa   = (float*)(smem + 115712);

    const int slot = blockIdx.y;
    const int q0 = blockIdx.x * 64;
    const int bb = slot >> 4, hh = slot & 15;
    const int jsrc = ((slot & 15) << 2) | (slot >> 4);   // sigma(slot)
    const int tid = threadIdx.x, wid = tid >> 5, lane = tid & 31;
    const int wm = wid >> 1, wn = wid & 1;
    const int gid = lane >> 2, tig = lane & 3;
    const int arow = lane & 15, ahalf = lane >> 4;

    for (int f = tid; f < 64 * RSTR; f += 256) Aa[f] = 0.f;
    if (tid < 64) lsum[tid] = 0.f;

    auto issueKV = [&](int stg, int kt) {
        const uint32_t base = sb + 16384 + stg * ASTG;
        const int k0 = kt * 64;
#pragma unroll
        for (int g = 0; g < 2; g++) {
            const int i = g * 256 + tid;
            const int row = i >> 3, c = i & 7;
            const uint32_t sw = (uint32_t)row * 128 + (uint32_t)((c ^ (row & 7)) * 16);
            const size_t go = (size_t)(bb * 1024 + k0 + row) * EDIM + hh * 64 + c * 8;
            cpasync16(base + sw,         Kh_ + go);
            cpasync16(base + 8192 + sw,  Kl_ + go);
            cpasync16(base + 16384 + sw, Vh_ + go);
            cpasync16(base + 24576 + sw, Vl_ + go);
        }
    };

#pragma unroll
    for (int g = 0; g < 2; g++) {
        const int i = g * 256 + tid;
        const int row = i >> 3, c = i & 7;
        const uint32_t sw = (uint32_t)row * 128 + (uint32_t)((c ^ (row & 7)) * 16);
        const size_t go = (size_t)(bb * 1024 + q0 + row) * EDIM + hh * 64 + c * 8;
        cpasync16(sb + sw,        Qh_ + go);
        cpasync16(sb + 8192 + sw, Ql_ + go);
    }
    issueKV(0, 0);
    CP_COMMIT();
    issueKV(1, 1);
    CP_COMMIT();

    uint32_t qfh[4][4], qfl[4][4];
    float o[8][4];
#pragma unroll
    for (int nf = 0; nf < 8; nf++)
#pragma unroll
        for (int e = 0; e < 4; e++) o[nf][e] = 0.f;

    const float* btq = Bt + (size_t)jsrc * 1024 * RSTR + (size_t)q0 * RSTR;
    const int row0l = wm * 16 + gid, row1l = row0l + 8;

    const float bc0_lo = __ldg(&btq[(size_t)row0l * RSTR + 0]);
    const float bc0_hi = __ldg(&btq[(size_t)row0l * RSTR + 256]);
    const float bc1_lo = __ldg(&btq[(size_t)row1l * RSTR + 0]);
    const float bc1_hi = __ldg(&btq[(size_t)row1l * RSTR + 256]);
    float ls0 = 0.f, ls1 = 0.f, lo0 = 0.f, lo1 = 0.f, hi0 = 0.f, hi1 = 0.f;

    for (int kt = 0; kt < 16; kt++) {
        if (kt + 2 < 16) { issueKV((kt + 2) % 3, kt + 2); CP_COMMIT(); }
        if (kt <= 13)      { CP_WAIT(2); }
        else if (kt == 14) { CP_WAIT(1); }
        else               { CP_WAIT(0); }
        __syncthreads();
        if (kt == 0) {
#pragma unroll
            for (int dd = 0; dd < 4; dd++) {
                const int row = wm * 16 + arow;
                const uint32_t addr = sb + (uint32_t)row * 128 +
                                      (uint32_t)(((dd * 2 + ahalf) ^ (row & 7)) * 16);
                ldsm4(qfh[dd], addr);
                ldsm4(qfl[dd], addr + 8192);
            }
        }
        const uint32_t st = sb + 16384 + (kt % 3) * ASTG;
        const int k0 = kt * 64;
        const int delta = q0 - k0;

        // ---- S = Q K^T (bf16 split, 3 terms), double-buffered K frags ----
        float s[4][4];
#pragma unroll
        for (int nf = 0; nf < 4; nf++)
#pragma unroll
            for (int e = 0; e < 4; e++) s[nf][e] = 0.f;

        uint32_t kb_h[2][2][4], kb_l[2][2][4];
        auto ldk = [&](int buf, int dd) {
#pragma unroll
            for (int g = 0; g < 2; g++) {
                const int row = wn * 32 + g * 16 + arow;
                const uint32_t addr = st + (uint32_t)row * 128 +
                                      (uint32_t)(((dd * 2 + ahalf) ^ (row & 7)) * 16);
                ldsm4(kb_h[buf][g], addr);
                ldsm4(kb_l[buf][g], addr + 8192);
            }
        };
        ldk(0, 0);
#pragma unroll
        for (int dd = 0; dd < 4; dd++) {
            const int cur = dd & 1;
            if (dd < 3) ldk(cur ^ 1, dd + 1);
#pragma unroll
            for (int g = 0; g < 2; g++)
#pragma unroll
                for (int h = 0; h < 2; h++) {
                    float* cc = s[g * 2 + h];
                    mma16816(cc, qfh[dd], kb_h[cur][g][h], kb_h[cur][g][h + 2]);
                    mma16816(cc, qfh[dd], kb_l[cur][g][h], kb_l[cur][g][h + 2]);
                    mma16816(cc, qfl[dd], kb_h[cur][g][h], kb_h[cur][g][h + 2]);
                }
        }

        // ---- bias + exp2 + row sums (+ buckets) ----  (logits are /ln2)
        float rs0 = 0.f, rs1 = 0.f;
        const bool clampHi = (delta >= 192), clampLo = (delta <= -192);
        if (clampHi || clampLo) {
            const float b0 = clampHi ? bc0_hi : bc0_lo;
            const float b1 = clampHi ? bc1_hi : bc1_lo;
#pragma unroll
            for (int nf = 0; nf < 4; nf++)
#pragma unroll
                for (int e = 0; e < 4; e++) {
                    const float p = exp2f(s[nf][e] + ((e >= 2) ? b1 : b0));
                    s[nf][e] = p;
                    if (e >= 2) rs1 += p; else rs0 += p;
                }
            if (clampHi) { hi0 += rs0; hi1 += rs1; }
            else         { lo0 += rs0; lo1 += rs1; }
        } else {
#pragma unroll
            for (int nf = 0; nf < 4; nf++) {
                const int kg = k0 + wn * 32 + nf * 8 + tig * 2;
#pragma unroll
                for (int e = 0; e < 4; e++) {
                    const int ql = (e >= 2) ? row1l : row0l;
                    const int dist = (q0 + ql) - (kg + (e & 1));
                    const int r = dist < -128 ? 0 : (dist > 128 ? 256 : dist + 128);
                    const float p = exp2f(s[nf][e] + __ldg(&btq[(size_t)ql * RSTR + r]));
                    s[nf][e] = p;
                    if (e >= 2) rs1 += p; else rs0 += p;
                }
            }
#pragma unroll
            for (int nf = 0; nf < 4; nf++) {
                const int kg = k0 + wn * 32 + nf * 8 + tig * 2;
#pragma unroll
                for (int e = 0; e < 4; e++) {
                    const int ql = (e >= 2) ? row1l : row0l;
                    const int dist = (q0 + ql) - (kg + (e & 1));
                    const int r = dist < -128 ? 0 : (dist > 128 ? 256 : dist + 128);
                    atomicAdd(&Aa[ql * RSTR + r], s[nf][e]);
                }
            }
        }
        ls0 += rs0; ls1 += rs1;

        // ---- P -> bf16 split A-frags ----
        uint32_t pah[2][4], pal[2][4];
#pragma unroll
        for (int b = 0; b < 2; b++)
#pragma unroll
            for (int a = 0; a < 4; a++) {
                const int nf = b * 2 + (a >> 1);
                const int eb = (a & 1) * 2;
                const float p0 = s[nf][eb], p1 = s[nf][eb + 1];
                const __nv_bfloat16 h0 = __float2bfloat16(p0), h1 = __float2bfloat16(p1);
                pah[b][a] = pack_bf2(h0, h1);
                pal[b][a] = pack_bf2(__float2bfloat16(p0 - __bfloat162float(h0)),
                                     __float2bfloat16(p1 - __bfloat162float(h1)));
            }

        // ---- O += P V, double-buffered V frags ----
        uint32_t vb_h[2][4], vb_l[2][4];
        auto ldv = [&](int buf, int i) {
            const int b = i >> 2, g = i & 3;
            const int krow = wn * 32 + b * 16 + arow;
            const uint32_t addr = st + 16384 + (uint32_t)krow * 128 +
                                  (uint32_t)(((g * 2 + ahalf) ^ (krow & 7)) * 16);
            ldsm4t(vb_h[buf], addr);
            ldsm4t(vb_l[buf], addr + 8192);
        };
        ldv(0, 0);
#pragma unroll
        for (int i = 0; i < 8; i++) {
            const int cur = i & 1;
            if (i < 7) ldv(cur ^ 1, i + 1);
            const int b = i >> 2, g = i & 3;
#pragma unroll
            for (int h = 0; h < 2; h++) {
                float* cc = o[g * 2 + h];
                mma16816(cc, pah[b], vb_h[cur][h * 2], vb_h[cur][h * 2 + 1]);
                mma16816(cc, pah[b], vb_l[cur][h * 2], vb_l[cur][h * 2 + 1]);
                mma16816(cc, pal[b], vb_h[cur][h * 2], vb_h[cur][h * 2 + 1]);
            }
        }
        __syncthreads();
    }

    // ---- flush deferred reductions ----
    ls0 += __shfl_xor_sync(0xffffffffu, ls0, 1); ls0 += __shfl_xor_sync(0xffffffffu, ls0, 2);
    ls1 += __shfl_xor_sync(0xffffffffu, ls1, 1); ls1 += __shfl_xor_sync(0xffffffffu, ls1, 2);
    lo0 += __shfl_xor_sync(0xffffffffu, lo0, 1); lo0 += __shfl_xor_sync(0xffffffffu, lo0, 2);
    lo1 += __shfl_xor_sync(0xffffffffu, lo1, 1); lo1 += __shfl_xor_sync(0xffffffffu, lo1, 2);
    hi0 += __shfl_xor_sync(0xffffffffu, hi0, 1); hi0 += __shfl_xor_sync(0xffffffffu, hi0, 2);
    hi1 += __shfl_xor_sync(0xffffffffu, hi1, 1); hi1 += __shfl_xor_sync(0xffffffffu, hi1, 2);
    if (tig == 0) {
        atomicAdd(&lsum[row0l], ls0);
        atomicAdd(&lsum[row1l], ls1);
        atomicAdd(&Aa[row0l * RSTR + 0], lo0);
        atomicAdd(&Aa[row1l * RSTR + 0], lo1);
        atomicAdd(&Aa[row0l * RSTR + 256], hi0);
        atomicAdd(&Aa[row1l * RSTR + 256], hi1);
    }

    // ---- epilogue: reduce wn halves, normalize, write w1 ----
    float* red = (float*)(smem + 16384);
    if (wn == 1) {
#pragma unroll
        for (int g = 0; g < 8; g++) {
            const int col = g * 8 + tig * 2;
            *(float2*)&red[row0l * 66 + col] = make_float2(o[g][0], o[g][1]);
            *(float2*)&red[row1l * 66 + col] = make_float2(o[g][2], o[g][3]);
        }
    }
    __syncthreads();
    if (wn == 0) {
        const float inv0 = 1.f / lsum[row0l];
        const float inv1 = 1.f / lsum[row1l];
#pragma unroll
        for (int g = 0; g < 8; g++) {
            const int col = g * 8 + tig * 2;
            const float2 r0 = *(const float2*)&red[row0l * 66 + col];
            const float2 r1 = *(const float2*)&red[row1l * 66 + col];
            float2 v0 = make_float2((o[g][0] + r0.x) * inv0, (o[g][1] + r0.y) * inv0);
            float2 v1 = make_float2((o[g][2] + r1.x) * inv1, (o[g][3] + r1.y) * inv1);
            *(float2*)&c1[(size_t)(bb * 1024 + q0 + row0l) * EDIM + hh * 64 + col] = v0;
            *(float2*)&c1[(size_t)(bb * 1024 + q0 + row1l) * EDIM + hh * 64 + col] = v1;
        }
    }

    // ---- w2 = (A/l) @ relv  -> sigma^-1 slot ----
    const int ty = tid >> 4, tx = tid & 15;
    u64t w2a[4][2];
#pragma unroll
    for (int i = 0; i < 4; i++) { w2a[i][0] = 0ull; w2a[i][1] = 0ull; }
    float invv[4];
#pragma unroll
    for (int i = 0; i < 4; i++) invv[i] = 1.f / lsum[ty * 4 + i];

    for (int r = 0; r < 257; r++) {
        const u64t bv0 = *(const u64t*)(relv + (size_t)r * 64 + tx * 4);
        const u64t bv1 = *(const u64t*)(relv + (size_t)r * 64 + tx * 4 + 2);
        float av[4];
#pragma unroll
        for (int i = 0; i < 4; i++) av[i] = Aa[(ty * 4 + i) * RSTR + r];
#pragma unroll
        for (int i = 0; i < 4; i++) {
            const u64t ad = pk2(av[i]);
            fma2(w2a[i][0], ad, bv0);
            fma2(w2a[i][1], ad, bv1);
        }
    }
    const int b2 = slot & 3, h2 = slot >> 2;
#pragma unroll
    for (int i = 0; i < 4; i++) {
        const int qg = q0 + ty * 4 + i;
        const float2 p0 = unpk(w2a[i][0]);
        const float2 p1 = unpk(w2a[i][1]);
        float4 v = make_float4(p0.x * invv[i], p0.y * invv[i], p1.x * invv[i], p1.y * invv[i]);
        *(float4*)&c2[(size_t)(b2 * 1024 + qg) * 1024 + h2 * 64 + tx * 4] = v;
    }
}

// ---------------------------------------------------------------------------
extern "C" void kernel_launch(void* const* d_in, const int* in_sizes, int n_in,
                              void* d_out, int out_size)
{
    const float* X    = (const float*)d_in[0];
    const float* Wq   = (const float*)d_in[1];
    const float* bq   = (const float*)d_in[2];
    const float* Wk   = (const float*)d_in[3];
    const float* bk   = (const float*)d_in[4];
    const float* Wv   = (const float*)d_in[5];
    const float* bv   = (const float*)d_in[6];
    const float* Wo   = (const float*)d_in[7];
    const float* bo   = (const float*)d_in[8];
    const float* relk = (const float*)d_in[9];
    const float* relv = (const float*)d_in[10];
    float* out = (float*)d_out;

    float *pB, *pc1, *pc2;
    cudaGetSymbolAddress((void**)&pB,  g_B);
    cudaGetSymbolAddress((void**)&pc1, g_c1);
    cudaGetSymbolAddress((void**)&pc2, g_c2);
    __nv_bfloat16 *pXh, *pXl, *pWqh, *pWql, *pWkh, *pWkl, *pWvh, *pWvl, *pWoh, *pWol;
    __nv_bfloat16 *pQbh, *pQbl, *pKbh, *pKbl, *pVbh, *pVbl, *pRkh, *pRkl;
    cudaGetSymbolAddress((void**)&pXh,  g_Xh);
    cudaGetSymbolAddress((void**)&pXl,  g_Xl);
    cudaGetSymbolAddress((void**)&pWqh, g_Wqh);
    cudaGetSymbolAddress((void**)&pWql, g_Wql);
    cudaGetSymbolAddress((void**)&pWkh, g_Wkh);
    cudaGetSymbolAddress((void**)&pWkl, g_Wkl);
    cudaGetSymbolAddress((void**)&pWvh, g_Wvh);
    cudaGetSymbolAddress((void**)&pWvl, g_Wvl);
    cudaGetSymbolAddress((void**)&pWoh, g_Woh);
    cudaGetSymbolAddress((void**)&pWol, g_Wol);
    cudaGetSymbolAddress((void**)&pQbh, g_Qbh);
    cudaGetSymbolAddress((void**)&pQbl, g_Qbl);
    cudaGetSymbolAddress((void**)&pKbh, g_Kbh);
    cudaGetSymbolAddress((void**)&pKbl, g_Kbl);
    cudaGetSymbolAddress((void**)&pVbh, g_Vbh);
    cudaGetSymbolAddress((void**)&pVbl, g_Vbl);
    cudaGetSymbolAddress((void**)&pRkh, g_Rkh);
    cudaGetSymbolAddress((void**)&pRkl, g_Rkl);

    // merged conversions (X, 4 weights, relk) — one launch
    CvtParams cp;
    cp.X = X; cp.Wq = Wq; cp.Wk = Wk; cp.Wv = Wv; cp.Wo = Wo; cp.relk = relk;
    cp.Xh = pXh; cp.Xl = pXl;
    cp.Wqh = pWqh; cp.Wql = pWql; cp.Wkh = pWkh; cp.Wkl = pWkl;
    cp.Wvh = pWvh; cp.Wvl = pWvl; cp.Woh = pWoh; cp.Wol = pWol;
    cp.Rkh = pRkh; cp.Rkl = pRkl;
    cvt_all<<<8192 + 20, 256>>>(cp);

    cudaFuncSetAttribute(mma_gemm,  cudaFuncAttributeMaxDynamicSharedMemorySize, GSMEM);
    cudaFuncSetAttribute(mma_gemm3, cudaFuncAttributeMaxDynamicSharedMemorySize, GSMEM);

    // merged QKV projections (grid.z selects weight set).
    // Q alpha = 0.125/ln2: scores AND bias table end up in log2 units -> exp2f.
    G3Params p;
    p.Bh[0] = pWqh; p.Bl[0] = pWql; p.bias[0] = bq; p.oh[0] = pQbh; p.ol[0] = pQbl;
    p.alpha[0] = 0.125f * 1.4426950408889634f;
    p.Bh[1] = pWkh; p.Bl[1] = pWkl; p.bias[1] = bk; p.oh[1] = pKbh; p.ol[1] = pKbl;
    p.alpha[1] = 1.0f;
    p.Bh[2] = pWvh; p.Bl[2] = pWvl; p.bias[2] = bv; p.oh[2] = pVbh; p.ol[2] = pVbl;
    p.alpha[2] = 1.0f;
    mma_gemm3<<<dim3(EDIM / 128, MROWS / 128, 3), 256, GSMEM>>>(pXh, pXl, p);

    cudaFuncSetAttribute(bias_mma, cudaFuncAttributeMaxDynamicSharedMemorySize, BIAS_SMEM);
    bias_mma<<<dim3(16, 64), 128, BIAS_SMEM>>>(pQbh, pQbl, pRkh, pRkl, pB);

    cudaFuncSetAttribute(attn2, cudaFuncAttributeMaxDynamicSharedMemorySize, ATT_SMEM);
    attn2<<<dim3(16, 64), 256, ATT_SMEM>>>(pQbh, pQbl, pKbh, pKbl, pVbh, pVbl,
                                           pB, relv, pc1, pc2);

    cvt_add_split<<<MROWS * EDIM / 1024, 256>>>(pc1, pc2, pXh, pXl);
    mma_gemm<<<dim3(EDIM / 128, MROWS / 128), 256, GSMEM>>>(pXh, pXl, pWoh, pWol, bo, out,
                                                            1.0f, nullptr, nullptr);
}

// round 13
// speedup vs baseline: 1.2091x; 1.0168x over previous
#include <cuda_runtime.h>
#include <cuda_bf16.h>
#include <cstdint>

// ---------------------------------------------------------------------------
// MultiheadRelativeAttention: B=4, T=1024, E=1024, H=16, D=64, MAX_REL=128
// Round 13: attn2 reworked for 2 CTAs/SM (32-row q-tile, 2 KV stages,
// <=128 regs); GEMM/bias/conversions unchanged from round 12.
// ---------------------------------------------------------------------------

#define MROWS 4096      // B*T
#define EDIM  1024
#define RSTR  260       // padded stride for 257 relative positions

typedef unsigned long long u64t;

__device__ float g_B [64 * 1024 * RSTR];   // bias table per source slot (log2 units)
__device__ float g_c1[MROWS * EDIM];
__device__ float g_c2[MROWS * EDIM];

__device__ __nv_bfloat16 g_Xh[MROWS * EDIM];
__device__ __nv_bfloat16 g_Xl[MROWS * EDIM];
__device__ __nv_bfloat16 g_Wqh[EDIM * EDIM], g_Wql[EDIM * EDIM];
__device__ __nv_bfloat16 g_Wkh[EDIM * EDIM], g_Wkl[EDIM * EDIM];
__device__ __nv_bfloat16 g_Wvh[EDIM * EDIM], g_Wvl[EDIM * EDIM];
__device__ __nv_bfloat16 g_Woh[EDIM * EDIM], g_Wol[EDIM * EDIM];
__device__ __nv_bfloat16 g_Qbh[MROWS * EDIM], g_Qbl[MROWS * EDIM];
__device__ __nv_bfloat16 g_Kbh[MROWS * EDIM], g_Kbl[MROWS * EDIM];
__device__ __nv_bfloat16 g_Vbh[MROWS * EDIM], g_Vbl[MROWS * EDIM];
__device__ __nv_bfloat16 g_Rkh[320 * 64], g_Rkl[320 * 64];

// ---------------------------------------------------------------------------
// helpers
// ---------------------------------------------------------------------------
__device__ __forceinline__ uint32_t smem_to_u32(const void* p) {
    uint32_t a;
    asm("{ .reg .u64 t; cvta.to.shared.u64 t, %1; cvt.u32.u64 %0, t; }" : "=r"(a) : "l"(p));
    return a;
}
__device__ __forceinline__ void cpasync16(uint32_t dst, const void* src) {
    asm volatile("cp.async.cg.shared.global [%0], [%1], 16;" :: "r"(dst), "l"(src));
}
#define CP_COMMIT() asm volatile("cp.async.commit_group;" ::: "memory")
#define CP_WAIT(n)  asm volatile("cp.async.wait_group %0;" :: "n"(n) : "memory")

__device__ __forceinline__ void ldsm4(uint32_t* r, uint32_t addr) {
    asm volatile("ldmatrix.sync.aligned.m8n8.x4.shared.b16 {%0,%1,%2,%3}, [%4];"
                 : "=r"(r[0]), "=r"(r[1]), "=r"(r[2]), "=r"(r[3]) : "r"(addr));
}
__device__ __forceinline__ void ldsm4t(uint32_t* r, uint32_t addr) {
    asm volatile("ldmatrix.sync.aligned.m8n8.x4.trans.shared.b16 {%0,%1,%2,%3}, [%4];"
                 : "=r"(r[0]), "=r"(r[1]), "=r"(r[2]), "=r"(r[3]) : "r"(addr));
}
__device__ __forceinline__ void mma16816(float* c, const uint32_t* a, uint32_t b0, uint32_t b1) {
    asm volatile("mma.sync.aligned.m16n8k16.row.col.f32.bf16.bf16.f32 "
                 "{%0,%1,%2,%3}, {%4,%5,%6,%7}, {%8,%9}, {%0,%1,%2,%3};"
                 : "+f"(c[0]), "+f"(c[1]), "+f"(c[2]), "+f"(c[3])
                 : "r"(a[0]), "r"(a[1]), "r"(a[2]), "r"(a[3]), "r"(b0), "r"(b1));
}
__device__ __forceinline__ uint32_t pack_bf2(__nv_bfloat16 lo, __nv_bfloat16 hi) {
    return ((uint32_t)__bfloat16_as_ushort(hi) << 16) | (uint32_t)__bfloat16_as_ushort(lo);
}
__device__ __forceinline__ u64t pk2(float x) {
    u64t r; asm("mov.b64 %0, {%1, %1};" : "=l"(r) : "f"(x)); return r;
}
__device__ __forceinline__ void fma2(u64t& d, u64t a, u64t b) {
    asm("fma.rn.f32x2 %0, %1, %2, %0;" : "+l"(d) : "l"(a), "l"(b));
}
__device__ __forceinline__ float2 unpk(u64t v) {
    float2 f; asm("mov.b64 {%0, %1}, %2;" : "=f"(f.x), "=f"(f.y) : "l"(v)); return f;
}

// ---------------------------------------------------------------------------
// merged input conversions (round 12)
// ---------------------------------------------------------------------------
struct CvtParams {
    const float *X, *Wq, *Wk, *Wv, *Wo, *relk;
    __nv_bfloat16 *Xh, *Xl, *Wqh, *Wql, *Wkh, *Wkl, *Wvh, *Wvl, *Woh, *Wol, *Rkh, *Rkl;
};

__device__ __forceinline__ void split4(const float* __restrict__ src,
                                       __nv_bfloat16* __restrict__ hi,
                                       __nv_bfloat16* __restrict__ lo, int i)
{
    float4 v = *(const float4*)(src + i);
    __nv_bfloat16 h0 = __float2bfloat16(v.x), h1 = __float2bfloat16(v.y);
    __nv_bfloat16 h2 = __float2bfloat16(v.z), h3 = __float2bfloat16(v.w);
    ((uint32_t*)(hi + i))[0] = pack_bf2(h0, h1);
    ((uint32_t*)(hi + i))[1] = pack_bf2(h2, h3);
    ((uint32_t*)(lo + i))[0] = pack_bf2(__float2bfloat16(v.x - __bfloat162float(h0)),
                                        __float2bfloat16(v.y - __bfloat162float(h1)));
    ((uint32_t*)(lo + i))[1] = pack_bf2(__float2bfloat16(v.z - __bfloat162float(h2)),
                                        __float2bfloat16(v.w - __bfloat162float(h3)));
}

__global__ __launch_bounds__(256)
void cvt_all(CvtParams p)
{
    const int bid = blockIdx.x;
    if (bid < 4096) {
        split4(p.X, p.Xh, p.Xl, (bid * 256 + threadIdx.x) * 4);
    } else if (bid < 8192) {
        const int w = (bid - 4096) >> 10;
        const int lb = (bid - 4096) & 1023;
        const int i = (lb * 256 + threadIdx.x) * 4;
        if (w == 0)      split4(p.Wq, p.Wqh, p.Wql, i);
        else if (w == 1) split4(p.Wk, p.Wkh, p.Wkl, i);
        else if (w == 2) split4(p.Wv, p.Wvh, p.Wvl, i);
        else             split4(p.Wo, p.Woh, p.Wol, i);
    } else {
        const int base = (bid - 8192) * 1024 + threadIdx.x * 4;
#pragma unroll
        for (int k = 0; k < 4; k++) {
            const int i = base + k;
            if (i >= 320 * 64) break;
            const int r = i >> 6, d = i & 63;
            const float v = (r < 257) ? p.relk[r * 64 + d] : 0.f;
            const __nv_bfloat16 h = __float2bfloat16(v);
            p.Rkh[i] = h;
            p.Rkl[i] = __float2bfloat16(v - __bfloat162float(h));
        }
    }
}

__global__ __launch_bounds__(256)
void cvt_add_split(const float* __restrict__ a, const float* __restrict__ b,
                   __nv_bfloat16* __restrict__ hi, __nv_bfloat16* __restrict__ lo)
{
    const int i = (blockIdx.x * 256 + threadIdx.x) * 4;
    float4 va = *(const float4*)(a + i);
    float4 vb = *(const float4*)(b + i);
    float4 v = make_float4(va.x + vb.x, va.y + vb.y, va.z + vb.z, va.w + vb.w);
    __nv_bfloat16 h0 = __float2bfloat16(v.x), h1 = __float2bfloat16(v.y);
    __nv_bfloat16 h2 = __float2bfloat16(v.z), h3 = __float2bfloat16(v.w);
    ((uint32_t*)(hi + i))[0] = pack_bf2(h0, h1);
    ((uint32_t*)(hi + i))[1] = pack_bf2(h2, h3);
    ((uint32_t*)(lo + i))[0] = pack_bf2(__float2bfloat16(v.x - __bfloat162float(h0)),
                                        __float2bfloat16(v.y - __bfloat162float(h1)));
    ((uint32_t*)(lo + i))[1] = pack_bf2(__float2bfloat16(v.z - __bfloat162float(h2)),
                                        __float2bfloat16(v.w - __bfloat162float(h3)));
}

// ---------------------------------------------------------------------------
// GEMM core (round-8 proven, unchanged)
// ---------------------------------------------------------------------------
#define GSTAGE 65536
#define GSMEM  (3 * GSTAGE)

__device__ __forceinline__ void gemm_core(
    const __nv_bfloat16* __restrict__ Ah, const __nv_bfloat16* __restrict__ Al,
    const __nv_bfloat16* __restrict__ Bh, const __nv_bfloat16* __restrict__ Bl,
    const float* __restrict__ bias, float* __restrict__ C, float alpha,
    __nv_bfloat16* __restrict__ ohi, __nv_bfloat16* __restrict__ olo)
{
    extern __shared__ char smem[];
    const uint32_t sb = smem_to_u32(smem);
    const int tid = threadIdx.x;
    const int wid = tid >> 5, lane = tid & 31;
    const int wm = wid >> 1, wn = wid & 1;
    const int n0 = blockIdx.x * 128, m0 = blockIdx.y * 128;

    float acc[2][8][4];
#pragma unroll
    for (int f = 0; f < 2; f++)
#pragma unroll
        for (int nf = 0; nf < 8; nf++)
#pragma unroll
            for (int e = 0; e < 4; e++) acc[f][nf][e] = 0.f;

    auto issue = [&](int stage, int c) {
        const uint32_t tbs = sb + stage * GSTAGE;
        const int k0 = c * 64;
#pragma unroll
        for (int g = 0; g < 4; g++) {
            const int gi = g * 256 + tid;
            const int row = gi >> 3, gc = gi & 7;
            const uint32_t bo = row * 128 + gc * 16;
            const uint32_t sw = bo ^ ((bo >> 3) & 0x70);
            const size_t aoff = (size_t)(m0 + row) * EDIM + k0 + gc * 8;
            const size_t boff = (size_t)(n0 + row) * EDIM + k0 + gc * 8;
            cpasync16(tbs + sw,         Ah + aoff);
            cpasync16(tbs + 16384 + sw, Al + aoff);
            cpasync16(tbs + 32768 + sw, Bh + boff);
            cpasync16(tbs + 49152 + sw, Bl + boff);
        }
        CP_COMMIT();
    };

    issue(0, 0);
    issue(1, 1);

    const int arow = lane & 15;
    const int achk = lane >> 4;

    uint32_t fah[2][2][4], fal[2][2][4], fbh[2][4][4], fbl[2][4][4];
    auto ldfrag = [&](int buf, int kk, uint32_t st) {
        const int chS = (kk * 2 + achk) ^ (arow & 7);
#pragma unroll
        for (int f = 0; f < 2; f++) {
            const uint32_t ra = st + (uint32_t)(wm * 32 + f * 16 + arow) * 128 + chS * 16;
            ldsm4(fah[buf][f], ra);
            ldsm4(fal[buf][f], ra + 16384);
        }
#pragma unroll
        for (int nb = 0; nb < 4; nb++) {
            const uint32_t rb = st + 32768 + (uint32_t)(wn * 64 + nb * 16 + arow) * 128 + chS * 16;
            ldsm4(fbh[buf][nb], rb);
            ldsm4(fbl[buf][nb], rb + 16384);
        }
    };

    for (int c = 0; c < 16; c++) {
        if (c + 2 < 16) issue((c + 2) % 3, c + 2);
        if (c <= 13)      { CP_WAIT(2); }
        else if (c == 14) { CP_WAIT(1); }
        else              { CP_WAIT(0); }
        __syncthreads();

        const uint32_t st = sb + (c % 3) * GSTAGE;
        ldfrag(0, 0, st);
#pragma unroll
        for (int kk = 0; kk < 4; kk++) {
            const int cur = kk & 1;
            if (kk < 3) ldfrag(cur ^ 1, kk + 1, st);
#pragma unroll
            for (int f = 0; f < 2; f++)
#pragma unroll
                for (int nb = 0; nb < 4; nb++)
#pragma unroll
                    for (int h = 0; h < 2; h++) {
                        float* cc = acc[f][nb * 2 + h];
                        mma16816(cc, fah[cur][f], fbh[cur][nb][h], fbh[cur][nb][h + 2]);
                        mma16816(cc, fah[cur][f], fbl[cur][nb][h], fbl[cur][nb][h + 2]);
                        mma16816(cc, fal[cur][f], fbh[cur][nb][h], fbh[cur][nb][h + 2]);
                    }
        }
        __syncthreads();
    }

    const int gid = lane >> 2, tig = lane & 3;
#pragma unroll
    for (int f = 0; f < 2; f++) {
        const int m = m0 + wm * 32 + f * 16 + gid;
#pragma unroll
        for (int nb = 0; nb < 4; nb++)
#pragma unroll
            for (int h = 0; h < 2; h++) {
                const int n = n0 + wn * 64 + nb * 16 + h * 8 + tig * 2;
                const float* cc = acc[f][nb * 2 + h];
                const float b0 = __ldg(&bias[n]), b1 = __ldg(&bias[n + 1]);
                float2 v0 = make_float2(alpha * (cc[0] + b0), alpha * (cc[1] + b1));
                float2 v1 = make_float2(alpha * (cc[2] + b0), alpha * (cc[3] + b1));
                if (C) {
                    *(float2*)&C[(size_t)m * EDIM + n]       = v0;
                    *(float2*)&C[(size_t)(m + 8) * EDIM + n] = v1;
                }
                if (ohi) {
                    __nv_bfloat16 h00 = __float2bfloat16(v0.x), h01 = __float2bfloat16(v0.y);
                    __nv_bfloat16 h10 = __float2bfloat16(v1.x), h11 = __float2bfloat16(v1.y);
                    *(uint32_t*)(ohi + (size_t)m * EDIM + n)       = pack_bf2(h00, h01);
                    *(uint32_t*)(ohi + (size_t)(m + 8) * EDIM + n) = pack_bf2(h10, h11);
                    *(uint32_t*)(olo + (size_t)m * EDIM + n) =
                        pack_bf2(__float2bfloat16(v0.x - __bfloat162float(h00)),
                                 __float2bfloat16(v0.y - __bfloat162float(h01)));
                    *(uint32_t*)(olo + (size_t)(m + 8) * EDIM + n) =
                        pack_bf2(__float2bfloat16(v1.x - __bfloat162float(h10)),
                                 __float2bfloat16(v1.y - __bfloat162float(h11)));
                }
            }
    }
}

__global__ __launch_bounds__(256, 1)
void mma_gemm(const __nv_bfloat16* __restrict__ Ah, const __nv_bfloat16* __restrict__ Al,
              const __nv_bfloat16* __restrict__ Bh, const __nv_bfloat16* __restrict__ Bl,
              const float* __restrict__ bias, float* __restrict__ C, float alpha,
              __nv_bfloat16* __restrict__ ohi, __nv_bfloat16* __restrict__ olo)
{
    gemm_core(Ah, Al, Bh, Bl, bias, C, alpha, ohi, olo);
}

struct G3Params {
    const __nv_bfloat16* Bh[3]; const __nv_bfloat16* Bl[3];
    const float* bias[3];
    __nv_bfloat16* oh[3]; __nv_bfloat16* ol[3];
    float alpha[3];
};
__global__ __launch_bounds__(256, 1)
void mma_gemm3(const __nv_bfloat16* __restrict__ Ah, const __nv_bfloat16* __restrict__ Al,
               G3Params p)
{
    const int z = blockIdx.z;
    gemm_core(Ah, Al, p.Bh[z], p.Bl[z], p.bias[z], nullptr, p.alpha[z], p.oh[z], p.ol[z]);
}

// ---------------------------------------------------------------------------
// Bias table via mma, r-tiles looped in-CTA (round 12)
// ---------------------------------------------------------------------------
#define BIAS_SMEM 49152
__global__ __launch_bounds__(128, 1)
void bias_mma(const __nv_bfloat16* __restrict__ Qbh, const __nv_bfloat16* __restrict__ Qbl,
              const __nv_bfloat16* __restrict__ Rh, const __nv_bfloat16* __restrict__ Rl,
              float* __restrict__ Bt)
{
    extern __shared__ char smem[];
    const uint32_t sb = smem_to_u32(smem);
    const int jslot = blockIdx.y;
    const int bb = jslot >> 4, hh = jslot & 15;
    const int q0 = blockIdx.x * 64;
    const int tid = threadIdx.x, wid = tid >> 5, lane = tid & 31;
    const int wm = wid >> 1, wn = wid & 1;
    const int arow = lane & 15, ahalf = lane >> 4;

    auto issueR = [&](int stg, int rt) {
        const uint32_t base = sb + 16384 + stg * 16384;
        const int r0 = rt * 64;
#pragma unroll
        for (int g = 0; g < 4; g++) {
            const int i = g * 128 + tid;
            const int row = i >> 3, c = i & 7;
            const uint32_t sw = (uint32_t)row * 128 + (uint32_t)((c ^ (row & 7)) * 16);
            const size_t ro = (size_t)(r0 + row) * 64 + c * 8;
            cpasync16(base + sw,        Rh + ro);
            cpasync16(base + 8192 + sw, Rl + ro);
        }
    };

#pragma unroll
    for (int g = 0; g < 4; g++) {
        const int i = g * 128 + tid;
        const int row = i >> 3, c = i & 7;
        const uint32_t sw = (uint32_t)row * 128 + (uint32_t)((c ^ (row & 7)) * 16);
        const size_t qo = (size_t)(bb * 1024 + q0 + row) * EDIM + hh * 64 + c * 8;
        cpasync16(sb + sw,        Qbh + qo);
        cpasync16(sb + 8192 + sw, Qbl + qo);
    }
    issueR(0, 0);
    CP_COMMIT();

    uint32_t qh[4][2][4], qlr[4][2][4];
    bool qloaded = false;
    const int gid = lane >> 2, tig = lane & 3;
    float* btj = Bt + (size_t)jslot * 1024 * RSTR;

    for (int rt = 0; rt < 5; rt++) {
        if (rt + 1 < 5) { issueR((rt + 1) & 1, rt + 1); CP_COMMIT(); }
        if (rt < 4) { CP_WAIT(1); } else { CP_WAIT(0); }
        __syncthreads();

        if (!qloaded) {
            qloaded = true;
#pragma unroll
            for (int dd = 0; dd < 4; dd++)
#pragma unroll
                for (int mf = 0; mf < 2; mf++) {
                    const int row = wm * 32 + mf * 16 + arow;
                    const uint32_t addr = sb + (uint32_t)row * 128 +
                                          (uint32_t)(((dd * 2 + ahalf) ^ (row & 7)) * 16);
                    ldsm4(qh[dd][mf], addr);
                    ldsm4(qlr[dd][mf], addr + 8192);
                }
        }

        const uint32_t rbuf = sb + 16384 + (rt & 1) * 16384;
        float s[2][4][4];
#pragma unroll
        for (int mf = 0; mf < 2; mf++)
#pragma unroll
            for (int nf = 0; nf < 4; nf++)
#pragma unroll
                for (int e = 0; e < 4; e++) s[mf][nf][e] = 0.f;

#pragma unroll
        for (int dd = 0; dd < 4; dd++) {
            uint32_t bh[2][4], bl[2][4];
#pragma unroll
            for (int ng = 0; ng < 2; ng++) {
                const int row = wn * 32 + ng * 16 + arow;
                const uint32_t addr = rbuf + (uint32_t)row * 128 +
                                      (uint32_t)(((dd * 2 + ahalf) ^ (row & 7)) * 16);
                ldsm4(bh[ng], addr);
                ldsm4(bl[ng], addr + 8192);
            }
#pragma unroll
            for (int mf = 0; mf < 2; mf++)
#pragma unroll
                for (int ng = 0; ng < 2; ng++)
#pragma unroll
                    for (int h = 0; h < 2; h++) {
                        float* cc = s[mf][ng * 2 + h];
                        mma16816(cc, qh[dd][mf], bh[ng][h], bh[ng][h + 2]);
                        mma16816(cc, qh[dd][mf], bl[ng][h], bl[ng][h + 2]);
                        mma16816(cc, qlr[dd][mf], bh[ng][h], bh[ng][h + 2]);
                    }
        }
        __syncthreads();

        const int r0 = rt * 64;
#pragma unroll
        for (int mf = 0; mf < 2; mf++) {
            const int q = q0 + wm * 32 + mf * 16 + gid;
#pragma unroll
            for (int nf = 0; nf < 4; nf++) {
                const int r = r0 + wn * 32 + nf * 8 + tig * 2;
                const float* cc = s[mf][nf];
                if (r < 257) {
                    btj[(size_t)q * RSTR + r]       = cc[0];
                    btj[(size_t)(q + 8) * RSTR + r] = cc[2];
                }
                if (r + 1 < 257) {
                    btj[(size_t)q * RSTR + r + 1]       = cc[1];
                    btj[(size_t)(q + 8) * RSTR + r + 1] = cc[3];
                }
            }
        }
    }
}

// ---------------------------------------------------------------------------
// Fused relative attention, 32-row q-tile, 2 CTAs/SM.
// 8 warps: 2(m) x 4(n). Warp: 16 q-rows, 16 k-cols (S) / 16 k-rows (PV).
// smem layout: Qh[0,4K) Ql[4K,8K) | 2 stages @8K+s*32K {Kh,Kl,Vh,Vl 8K each} |
//   lsum @73728 (1K pad) | Aa[32][260] @74752 -> total 108032
// ---------------------------------------------------------------------------
#define ASTG 32768
#define ATT_SMEM 108032

__global__ __launch_bounds__(256, 2)
void attn2(const __nv_bfloat16* __restrict__ Qh_, const __nv_bfloat16* __restrict__ Ql_,
           const __nv_bfloat16* __restrict__ Kh_, const __nv_bfloat16* __restrict__ Kl_,
           const __nv_bfloat16* __restrict__ Vh_, const __nv_bfloat16* __restrict__ Vl_,
           const float* __restrict__ Bt, const float* __restrict__ relv,
           float* __restrict__ c1, float* __restrict__ c2)
{
    extern __shared__ char smem[];
    const uint32_t sb = smem_to_u32(smem);
    float* lsum = (float*)(smem + 73728);
    float* Aa   = (float*)(smem + 74752);

    const int slot = blockIdx.y;
    const int q0 = blockIdx.x * 32;
    const int bb = slot >> 4, hh = slot & 15;
    const int jsrc = ((slot & 15) << 2) | (slot >> 4);   // sigma(slot)
    const int tid = threadIdx.x, wid = tid >> 5, lane = tid & 31;
    const int wm = wid >> 2, wn = wid & 3;               // 2(m) x 4(n)
    const int gid = lane >> 2, tig = lane & 3;
    const int arow = lane & 15, ahalf = lane >> 4;

    for (int f = tid; f < 32 * RSTR; f += 256) Aa[f] = 0.f;
    if (tid < 32) lsum[tid] = 0.f;

    auto issueKV = [&](int stg, int kt) {
        const uint32_t base = sb + 8192 + stg * ASTG;
        const int k0 = kt * 64;
#pragma unroll
        for (int g = 0; g < 2; g++) {
            const int i = g * 256 + tid;        // 0..511
            const int row = i >> 3, c = i & 7;
            const uint32_t sw = (uint32_t)row * 128 + (uint32_t)((c ^ (row & 7)) * 16);
            const size_t go = (size_t)(bb * 1024 + k0 + row) * EDIM + hh * 64 + c * 8;
            cpasync16(base + sw,         Kh_ + go);
            cpasync16(base + 8192 + sw,  Kl_ + go);
            cpasync16(base + 16384 + sw, Vh_ + go);
            cpasync16(base + 24576 + sw, Vl_ + go);
        }
    };

    // group 0: Q(32 rows, hi+lo) + KV0 ; group 1: KV1
    {
        const int i = tid;                      // 0..255
        const int row = i >> 3, c = i & 7;
        const uint32_t sw = (uint32_t)row * 128 + (uint32_t)((c ^ (row & 7)) * 16);
        const size_t go = (size_t)(bb * 1024 + q0 + row) * EDIM + hh * 64 + c * 8;
        cpasync16(sb + sw,        Qh_ + go);
        cpasync16(sb + 4096 + sw, Ql_ + go);
    }
    issueKV(0, 0);
    CP_COMMIT();
    issueKV(1, 1);
    CP_COMMIT();

    float o[8][4];
#pragma unroll
    for (int nf = 0; nf < 8; nf++)
#pragma unroll
        for (int e = 0; e < 4; e++) o[nf][e] = 0.f;

    const float* btq = Bt + (size_t)jsrc * 1024 * RSTR + (size_t)q0 * RSTR;
    const int row0l = wm * 16 + gid, row1l = row0l + 8;   // 0..31

    const float bc0_lo = __ldg(&btq[(size_t)row0l * RSTR + 0]);
    const float bc0_hi = __ldg(&btq[(size_t)row0l * RSTR + 256]);
    const float bc1_lo = __ldg(&btq[(size_t)row1l * RSTR + 0]);
    const float bc1_hi = __ldg(&btq[(size_t)row1l * RSTR + 256]);
    float ls0 = 0.f, ls1 = 0.f, lo0 = 0.f, lo1 = 0.f, hi0 = 0.f, hi1 = 0.f;

    for (int kt = 0; kt < 16; kt++) {
        if (kt < 15) { CP_WAIT(1); } else { CP_WAIT(0); }
        __syncthreads();
        const uint32_t st = sb + 8192 + (kt & 1) * ASTG;
        const int k0 = kt * 64;
        const int delta = q0 - k0;

        // ---- S = Q K^T (bf16 split, 3 terms); Q frags re-ldsm'd per dd ----
        float s[2][4];
        s[0][0] = s[0][1] = s[0][2] = s[0][3] = 0.f;
        s[1][0] = s[1][1] = s[1][2] = s[1][3] = 0.f;
#pragma unroll
        for (int dd = 0; dd < 4; dd++) {
            uint32_t qh[4], ql[4], kh[4], kl[4];
            {
                const int row = wm * 16 + arow;
                const uint32_t qa = sb + (uint32_t)row * 128 +
                                    (uint32_t)(((dd * 2 + ahalf) ^ (row & 7)) * 16);
                ldsm4(qh, qa);
                ldsm4(ql, qa + 4096);
            }
            {
                const int row = wn * 16 + arow;
                const uint32_t ka = st + (uint32_t)row * 128 +
                                    (uint32_t)(((dd * 2 + ahalf) ^ (row & 7)) * 16);
                ldsm4(kh, ka);
                ldsm4(kl, ka + 8192);
            }
#pragma unroll
            for (int h = 0; h < 2; h++) {
                mma16816(s[h], qh, kh[h], kh[h + 2]);
                mma16816(s[h], qh, kl[h], kl[h + 2]);
                mma16816(s[h], ql, kh[h], kh[h + 2]);
            }
        }

        // ---- bias + exp2 + row sums (+ buckets) ----
        float rs0 = 0.f, rs1 = 0.f;
        const bool clampHi = (delta >= 192), clampLo = (delta <= -160);
        if (clampHi || clampLo) {
            const float b0 = clampHi ? bc0_hi : bc0_lo;
            const float b1 = clampHi ? bc1_hi : bc1_lo;
#pragma unroll
            for (int h = 0; h < 2; h++)
#pragma unroll
                for (int e = 0; e < 4; e++) {
                    const float p = exp2f(s[h][e] + ((e >= 2) ? b1 : b0));
                    s[h][e] = p;
                    if (e >= 2) rs1 += p; else rs0 += p;
                }
            if (clampHi) { hi0 += rs0; hi1 += rs1; }
            else         { lo0 += rs0; lo1 += rs1; }
        } else {
#pragma unroll
            for (int h = 0; h < 2; h++) {
                const int kg = k0 + wn * 16 + h * 8 + tig * 2;
#pragma unroll
                for (int e = 0; e < 4; e++) {
                    const int ql2 = (e >= 2) ? row1l : row0l;
                    const int dist = (q0 + ql2) - (kg + (e & 1));
                    const int r = dist < -128 ? 0 : (dist > 128 ? 256 : dist + 128);
                    const float p = exp2f(s[h][e] + __ldg(&btq[(size_t)ql2 * RSTR + r]));
                    s[h][e] = p;
                    if (e >= 2) rs1 += p; else rs0 += p;
                }
            }
#pragma unroll
            for (int h = 0; h < 2; h++) {
                const int kg = k0 + wn * 16 + h * 8 + tig * 2;
#pragma unroll
                for (int e = 0; e < 4; e++) {
                    const int ql2 = (e >= 2) ? row1l : row0l;
                    const int dist = (q0 + ql2) - (kg + (e & 1));
                    const int r = dist < -128 ? 0 : (dist > 128 ? 256 : dist + 128);
                    atomicAdd(&Aa[ql2 * RSTR + r], s[h][e]);
                }
            }
        }
        ls0 += rs0; ls1 += rs1;

        // ---- P -> bf16 split A-frag (m16 x k16) ----
        uint32_t pah[4], pal[4];
#pragma unroll
        for (int a = 0; a < 4; a++) {
            const int h = a >> 1, eb = (a & 1) * 2;
            const float p0 = s[h][eb], p1 = s[h][eb + 1];
            const __nv_bfloat16 h0 = __float2bfloat16(p0), h1 = __float2bfloat16(p1);
            pah[a] = pack_bf2(h0, h1);
            pal[a] = pack_bf2(__float2bfloat16(p0 - __bfloat162float(h0)),
                              __float2bfloat16(p1 - __bfloat162float(h1)));
        }

        // ---- O += P V (warp's 16-k slice) ----
#pragma unroll
        for (int g = 0; g < 4; g++) {
            uint32_t vh[4], vl[4];
            const int krow = wn * 16 + arow;
            const uint32_t va = st + 16384 + (uint32_t)krow * 128 +
                                (uint32_t)(((g * 2 + ahalf) ^ (krow & 7)) * 16);
            ldsm4t(vh, va);
            ldsm4t(vl, va + 8192);
#pragma unroll
            for (int h = 0; h < 2; h++) {
                float* cc = o[g * 2 + h];
                mma16816(cc, pah, vh[h * 2], vh[h * 2 + 1]);
                mma16816(cc, pah, vl[h * 2], vl[h * 2 + 1]);
                mma16816(cc, pal, vh[h * 2], vh[h * 2 + 1]);
            }
        }
        __syncthreads();
        if (kt + 2 < 16) { issueKV(kt & 1, kt + 2); CP_COMMIT(); }
    }

    // ---- flush deferred reductions ----
    ls0 += __shfl_xor_sync(0xffffffffu, ls0, 1); ls0 += __shfl_xor_sync(0xffffffffu, ls0, 2);
    ls1 += __shfl_xor_sync(0xffffffffu, ls1, 1); ls1 += __shfl_xor_sync(0xffffffffu, ls1, 2);
    lo0 += __shfl_xor_sync(0xffffffffu, lo0, 1); lo0 += __shfl_xor_sync(0xffffffffu, lo0, 2);
    lo1 += __shfl_xor_sync(0xffffffffu, lo1, 1); lo1 += __shfl_xor_sync(0xffffffffu, lo1, 2);
    hi0 += __shfl_xor_sync(0xffffffffu, hi0, 1); hi0 += __shfl_xor_sync(0xffffffffu, hi0, 2);
    hi1 += __shfl_xor_sync(0xffffffffu, hi1, 1); hi1 += __shfl_xor_sync(0xffffffffu, hi1, 2);
    if (tig == 0) {
        atomicAdd(&lsum[row0l], ls0);
        atomicAdd(&lsum[row1l], ls1);
        atomicAdd(&Aa[row0l * RSTR + 0], lo0);
        atomicAdd(&Aa[row1l * RSTR + 0], lo1);
        atomicAdd(&Aa[row0l * RSTR + 256], hi0);
        atomicAdd(&Aa[row1l * RSTR + 256], hi1);
    }

    // ---- epilogue: reduce 4 wn partials, normalize, write w1 ----
    float* red = (float*)(smem + 8192);   // 3 blocks of 32x68 floats (stage area)
    if (wn > 0) {
        float* rb = red + (size_t)(wn - 1) * 32 * 68;
#pragma unroll
        for (int g = 0; g < 8; g++) {
            const int col = g * 8 + tig * 2;
            *(float2*)&rb[row0l * 68 + col] = make_float2(o[g][0], o[g][1]);
            *(float2*)&rb[row1l * 68 + col] = make_float2(o[g][2], o[g][3]);
        }
    }
    __syncthreads();
    if (wn == 0) {
        const float inv0 = 1.f / lsum[row0l];
        const float inv1 = 1.f / lsum[row1l];
#pragma unroll
        for (int g = 0; g < 8; g++) {
            const int col = g * 8 + tig * 2;
            float a0 = o[g][0], a1 = o[g][1], a2 = o[g][2], a3 = o[g][3];
#pragma unroll
            for (int wv = 0; wv < 3; wv++) {
                const float* rb = red + (size_t)wv * 32 * 68;
                const float2 r0 = *(const float2*)&rb[row0l * 68 + col];
                const float2 r1 = *(const float2*)&rb[row1l * 68 + col];
                a0 += r0.x; a1 += r0.y; a2 += r1.x; a3 += r1.y;
            }
            float2 v0 = make_float2(a0 * inv0, a1 * inv0);
            float2 v1 = make_float2(a2 * inv1, a3 * inv1);
            *(float2*)&c1[(size_t)(bb * 1024 + q0 + row0l) * EDIM + hh * 64 + col] = v0;
            *(float2*)&c1[(size_t)(bb * 1024 + q0 + row1l) * EDIM + hh * 64 + col] = v1;
        }
    }

    // ---- w2 = (A/l) @ relv  -> sigma^-1 slot (2 rows/thread) ----
    const int ty = tid >> 4, tx = tid & 15;   // ty 0..15 -> rows ty*2, ty*2+1
    u64t w2a[2][2];
    w2a[0][0] = w2a[0][1] = w2a[1][0] = w2a[1][1] = 0ull;
    float invv[2];
    invv[0] = 1.f / lsum[ty * 2 + 0];
    invv[1] = 1.f / lsum[ty * 2 + 1];

    for (int r = 0; r < 257; r++) {
        const u64t bv0 = *(const u64t*)(relv + (size_t)r * 64 + tx * 4);
        const u64t bv1 = *(const u64t*)(relv + (size_t)r * 64 + tx * 4 + 2);
#pragma unroll
        for (int i = 0; i < 2; i++) {
            const u64t ad = pk2(Aa[(ty * 2 + i) * RSTR + r]);
            fma2(w2a[i][0], ad, bv0);
            fma2(w2a[i][1], ad, bv1);
        }
    }
    const int b2 = slot & 3, h2 = slot >> 2;
#pragma unroll
    for (int i = 0; i < 2; i++) {
        const int qg = q0 + ty * 2 + i;
        const float2 p0 = unpk(w2a[i][0]);
        const float2 p1 = unpk(w2a[i][1]);
        float4 v = make_float4(p0.x * invv[i], p0.y * invv[i], p1.x * invv[i], p1.y * invv[i]);
        *(float4*)&c2[(size_t)(b2 * 1024 + qg) * 1024 + h2 * 64 + tx * 4] = v;
    }
}

// ---------------------------------------------------------------------------
extern "C" void kernel_launch(void* const* d_in, const int* in_sizes, int n_in,
                              void* d_out, int out_size)
{
    const float* X    = (const float*)d_in[0];
    const float* Wq   = (const float*)d_in[1];
    const float* bq   = (const float*)d_in[2];
    const float* Wk   = (const float*)d_in[3];
    const float* bk   = (const float*)d_in[4];
    const float* Wv   = (const float*)d_in[5];
    const float* bv   = (const float*)d_in[6];
    const float* Wo   = (const float*)d_in[7];
    const float* bo   = (const float*)d_in[8];
    const float* relk = (const float*)d_in[9];
    const float* relv = (const float*)d_in[10];
    float* out = (float*)d_out;

    float *pB, *pc1, *pc2;
    cudaGetSymbolAddress((void**)&pB,  g_B);
    cudaGetSymbolAddress((void**)&pc1, g_c1);
    cudaGetSymbolAddress((void**)&pc2, g_c2);
    __nv_bfloat16 *pXh, *pXl, *pWqh, *pWql, *pWkh, *pWkl, *pWvh, *pWvl, *pWoh, *pWol;
    __nv_bfloat16 *pQbh, *pQbl, *pKbh, *pKbl, *pVbh, *pVbl, *pRkh, *pRkl;
    cudaGetSymbolAddress((void**)&pXh,  g_Xh);
    cudaGetSymbolAddress((void**)&pXl,  g_Xl);
    cudaGetSymbolAddress((void**)&pWqh, g_Wqh);
    cudaGetSymbolAddress((void**)&pWql, g_Wql);
    cudaGetSymbolAddress((void**)&pWkh, g_Wkh);
    cudaGetSymbolAddress((void**)&pWkl, g_Wkl);
    cudaGetSymbolAddress((void**)&pWvh, g_Wvh);
    cudaGetSymbolAddress((void**)&pWvl, g_Wvl);
    cudaGetSymbolAddress((void**)&pWoh, g_Woh);
    cudaGetSymbolAddress((void**)&pWol, g_Wol);
    cudaGetSymbolAddress((void**)&pQbh, g_Qbh);
    cudaGetSymbolAddress((void**)&pQbl, g_Qbl);
    cudaGetSymbolAddress((void**)&pKbh, g_Kbh);
    cudaGetSymbolAddress((void**)&pKbl, g_Kbl);
    cudaGetSymbolAddress((void**)&pVbh, g_Vbh);
    cudaGetSymbolAddress((void**)&pVbl, g_Vbl);
    cudaGetSymbolAddress((void**)&pRkh, g_Rkh);
    cudaGetSymbolAddress((void**)&pRkl, g_Rkl);

    CvtParams cp;
    cp.X = X; cp.Wq = Wq; cp.Wk = Wk; cp.Wv = Wv; cp.Wo = Wo; cp.relk = relk;
    cp.Xh = pXh; cp.Xl = pXl;
    cp.Wqh = pWqh; cp.Wql = pWql; cp.Wkh = pWkh; cp.Wkl = pWkl;
    cp.Wvh = pWvh; cp.Wvl = pWvl; cp.Woh = pWoh; cp.Wol = pWol;
    cp.Rkh = pRkh; cp.Rkl = pRkl;
    cvt_all<<<8192 + 20, 256>>>(cp);

    cudaFuncSetAttribute(mma_gemm,  cudaFuncAttributeMaxDynamicSharedMemorySize, GSMEM);
    cudaFuncSetAttribute(mma_gemm3, cudaFuncAttributeMaxDynamicSharedMemorySize, GSMEM);

    // Q alpha = 0.125/ln2: scores and bias table in log2 units -> exp2f.
    G3Params p;
    p.Bh[0] = pWqh; p.Bl[0] = pWql; p.bias[0] = bq; p.oh[0] = pQbh; p.ol[0] = pQbl;
    p.alpha[0] = 0.125f * 1.4426950408889634f;
    p.Bh[1] = pWkh; p.Bl[1] = pWkl; p.bias[1] = bk; p.oh[1] = pKbh; p.ol[1] = pKbl;
    p.alpha[1] = 1.0f;
    p.Bh[2] = pWvh; p.Bl[2] = pWvl; p.bias[2] = bv; p.oh[2] = pVbh; p.ol[2] = pVbl;
    p.alpha[2] = 1.0f;
    mma_gemm3<<<dim3(EDIM / 128, MROWS / 128, 3), 256, GSMEM>>>(pXh, pXl, p);

    cudaFuncSetAttribute(bias_mma, cudaFuncAttributeMaxDynamicSharedMemorySize, BIAS_SMEM);
    bias_mma<<<dim3(16, 64), 128, BIAS_SMEM>>>(pQbh, pQbl, pRkh, pRkl, pB);

    cudaFuncSetAttribute(attn2, cudaFuncAttributeMaxDynamicSharedMemorySize, ATT_SMEM);
    attn2<<<dim3(32, 64), 256, ATT_SMEM>>>(pQbh, pQbl, pKbh, pKbl, pVbh, pVbl,
                                           pB, relv, pc1, pc2);

    cvt_add_split<<<MROWS * EDIM / 1024, 256>>>(pc1, pc2, pXh, pXl);
    mma_gemm<<<dim3(EDIM / 128, MROWS / 128), 256, GSMEM>>>(pXh, pXl, pWoh, pWol, bo, out,
                                                            1.0f, nullptr, nullptr);
}

// round 14
// speedup vs baseline: 1.3138x; 1.0866x over previous
#include <cuda_runtime.h>
#include <cuda_bf16.h>
#include <cstdint>

// ---------------------------------------------------------------------------
// MultiheadRelativeAttention: B=4, T=1024, E=1024, H=16, D=64, MAX_REL=128
// Round 14: attn2 smem-traffic cut — K and V single bf16 (decorrelated
// rounding, error ~1e-4), Q/P stay split; Q fragments hoisted to registers.
// GEMM/bias/conversions unchanged (round 12/13 proven).
// ---------------------------------------------------------------------------

#define MROWS 4096      // B*T
#define EDIM  1024
#define RSTR  260       // padded stride for 257 relative positions

typedef unsigned long long u64t;

__device__ float g_B [64 * 1024 * RSTR];   // bias table per source slot (log2 units)
__device__ float g_c1[MROWS * EDIM];
__device__ float g_c2[MROWS * EDIM];

__device__ __nv_bfloat16 g_Xh[MROWS * EDIM];
__device__ __nv_bfloat16 g_Xl[MROWS * EDIM];
__device__ __nv_bfloat16 g_Wqh[EDIM * EDIM], g_Wql[EDIM * EDIM];
__device__ __nv_bfloat16 g_Wkh[EDIM * EDIM], g_Wkl[EDIM * EDIM];
__device__ __nv_bfloat16 g_Wvh[EDIM * EDIM], g_Wvl[EDIM * EDIM];
__device__ __nv_bfloat16 g_Woh[EDIM * EDIM], g_Wol[EDIM * EDIM];
__device__ __nv_bfloat16 g_Qbh[MROWS * EDIM], g_Qbl[MROWS * EDIM];
__device__ __nv_bfloat16 g_Kbh[MROWS * EDIM];   // K single
__device__ __nv_bfloat16 g_Vbh[MROWS * EDIM];   // V single
__device__ __nv_bfloat16 g_Rkh[320 * 64], g_Rkl[320 * 64];

// ---------------------------------------------------------------------------
// helpers
// ---------------------------------------------------------------------------
__device__ __forceinline__ uint32_t smem_to_u32(const void* p) {
    uint32_t a;
    asm("{ .reg .u64 t; cvta.to.shared.u64 t, %1; cvt.u32.u64 %0, t; }" : "=r"(a) : "l"(p));
    return a;
}
__device__ __forceinline__ void cpasync16(uint32_t dst, const void* src) {
    asm volatile("cp.async.cg.shared.global [%0], [%1], 16;" :: "r"(dst), "l"(src));
}
#define CP_COMMIT() asm volatile("cp.async.commit_group;" ::: "memory")
#define CP_WAIT(n)  asm volatile("cp.async.wait_group %0;" :: "n"(n) : "memory")

__device__ __forceinline__ void ldsm4(uint32_t* r, uint32_t addr) {
    asm volatile("ldmatrix.sync.aligned.m8n8.x4.shared.b16 {%0,%1,%2,%3}, [%4];"
                 : "=r"(r[0]), "=r"(r[1]), "=r"(r[2]), "=r"(r[3]) : "r"(addr));
}
__device__ __forceinline__ void ldsm4t(uint32_t* r, uint32_t addr) {
    asm volatile("ldmatrix.sync.aligned.m8n8.x4.trans.shared.b16 {%0,%1,%2,%3}, [%4];"
                 : "=r"(r[0]), "=r"(r[1]), "=r"(r[2]), "=r"(r[3]) : "r"(addr));
}
__device__ __forceinline__ void mma16816(float* c, const uint32_t* a, uint32_t b0, uint32_t b1) {
    asm volatile("mma.sync.aligned.m16n8k16.row.col.f32.bf16.bf16.f32 "
                 "{%0,%1,%2,%3}, {%4,%5,%6,%7}, {%8,%9}, {%0,%1,%2,%3};"
                 : "+f"(c[0]), "+f"(c[1]), "+f"(c[2]), "+f"(c[3])
                 : "r"(a[0]), "r"(a[1]), "r"(a[2]), "r"(a[3]), "r"(b0), "r"(b1));
}
__device__ __forceinline__ uint32_t pack_bf2(__nv_bfloat16 lo, __nv_bfloat16 hi) {
    return ((uint32_t)__bfloat16_as_ushort(hi) << 16) | (uint32_t)__bfloat16_as_ushort(lo);
}
__device__ __forceinline__ u64t pk2(float x) {
    u64t r; asm("mov.b64 %0, {%1, %1};" : "=l"(r) : "f"(x)); return r;
}
__device__ __forceinline__ void fma2(u64t& d, u64t a, u64t b) {
    asm("fma.rn.f32x2 %0, %1, %2, %0;" : "+l"(d) : "l"(a), "l"(b));
}
__device__ __forceinline__ float2 unpk(u64t v) {
    float2 f; asm("mov.b64 {%0, %1}, %2;" : "=f"(f.x), "=f"(f.y) : "l"(v)); return f;
}

// ---------------------------------------------------------------------------
// merged input conversions
// ---------------------------------------------------------------------------
struct CvtParams {
    const float *X, *Wq, *Wk, *Wv, *Wo, *relk;
    __nv_bfloat16 *Xh, *Xl, *Wqh, *Wql, *Wkh, *Wkl, *Wvh, *Wvl, *Woh, *Wol, *Rkh, *Rkl;
};

__device__ __forceinline__ void split4(const float* __restrict__ src,
                                       __nv_bfloat16* __restrict__ hi,
                                       __nv_bfloat16* __restrict__ lo, int i)
{
    float4 v = *(const float4*)(src + i);
    __nv_bfloat16 h0 = __float2bfloat16(v.x), h1 = __float2bfloat16(v.y);
    __nv_bfloat16 h2 = __float2bfloat16(v.z), h3 = __float2bfloat16(v.w);
    ((uint32_t*)(hi + i))[0] = pack_bf2(h0, h1);
    ((uint32_t*)(hi + i))[1] = pack_bf2(h2, h3);
    ((uint32_t*)(lo + i))[0] = pack_bf2(__float2bfloat16(v.x - __bfloat162float(h0)),
                                        __float2bfloat16(v.y - __bfloat162float(h1)));
    ((uint32_t*)(lo + i))[1] = pack_bf2(__float2bfloat16(v.z - __bfloat162float(h2)),
                                        __float2bfloat16(v.w - __bfloat162float(h3)));
}

__global__ __launch_bounds__(256)
void cvt_all(CvtParams p)
{
    const int bid = blockIdx.x;
    if (bid < 4096) {
        split4(p.X, p.Xh, p.Xl, (bid * 256 + threadIdx.x) * 4);
    } else if (bid < 8192) {
        const int w = (bid - 4096) >> 10;
        const int lb = (bid - 4096) & 1023;
        const int i = (lb * 256 + threadIdx.x) * 4;
        if (w == 0)      split4(p.Wq, p.Wqh, p.Wql, i);
        else if (w == 1) split4(p.Wk, p.Wkh, p.Wkl, i);
        else if (w == 2) split4(p.Wv, p.Wvh, p.Wvl, i);
        else             split4(p.Wo, p.Woh, p.Wol, i);
    } else {
        const int base = (bid - 8192) * 1024 + threadIdx.x * 4;
#pragma unroll
        for (int k = 0; k < 4; k++) {
            const int i = base + k;
            if (i >= 320 * 64) break;
            const int r = i >> 6, d = i & 63;
            const float v = (r < 257) ? p.relk[r * 64 + d] : 0.f;
            const __nv_bfloat16 h = __float2bfloat16(v);
            p.Rkh[i] = h;
            p.Rkl[i] = __float2bfloat16(v - __bfloat162float(h));
        }
    }
}

__global__ __launch_bounds__(256)
void cvt_add_split(const float* __restrict__ a, const float* __restrict__ b,
                   __nv_bfloat16* __restrict__ hi, __nv_bfloat16* __restrict__ lo)
{
    const int i = (blockIdx.x * 256 + threadIdx.x) * 4;
    float4 va = *(const float4*)(a + i);
    float4 vb = *(const float4*)(b + i);
    float4 v = make_float4(va.x + vb.x, va.y + vb.y, va.z + vb.z, va.w + vb.w);
    __nv_bfloat16 h0 = __float2bfloat16(v.x), h1 = __float2bfloat16(v.y);
    __nv_bfloat16 h2 = __float2bfloat16(v.z), h3 = __float2bfloat16(v.w);
    ((uint32_t*)(hi + i))[0] = pack_bf2(h0, h1);
    ((uint32_t*)(hi + i))[1] = pack_bf2(h2, h3);
    ((uint32_t*)(lo + i))[0] = pack_bf2(__float2bfloat16(v.x - __bfloat162float(h0)),
                                        __float2bfloat16(v.y - __bfloat162float(h1)));
    ((uint32_t*)(lo + i))[1] = pack_bf2(__float2bfloat16(v.z - __bfloat162float(h2)),
                                        __float2bfloat16(v.w - __bfloat162float(h3)));
}

// ---------------------------------------------------------------------------
// GEMM core (round-8 proven); hi/lo output streams independently nullable.
// ---------------------------------------------------------------------------
#define GSTAGE 65536
#define GSMEM  (3 * GSTAGE)

__device__ __forceinline__ void gemm_core(
    const __nv_bfloat16* __restrict__ Ah, const __nv_bfloat16* __restrict__ Al,
    const __nv_bfloat16* __restrict__ Bh, const __nv_bfloat16* __restrict__ Bl,
    const float* __restrict__ bias, float* __restrict__ C, float alpha,
    __nv_bfloat16* __restrict__ ohi, __nv_bfloat16* __restrict__ olo)
{
    extern __shared__ char smem[];
    const uint32_t sb = smem_to_u32(smem);
    const int tid = threadIdx.x;
    const int wid = tid >> 5, lane = tid & 31;
    const int wm = wid >> 1, wn = wid & 1;
    const int n0 = blockIdx.x * 128, m0 = blockIdx.y * 128;

    float acc[2][8][4];
#pragma unroll
    for (int f = 0; f < 2; f++)
#pragma unroll
        for (int nf = 0; nf < 8; nf++)
#pragma unroll
            for (int e = 0; e < 4; e++) acc[f][nf][e] = 0.f;

    auto issue = [&](int stage, int c) {
        const uint32_t tbs = sb + stage * GSTAGE;
        const int k0 = c * 64;
#pragma unroll
        for (int g = 0; g < 4; g++) {
            const int gi = g * 256 + tid;
            const int row = gi >> 3, gc = gi & 7;
            const uint32_t bo = row * 128 + gc * 16;
            const uint32_t sw = bo ^ ((bo >> 3) & 0x70);
            const size_t aoff = (size_t)(m0 + row) * EDIM + k0 + gc * 8;
            const size_t boff = (size_t)(n0 + row) * EDIM + k0 + gc * 8;
            cpasync16(tbs + sw,         Ah + aoff);
            cpasync16(tbs + 16384 + sw, Al + aoff);
            cpasync16(tbs + 32768 + sw, Bh + boff);
            cpasync16(tbs + 49152 + sw, Bl + boff);
        }
        CP_COMMIT();
    };

    issue(0, 0);
    issue(1, 1);

    const int arow = lane & 15;
    const int achk = lane >> 4;

    uint32_t fah[2][2][4], fal[2][2][4], fbh[2][4][4], fbl[2][4][4];
    auto ldfrag = [&](int buf, int kk, uint32_t st) {
        const int chS = (kk * 2 + achk) ^ (arow & 7);
#pragma unroll
        for (int f = 0; f < 2; f++) {
            const uint32_t ra = st + (uint32_t)(wm * 32 + f * 16 + arow) * 128 + chS * 16;
            ldsm4(fah[buf][f], ra);
            ldsm4(fal[buf][f], ra + 16384);
        }
#pragma unroll
        for (int nb = 0; nb < 4; nb++) {
            const uint32_t rb = st + 32768 + (uint32_t)(wn * 64 + nb * 16 + arow) * 128 + chS * 16;
            ldsm4(fbh[buf][nb], rb);
            ldsm4(fbl[buf][nb], rb + 16384);
        }
    };

    for (int c = 0; c < 16; c++) {
        if (c + 2 < 16) issue((c + 2) % 3, c + 2);
        if (c <= 13)      { CP_WAIT(2); }
        else if (c == 14) { CP_WAIT(1); }
        else              { CP_WAIT(0); }
        __syncthreads();

        const uint32_t st = sb + (c % 3) * GSTAGE;
        ldfrag(0, 0, st);
#pragma unroll
        for (int kk = 0; kk < 4; kk++) {
            const int cur = kk & 1;
            if (kk < 3) ldfrag(cur ^ 1, kk + 1, st);
#pragma unroll
            for (int f = 0; f < 2; f++)
#pragma unroll
                for (int nb = 0; nb < 4; nb++)
#pragma unroll
                    for (int h = 0; h < 2; h++) {
                        float* cc = acc[f][nb * 2 + h];
                        mma16816(cc, fah[cur][f], fbh[cur][nb][h], fbh[cur][nb][h + 2]);
                        mma16816(cc, fah[cur][f], fbl[cur][nb][h], fbl[cur][nb][h + 2]);
                        mma16816(cc, fal[cur][f], fbh[cur][nb][h], fbh[cur][nb][h + 2]);
                    }
        }
        __syncthreads();
    }

    const int gid = lane >> 2, tig = lane & 3;
#pragma unroll
    for (int f = 0; f < 2; f++) {
        const int m = m0 + wm * 32 + f * 16 + gid;
#pragma unroll
        for (int nb = 0; nb < 4; nb++)
#pragma unroll
            for (int h = 0; h < 2; h++) {
                const int n = n0 + wn * 64 + nb * 16 + h * 8 + tig * 2;
                const float* cc = acc[f][nb * 2 + h];
                const float b0 = __ldg(&bias[n]), b1 = __ldg(&bias[n + 1]);
                float2 v0 = make_float2(alpha * (cc[0] + b0), alpha * (cc[1] + b1));
                float2 v1 = make_float2(alpha * (cc[2] + b0), alpha * (cc[3] + b1));
                if (C) {
                    *(float2*)&C[(size_t)m * EDIM + n]       = v0;
                    *(float2*)&C[(size_t)(m + 8) * EDIM + n] = v1;
                }
                __nv_bfloat16 h00 = __float2bfloat16(v0.x), h01 = __float2bfloat16(v0.y);
                __nv_bfloat16 h10 = __float2bfloat16(v1.x), h11 = __float2bfloat16(v1.y);
                if (ohi) {
                    *(uint32_t*)(ohi + (size_t)m * EDIM + n)       = pack_bf2(h00, h01);
                    *(uint32_t*)(ohi + (size_t)(m + 8) * EDIM + n) = pack_bf2(h10, h11);
                }
                if (olo) {
                    *(uint32_t*)(olo + (size_t)m * EDIM + n) =
                        pack_bf2(__float2bfloat16(v0.x - __bfloat162float(h00)),
                                 __float2bfloat16(v0.y - __bfloat162float(h01)));
                    *(uint32_t*)(olo + (size_t)(m + 8) * EDIM + n) =
                        pack_bf2(__float2bfloat16(v1.x - __bfloat162float(h10)),
                                 __float2bfloat16(v1.y - __bfloat162float(h11)));
                }
            }
    }
}

__global__ __launch_bounds__(256, 1)
void mma_gemm(const __nv_bfloat16* __restrict__ Ah, const __nv_bfloat16* __restrict__ Al,
              const __nv_bfloat16* __restrict__ Bh, const __nv_bfloat16* __restrict__ Bl,
              const float* __restrict__ bias, float* __restrict__ C, float alpha,
              __nv_bfloat16* __restrict__ ohi, __nv_bfloat16* __restrict__ olo)
{
    gemm_core(Ah, Al, Bh, Bl, bias, C, alpha, ohi, olo);
}

struct G3Params {
    const __nv_bfloat16* Bh[3]; const __nv_bfloat16* Bl[3];
    const float* bias[3];
    __nv_bfloat16* oh[3]; __nv_bfloat16* ol[3];
    float alpha[3];
};
__global__ __launch_bounds__(256, 1)
void mma_gemm3(const __nv_bfloat16* __restrict__ Ah, const __nv_bfloat16* __restrict__ Al,
               G3Params p)
{
    const int z = blockIdx.z;
    gemm_core(Ah, Al, p.Bh[z], p.Bl[z], p.bias[z], nullptr, p.alpha[z], p.oh[z], p.ol[z]);
}

// ---------------------------------------------------------------------------
// Bias table via mma, r-tiles looped in-CTA (round 12, unchanged)
// ---------------------------------------------------------------------------
#define BIAS_SMEM 49152
__global__ __launch_bounds__(128, 1)
void bias_mma(const __nv_bfloat16* __restrict__ Qbh, const __nv_bfloat16* __restrict__ Qbl,
              const __nv_bfloat16* __restrict__ Rh, const __nv_bfloat16* __restrict__ Rl,
              float* __restrict__ Bt)
{
    extern __shared__ char smem[];
    const uint32_t sb = smem_to_u32(smem);
    const int jslot = blockIdx.y;
    const int bb = jslot >> 4, hh = jslot & 15;
    const int q0 = blockIdx.x * 64;
    const int tid = threadIdx.x, wid = tid >> 5, lane = tid & 31;
    const int wm = wid >> 1, wn = wid & 1;
    const int arow = lane & 15, ahalf = lane >> 4;

    auto issueR = [&](int stg, int rt) {
        const uint32_t base = sb + 16384 + stg * 16384;
        const int r0 = rt * 64;
#pragma unroll
        for (int g = 0; g < 4; g++) {
            const int i = g * 128 + tid;
            const int row = i >> 3, c = i & 7;
            const uint32_t sw = (uint32_t)row * 128 + (uint32_t)((c ^ (row & 7)) * 16);
            const size_t ro = (size_t)(r0 + row) * 64 + c * 8;
            cpasync16(base + sw,        Rh + ro);
            cpasync16(base + 8192 + sw, Rl + ro);
        }
    };

#pragma unroll
    for (int g = 0; g < 4; g++) {
        const int i = g * 128 + tid;
        const int row = i >> 3, c = i & 7;
        const uint32_t sw = (uint32_t)row * 128 + (uint32_t)((c ^ (row & 7)) * 16);
        const size_t qo = (size_t)(bb * 1024 + q0 + row) * EDIM + hh * 64 + c * 8;
        cpasync16(sb + sw,        Qbh + qo);
        cpasync16(sb + 8192 + sw, Qbl + qo);
    }
    issueR(0, 0);
    CP_COMMIT();

    uint32_t qh[4][2][4], qlr[4][2][4];
    bool qloaded = false;
    const int gid = lane >> 2, tig = lane & 3;
    float* btj = Bt + (size_t)jslot * 1024 * RSTR;

    for (int rt = 0; rt < 5; rt++) {
        if (rt + 1 < 5) { issueR((rt + 1) & 1, rt + 1); CP_COMMIT(); }
        if (rt < 4) { CP_WAIT(1); } else { CP_WAIT(0); }
        __syncthreads();

        if (!qloaded) {
            qloaded = true;
#pragma unroll
            for (int dd = 0; dd < 4; dd++)
#pragma unroll
                for (int mf = 0; mf < 2; mf++) {
                    const int row = wm * 32 + mf * 16 + arow;
                    const uint32_t addr = sb + (uint32_t)row * 128 +
                                          (uint32_t)(((dd * 2 + ahalf) ^ (row & 7)) * 16);
                    ldsm4(qh[dd][mf], addr);
                    ldsm4(qlr[dd][mf], addr + 8192);
                }
        }

        const uint32_t rbuf = sb + 16384 + (rt & 1) * 16384;
        float s[2][4][4];
#pragma unroll
        for (int mf = 0; mf < 2; mf++)
#pragma unroll
            for (int nf = 0; nf < 4; nf++)
#pragma unroll
                for (int e = 0; e < 4; e++) s[mf][nf][e] = 0.f;

#pragma unroll
        for (int dd = 0; dd < 4; dd++) {
            uint32_t bh[2][4], bl[2][4];
#pragma unroll
            for (int ng = 0; ng < 2; ng++) {
                const int row = wn * 32 + ng * 16 + arow;
                const uint32_t addr = rbuf + (uint32_t)row * 128 +
                                      (uint32_t)(((dd * 2 + ahalf) ^ (row & 7)) * 16);
                ldsm4(bh[ng], addr);
                ldsm4(bl[ng], addr + 8192);
            }
#pragma unroll
            for (int mf = 0; mf < 2; mf++)
#pragma unroll
                for (int ng = 0; ng < 2; ng++)
#pragma unroll
                    for (int h = 0; h < 2; h++) {
                        float* cc = s[mf][ng * 2 + h];
                        mma16816(cc, qh[dd][mf], bh[ng][h], bh[ng][h + 2]);
                        mma16816(cc, qh[dd][mf], bl[ng][h], bl[ng][h + 2]);
                        mma16816(cc, qlr[dd][mf], bh[ng][h], bh[ng][h + 2]);
                    }
        }
        __syncthreads();

        const int r0 = rt * 64;
#pragma unroll
        for (int mf = 0; mf < 2; mf++) {
            const int q = q0 + wm * 32 + mf * 16 + gid;
#pragma unroll
            for (int nf = 0; nf < 4; nf++) {
                const int r = r0 + wn * 32 + nf * 8 + tig * 2;
                const float* cc = s[mf][nf];
                if (r < 257) {
                    btj[(size_t)q * RSTR + r]       = cc[0];
                    btj[(size_t)(q + 8) * RSTR + r] = cc[2];
                }
                if (r + 1 < 257) {
                    btj[(size_t)q * RSTR + r + 1]       = cc[1];
                    btj[(size_t)(q + 8) * RSTR + r + 1] = cc[3];
                }
            }
        }
    }
}

// ---------------------------------------------------------------------------
// Fused relative attention, 32-row q-tile, 2 CTAs/SM, K/V single bf16.
// smem: Qh[0,4K) Ql[4K,8K) | 2 stages @8K+s*16K {Kh 8K, Vh 8K} |
//   lsum @40960 | Aa[32][260] @41984 -> total 75264
// ---------------------------------------------------------------------------
#define ASTG 16384
#define ATT_SMEM 75264

__global__ __launch_bounds__(256, 2)
void attn2(const __nv_bfloat16* __restrict__ Qh_, const __nv_bfloat16* __restrict__ Ql_,
           const __nv_bfloat16* __restrict__ Kh_, const __nv_bfloat16* __restrict__ Vh_,
           const float* __restrict__ Bt, const float* __restrict__ relv,
           float* __restrict__ c1, float* __restrict__ c2)
{
    extern __shared__ char smem[];
    const uint32_t sb = smem_to_u32(smem);
    float* lsum = (float*)(smem + 40960);
    float* Aa   = (float*)(smem + 41984);

    const int slot = blockIdx.y;
    const int q0 = blockIdx.x * 32;
    const int bb = slot >> 4, hh = slot & 15;
    const int jsrc = ((slot & 15) << 2) | (slot >> 4);   // sigma(slot)
    const int tid = threadIdx.x, wid = tid >> 5, lane = tid & 31;
    const int wm = wid >> 2, wn = wid & 3;               // 2(m) x 4(n)
    const int gid = lane >> 2, tig = lane & 3;
    const int arow = lane & 15, ahalf = lane >> 4;

    for (int f = tid; f < 32 * RSTR; f += 256) Aa[f] = 0.f;
    if (tid < 32) lsum[tid] = 0.f;

    auto issueKV = [&](int stg, int kt) {
        const uint32_t base = sb + 8192 + stg * ASTG;
        const int k0 = kt * 64;
#pragma unroll
        for (int g = 0; g < 2; g++) {
            const int i = g * 256 + tid;        // 0..511
            const int row = i >> 3, c = i & 7;
            const uint32_t sw = (uint32_t)row * 128 + (uint32_t)((c ^ (row & 7)) * 16);
            const size_t go = (size_t)(bb * 1024 + k0 + row) * EDIM + hh * 64 + c * 8;
            cpasync16(base + sw,        Kh_ + go);
            cpasync16(base + 8192 + sw, Vh_ + go);
        }
    };

    // group 0: Q(32 rows, hi+lo) + KV0 ; group 1: KV1
    {
        const int i = tid;                      // 0..255
        const int row = i >> 3, c = i & 7;
        const uint32_t sw = (uint32_t)row * 128 + (uint32_t)((c ^ (row & 7)) * 16);
        const size_t go = (size_t)(bb * 1024 + q0 + row) * EDIM + hh * 64 + c * 8;
        cpasync16(sb + sw,        Qh_ + go);
        cpasync16(sb + 4096 + sw, Ql_ + go);
    }
    issueKV(0, 0);
    CP_COMMIT();
    issueKV(1, 1);
    CP_COMMIT();

    float o[8][4];
#pragma unroll
    for (int nf = 0; nf < 8; nf++)
#pragma unroll
        for (int e = 0; e < 4; e++) o[nf][e] = 0.f;

    const float* btq = Bt + (size_t)jsrc * 1024 * RSTR + (size_t)q0 * RSTR;
    const int row0l = wm * 16 + gid, row1l = row0l + 8;   // 0..31

    const float bc0_lo = __ldg(&btq[(size_t)row0l * RSTR + 0]);
    const float bc0_hi = __ldg(&btq[(size_t)row0l * RSTR + 256]);
    const float bc1_lo = __ldg(&btq[(size_t)row1l * RSTR + 0]);
    const float bc1_hi = __ldg(&btq[(size_t)row1l * RSTR + 256]);
    float ls0 = 0.f, ls1 = 0.f, lo0 = 0.f, lo1 = 0.f, hi0 = 0.f, hi1 = 0.f;

    uint32_t qfh[4][4], qfl[4][4];   // hoisted Q fragments

    for (int kt = 0; kt < 16; kt++) {
        if (kt < 15) { CP_WAIT(1); } else { CP_WAIT(0); }
        __syncthreads();
        if (kt == 0) {
#pragma unroll
            for (int dd = 0; dd < 4; dd++) {
                const int row = wm * 16 + arow;
                const uint32_t qa = sb + (uint32_t)row * 128 +
                                    (uint32_t)(((dd * 2 + ahalf) ^ (row & 7)) * 16);
                ldsm4(qfh[dd], qa);
                ldsm4(qfl[dd], qa + 4096);
            }
        }
        const uint32_t st = sb + 8192 + (kt & 1) * ASTG;
        const int k0 = kt * 64;
        const int delta = q0 - k0;

        // ---- S = (Qh+Ql) K^T  (K single bf16) ----
        float s[2][4];
        s[0][0] = s[0][1] = s[0][2] = s[0][3] = 0.f;
        s[1][0] = s[1][1] = s[1][2] = s[1][3] = 0.f;
#pragma unroll
        for (int dd = 0; dd < 4; dd++) {
            uint32_t kh[4];
            const int row = wn * 16 + arow;
            const uint32_t ka = st + (uint32_t)row * 128 +
                                (uint32_t)(((dd * 2 + ahalf) ^ (row & 7)) * 16);
            ldsm4(kh, ka);
#pragma unroll
            for (int h = 0; h < 2; h++) {
                mma16816(s[h], qfh[dd], kh[h], kh[h + 2]);
                mma16816(s[h], qfl[dd], kh[h], kh[h + 2]);
            }
        }

        // ---- bias + exp2 + row sums (+ buckets) ----
        float rs0 = 0.f, rs1 = 0.f;
        const bool clampHi = (delta >= 192), clampLo = (delta <= -160);
        if (clampHi || clampLo) {
            const float b0 = clampHi ? bc0_hi : bc0_lo;
            const float b1 = clampHi ? bc1_hi : bc1_lo;
#pragma unroll
            for (int h = 0; h < 2; h++)
#pragma unroll
                for (int e = 0; e < 4; e++) {
                    const float p = exp2f(s[h][e] + ((e >= 2) ? b1 : b0));
                    s[h][e] = p;
                    if (e >= 2) rs1 += p; else rs0 += p;
                }
            if (clampHi) { hi0 += rs0; hi1 += rs1; }
            else         { lo0 += rs0; lo1 += rs1; }
        } else {
#pragma unroll
            for (int h = 0; h < 2; h++) {
                const int kg = k0 + wn * 16 + h * 8 + tig * 2;
#pragma unroll
                for (int e = 0; e < 4; e++) {
                    const int ql2 = (e >= 2) ? row1l : row0l;
                    const int dist = (q0 + ql2) - (kg + (e & 1));
                    const int r = dist < -128 ? 0 : (dist > 128 ? 256 : dist + 128);
                    const float p = exp2f(s[h][e] + __ldg(&btq[(size_t)ql2 * RSTR + r]));
                    s[h][e] = p;
                    if (e >= 2) rs1 += p; else rs0 += p;
                }
            }
#pragma unroll
            for (int h = 0; h < 2; h++) {
                const int kg = k0 + wn * 16 + h * 8 + tig * 2;
#pragma unroll
                for (int e = 0; e < 4; e++) {
                    const int ql2 = (e >= 2) ? row1l : row0l;
                    const int dist = (q0 + ql2) - (kg + (e & 1));
                    const int r = dist < -128 ? 0 : (dist > 128 ? 256 : dist + 128);
                    atomicAdd(&Aa[ql2 * RSTR + r], s[h][e]);
                }
            }
        }
        ls0 += rs0; ls1 += rs1;

        // ---- P -> bf16 split A-frag ----
        uint32_t pah[4], pal[4];
#pragma unroll
        for (int a = 0; a < 4; a++) {
            const int h = a >> 1, eb = (a & 1) * 2;
            const float p0 = s[h][eb], p1 = s[h][eb + 1];
            const __nv_bfloat16 h0 = __float2bfloat16(p0), h1 = __float2bfloat16(p1);
            pah[a] = pack_bf2(h0, h1);
            pal[a] = pack_bf2(__float2bfloat16(p0 - __bfloat162float(h0)),
                              __float2bfloat16(p1 - __bfloat162float(h1)));
        }

        // ---- O += (Ph+Pl) V  (V single bf16) ----
#pragma unroll
        for (int g = 0; g < 4; g++) {
            uint32_t vh[4];
            const int krow = wn * 16 + arow;
            const uint32_t va = st + 8192 + (uint32_t)krow * 128 +
                                (uint32_t)(((g * 2 + ahalf) ^ (krow & 7)) * 16);
            ldsm4t(vh, va);
#pragma unroll
            for (int h = 0; h < 2; h++) {
                float* cc = o[g * 2 + h];
                mma16816(cc, pah, vh[h * 2], vh[h * 2 + 1]);
                mma16816(cc, pal, vh[h * 2], vh[h * 2 + 1]);
            }
        }
        __syncthreads();
        if (kt + 2 < 16) { issueKV(kt & 1, kt + 2); CP_COMMIT(); }
    }

    // ---- flush deferred reductions ----
    ls0 += __shfl_xor_sync(0xffffffffu, ls0, 1); ls0 += __shfl_xor_sync(0xffffffffu, ls0, 2);
    ls1 += __shfl_xor_sync(0xffffffffu, ls1, 1); ls1 += __shfl_xor_sync(0xffffffffu, ls1, 2);
    lo0 += __shfl_xor_sync(0xffffffffu, lo0, 1); lo0 += __shfl_xor_sync(0xffffffffu, lo0, 2);
    lo1 += __shfl_xor_sync(0xffffffffu, lo1, 1); lo1 += __shfl_xor_sync(0xffffffffu, lo1, 2);
    hi0 += __shfl_xor_sync(0xffffffffu, hi0, 1); hi0 += __shfl_xor_sync(0xffffffffu, hi0, 2);
    hi1 += __shfl_xor_sync(0xffffffffu, hi1, 1); hi1 += __shfl_xor_sync(0xffffffffu, hi1, 2);
    if (tig == 0) {
        atomicAdd(&lsum[row0l], ls0);
        atomicAdd(&lsum[row1l], ls1);
        atomicAdd(&Aa[row0l * RSTR + 0], lo0);
        atomicAdd(&Aa[row1l * RSTR + 0], lo1);
        atomicAdd(&Aa[row0l * RSTR + 256], hi0);
        atomicAdd(&Aa[row1l * RSTR + 256], hi1);
    }

    // ---- epilogue: reduce 4 wn partials, normalize, write w1 ----
    float* red = (float*)(smem + 8192);   // 3 blocks of 32x68 floats (stage area)
    if (wn > 0) {
        float* rb = red + (size_t)(wn - 1) * 32 * 68;
#pragma unroll
        for (int g = 0; g < 8; g++) {
            const int col = g * 8 + tig * 2;
            *(float2*)&rb[row0l * 68 + col] = make_float2(o[g][0], o[g][1]);
            *(float2*)&rb[row1l * 68 + col] = make_float2(o[g][2], o[g][3]);
        }
    }
    __syncthreads();
    if (wn == 0) {
        const float inv0 = 1.f / lsum[row0l];
        const float inv1 = 1.f / lsum[row1l];
#pragma unroll
        for (int g = 0; g < 8; g++) {
            const int col = g * 8 + tig * 2;
            float a0 = o[g][0], a1 = o[g][1], a2 = o[g][2], a3 = o[g][3];
#pragma unroll
            for (int wv = 0; wv < 3; wv++) {
                const float* rb = red + (size_t)wv * 32 * 68;
                const float2 r0 = *(const float2*)&rb[row0l * 68 + col];
                const float2 r1 = *(const float2*)&rb[row1l * 68 + col];
                a0 += r0.x; a1 += r0.y; a2 += r1.x; a3 += r1.y;
            }
            float2 v0 = make_float2(a0 * inv0, a1 * inv0);
            float2 v1 = make_float2(a2 * inv1, a3 * inv1);
            *(float2*)&c1[(size_t)(bb * 1024 + q0 + row0l) * EDIM + hh * 64 + col] = v0;
            *(float2*)&c1[(size_t)(bb * 1024 + q0 + row1l) * EDIM + hh * 64 + col] = v1;
        }
    }

    // ---- w2 = (A/l) @ relv  -> sigma^-1 slot (2 rows/thread) ----
    const int ty = tid >> 4, tx = tid & 15;
    u64t w2a[2][2];
    w2a[0][0] = w2a[0][1] = w2a[1][0] = w2a[1][1] = 0ull;
    float invv[2];
    invv[0] = 1.f / lsum[ty * 2 + 0];
    invv[1] = 1.f / lsum[ty * 2 + 1];

    for (int r = 0; r < 257; r++) {
        const u64t bv0 = *(const u64t*)(relv + (size_t)r * 64 + tx * 4);
        const u64t bv1 = *(const u64t*)(relv + (size_t)r * 64 + tx * 4 + 2);
#pragma unroll
        for (int i = 0; i < 2; i++) {
            const u64t ad = pk2(Aa[(ty * 2 + i) * RSTR + r]);
            fma2(w2a[i][0], ad, bv0);
            fma2(w2a[i][1], ad, bv1);
        }
    }
    const int b2 = slot & 3, h2 = slot >> 2;
#pragma unroll
    for (int i = 0; i < 2; i++) {
        const int qg = q0 + ty * 2 + i;
        const float2 p0 = unpk(w2a[i][0]);
        const float2 p1 = unpk(w2a[i][1]);
        float4 v = make_float4(p0.x * invv[i], p0.y * invv[i], p1.x * invv[i], p1.y * invv[i]);
        *(float4*)&c2[(size_t)(b2 * 1024 + qg) * 1024 + h2 * 64 + tx * 4] = v;
    }
}

// ---------------------------------------------------------------------------
extern "C" void kernel_launch(void* const* d_in, const int* in_sizes, int n_in,
                              void* d_out, int out_size)
{
    const float* X    = (const float*)d_in[0];
    const float* Wq   = (const float*)d_in[1];
    const float* bq   = (const float*)d_in[2];
    const float* Wk   = (const float*)d_in[3];
    const float* bk   = (const float*)d_in[4];
    const float* Wv   = (const float*)d_in[5];
    const float* bv   = (const float*)d_in[6];
    const float* Wo   = (const float*)d_in[7];
    const float* bo   = (const float*)d_in[8];
    const float* relk = (const float*)d_in[9];
    const float* relv = (const float*)d_in[10];
    float* out = (float*)d_out;

    float *pB, *pc1, *pc2;
    cudaGetSymbolAddress((void**)&pB,  g_B);
    cudaGetSymbolAddress((void**)&pc1, g_c1);
    cudaGetSymbolAddress((void**)&pc2, g_c2);
    __nv_bfloat16 *pXh, *pXl, *pWqh, *pWql, *pWkh, *pWkl, *pWvh, *pWvl, *pWoh, *pWol;
    __nv_bfloat16 *pQbh, *pQbl, *pKbh, *pVbh, *pRkh, *pRkl;
    cudaGetSymbolAddress((void**)&pXh,  g_Xh);
    cudaGetSymbolAddress((void**)&pXl,  g_Xl);
    cudaGetSymbolAddress((void**)&pWqh, g_Wqh);
    cudaGetSymbolAddress((void**)&pWql, g_Wql);
    cudaGetSymbolAddress((void**)&pWkh, g_Wkh);
    cudaGetSymbolAddress((void**)&pWkl, g_Wkl);
    cudaGetSymbolAddress((void**)&pWvh, g_Wvh);
    cudaGetSymbolAddress((void**)&pWvl, g_Wvl);
    cudaGetSymbolAddress((void**)&pWoh, g_Woh);
    cudaGetSymbolAddress((void**)&pWol, g_Wol);
    cudaGetSymbolAddress((void**)&pQbh, g_Qbh);
    cudaGetSymbolAddress((void**)&pQbl, g_Qbl);
    cudaGetSymbolAddress((void**)&pKbh, g_Kbh);
    cudaGetSymbolAddress((void**)&pVbh, g_Vbh);
    cudaGetSymbolAddress((void**)&pRkh, g_Rkh);
    cudaGetSymbolAddress((void**)&pRkl, g_Rkl);

    CvtParams cp;
    cp.X = X; cp.Wq = Wq; cp.Wk = Wk; cp.Wv = Wv; cp.Wo = Wo; cp.relk = relk;
    cp.Xh = pXh; cp.Xl = pXl;
    cp.Wqh = pWqh; cp.Wql = pWql; cp.Wkh = pWkh; cp.Wkl = pWkl;
    cp.Wvh = pWvh; cp.Wvl = pWvl; cp.Woh = pWoh; cp.Wol = pWol;
    cp.Rkh = pRkh; cp.Rkl = pRkl;
    cvt_all<<<8192 + 20, 256>>>(cp);

    cudaFuncSetAttribute(mma_gemm,  cudaFuncAttributeMaxDynamicSharedMemorySize, GSMEM);
    cudaFuncSetAttribute(mma_gemm3, cudaFuncAttributeMaxDynamicSharedMemorySize, GSMEM);

    // Q alpha = 0.125/ln2: scores and bias table in log2 units -> exp2f.
    // K and V write single bf16 (hi only).
    G3Params p;
    p.Bh[0] = pWqh; p.Bl[0] = pWql; p.bias[0] = bq; p.oh[0] = pQbh; p.ol[0] = pQbl;
    p.alpha[0] = 0.125f * 1.4426950408889634f;
    p.Bh[1] = pWkh; p.Bl[1] = pWkl; p.bias[1] = bk; p.oh[1] = pKbh; p.ol[1] = nullptr;
    p.alpha[1] = 1.0f;
    p.Bh[2] = pWvh; p.Bl[2] = pWvl; p.bias[2] = bv; p.oh[2] = pVbh; p.ol[2] = nullptr;
    p.alpha[2] = 1.0f;
    mma_gemm3<<<dim3(EDIM / 128, MROWS / 128, 3), 256, GSMEM>>>(pXh, pXl, p);

    cudaFuncSetAttribute(bias_mma, cudaFuncAttributeMaxDynamicSharedMemorySize, BIAS_SMEM);
    bias_mma<<<dim3(16, 64), 128, BIAS_SMEM>>>(pQbh, pQbl, pRkh, pRkl, pB);

    cudaFuncSetAttribute(attn2, cudaFuncAttributeMaxDynamicSharedMemorySize, ATT_SMEM);
    attn2<<<dim3(32, 64), 256, ATT_SMEM>>>(pQbh, pQbl, pKbh, pVbh,
                                           pB, relv, pc1, pc2);

    cvt_add_split<<<MROWS * EDIM / 1024, 256>>>(pc1, pc2, pXh, pXl);
    mma_gemm<<<dim3(EDIM / 128, MROWS / 128), 256, GSMEM>>>(pXh, pXl, pWoh, pWol, bo, out,
                                                            1.0f, nullptr, nullptr);
}

// round 15
// speedup vs baseline: 1.4631x; 1.1136x over previous
#include <cuda_runtime.h>
#include <cuda_bf16.h>
#include <cstdint>

// ---------------------------------------------------------------------------
// MultiheadRelativeAttention: B=4, T=1024, E=1024, H=16, D=64, MAX_REL=128
// Round 15: attn2's scalar w2 epilogue replaced by a bf16-split MMA GEMM
// (w2_gemm). attn2 writes normalized bucket matrix A/l as bf16 hi/lo.
// Everything else = round-14 best (680us).
// ---------------------------------------------------------------------------

#define MROWS 4096      // B*T
#define EDIM  1024
#define RSTR  260       // padded stride for 257 relative positions
#define ASTRIDE 320     // padded K for w2 gemm (260 -> 320)

typedef unsigned long long u64t;

__device__ float g_B [64 * 1024 * RSTR];   // bias table per source slot (log2 units)
__device__ float g_c1[MROWS * EDIM];
__device__ float g_c2[MROWS * EDIM];

__device__ __nv_bfloat16 g_Xh[MROWS * EDIM];
__device__ __nv_bfloat16 g_Xl[MROWS * EDIM];
__device__ __nv_bfloat16 g_Wqh[EDIM * EDIM], g_Wql[EDIM * EDIM];
__device__ __nv_bfloat16 g_Wkh[EDIM * EDIM], g_Wkl[EDIM * EDIM];
__device__ __nv_bfloat16 g_Wvh[EDIM * EDIM], g_Wvl[EDIM * EDIM];
__device__ __nv_bfloat16 g_Woh[EDIM * EDIM], g_Wol[EDIM * EDIM];
__device__ __nv_bfloat16 g_Qbh[MROWS * EDIM], g_Qbl[MROWS * EDIM];
__device__ __nv_bfloat16 g_Kbh[MROWS * EDIM];   // K single
__device__ __nv_bfloat16 g_Vbh[MROWS * EDIM];   // V single
__device__ __nv_bfloat16 g_Rkh[320 * 64], g_Rkl[320 * 64];
// normalized bucket matrix A/l, bf16 split, [64*1024][ASTRIDE]
__device__ __nv_bfloat16 g_A2h[64 * 1024 * ASTRIDE], g_A2l[64 * 1024 * ASTRIDE];
// relv transposed + zero-padded: Rvt[d][r], [64][ASTRIDE], bf16 split
__device__ __nv_bfloat16 g_Rvh[64 * ASTRIDE], g_Rvl[64 * ASTRIDE];

// ---------------------------------------------------------------------------
// helpers
// ---------------------------------------------------------------------------
__device__ __forceinline__ uint32_t smem_to_u32(const void* p) {
    uint32_t a;
    asm("{ .reg .u64 t; cvta.to.shared.u64 t, %1; cvt.u32.u64 %0, t; }" : "=r"(a) : "l"(p));
    return a;
}
__device__ __forceinline__ void cpasync16(uint32_t dst, const void* src) {
    asm volatile("cp.async.cg.shared.global [%0], [%1], 16;" :: "r"(dst), "l"(src));
}
#define CP_COMMIT() asm volatile("cp.async.commit_group;" ::: "memory")
#define CP_WAIT(n)  asm volatile("cp.async.wait_group %0;" :: "n"(n) : "memory")

__device__ __forceinline__ void ldsm4(uint32_t* r, uint32_t addr) {
    asm volatile("ldmatrix.sync.aligned.m8n8.x4.shared.b16 {%0,%1,%2,%3}, [%4];"
                 : "=r"(r[0]), "=r"(r[1]), "=r"(r[2]), "=r"(r[3]) : "r"(addr));
}
__device__ __forceinline__ void ldsm4t(uint32_t* r, uint32_t addr) {
    asm volatile("ldmatrix.sync.aligned.m8n8.x4.trans.shared.b16 {%0,%1,%2,%3}, [%4];"
                 : "=r"(r[0]), "=r"(r[1]), "=r"(r[2]), "=r"(r[3]) : "r"(addr));
}
__device__ __forceinline__ void mma16816(float* c, const uint32_t* a, uint32_t b0, uint32_t b1) {
    asm volatile("mma.sync.aligned.m16n8k16.row.col.f32.bf16.bf16.f32 "
                 "{%0,%1,%2,%3}, {%4,%5,%6,%7}, {%8,%9}, {%0,%1,%2,%3};"
                 : "+f"(c[0]), "+f"(c[1]), "+f"(c[2]), "+f"(c[3])
                 : "r"(a[0]), "r"(a[1]), "r"(a[2]), "r"(a[3]), "r"(b0), "r"(b1));
}
__device__ __forceinline__ uint32_t pack_bf2(__nv_bfloat16 lo, __nv_bfloat16 hi) {
    return ((uint32_t)__bfloat16_as_ushort(hi) << 16) | (uint32_t)__bfloat16_as_ushort(lo);
}

// ---------------------------------------------------------------------------
// merged input conversions
// block ranges: [0,4096) X | [4096,8192) weights | [8192,8212) relk |
//               [8212,8232) relv transposed split
// ---------------------------------------------------------------------------
struct CvtParams {
    const float *X, *Wq, *Wk, *Wv, *Wo, *relk, *relv;
    __nv_bfloat16 *Xh, *Xl, *Wqh, *Wql, *Wkh, *Wkl, *Wvh, *Wvl, *Woh, *Wol;
    __nv_bfloat16 *Rkh, *Rkl, *Rvh, *Rvl;
};

__device__ __forceinline__ void split4(const float* __restrict__ src,
                                       __nv_bfloat16* __restrict__ hi,
                                       __nv_bfloat16* __restrict__ lo, int i)
{
    float4 v = *(const float4*)(src + i);
    __nv_bfloat16 h0 = __float2bfloat16(v.x), h1 = __float2bfloat16(v.y);
    __nv_bfloat16 h2 = __float2bfloat16(v.z), h3 = __float2bfloat16(v.w);
    ((uint32_t*)(hi + i))[0] = pack_bf2(h0, h1);
    ((uint32_t*)(hi + i))[1] = pack_bf2(h2, h3);
    ((uint32_t*)(lo + i))[0] = pack_bf2(__float2bfloat16(v.x - __bfloat162float(h0)),
                                        __float2bfloat16(v.y - __bfloat162float(h1)));
    ((uint32_t*)(lo + i))[1] = pack_bf2(__float2bfloat16(v.z - __bfloat162float(h2)),
                                        __float2bfloat16(v.w - __bfloat162float(h3)));
}

__global__ __launch_bounds__(256)
void cvt_all(CvtParams p)
{
    const int bid = blockIdx.x;
    if (bid < 4096) {
        split4(p.X, p.Xh, p.Xl, (bid * 256 + threadIdx.x) * 4);
    } else if (bid < 8192) {
        const int w = (bid - 4096) >> 10;
        const int lb = (bid - 4096) & 1023;
        const int i = (lb * 256 + threadIdx.x) * 4;
        if (w == 0)      split4(p.Wq, p.Wqh, p.Wql, i);
        else if (w == 1) split4(p.Wk, p.Wkh, p.Wkl, i);
        else if (w == 2) split4(p.Wv, p.Wvh, p.Wvl, i);
        else             split4(p.Wo, p.Woh, p.Wol, i);
    } else if (bid < 8212) {
        const int base = (bid - 8192) * 1024 + threadIdx.x * 4;
#pragma unroll
        for (int k = 0; k < 4; k++) {
            const int i = base + k;
            if (i >= 320 * 64) break;
            const int r = i >> 6, d = i & 63;
            const float v = (r < 257) ? p.relk[r * 64 + d] : 0.f;
            const __nv_bfloat16 h = __float2bfloat16(v);
            p.Rkh[i] = h;
            p.Rkl[i] = __float2bfloat16(v - __bfloat162float(h));
        }
    } else {
        // relv transposed split: Rvt[d][r] = relv[r][d], padded r<320
        const int base = (bid - 8212) * 1024 + threadIdx.x * 4;
#pragma unroll
        for (int k = 0; k < 4; k++) {
            const int i = base + k;
            if (i >= 64 * ASTRIDE) break;
            const int d = i / ASTRIDE, r = i % ASTRIDE;
            const float v = (r < 257) ? p.relv[r * 64 + d] : 0.f;
            const __nv_bfloat16 h = __float2bfloat16(v);
            p.Rvh[i] = h;
            p.Rvl[i] = __float2bfloat16(v - __bfloat162float(h));
        }
    }
}

__global__ __launch_bounds__(256)
void cvt_add_split(const float* __restrict__ a, const float* __restrict__ b,
                   __nv_bfloat16* __restrict__ hi, __nv_bfloat16* __restrict__ lo)
{
    const int i = (blockIdx.x * 256 + threadIdx.x) * 4;
    float4 va = *(const float4*)(a + i);
    float4 vb = *(const float4*)(b + i);
    float4 v = make_float4(va.x + vb.x, va.y + vb.y, va.z + vb.z, va.w + vb.w);
    __nv_bfloat16 h0 = __float2bfloat16(v.x), h1 = __float2bfloat16(v.y);
    __nv_bfloat16 h2 = __float2bfloat16(v.z), h3 = __float2bfloat16(v.w);
    ((uint32_t*)(hi + i))[0] = pack_bf2(h0, h1);
    ((uint32_t*)(hi + i))[1] = pack_bf2(h2, h3);
    ((uint32_t*)(lo + i))[0] = pack_bf2(__float2bfloat16(v.x - __bfloat162float(h0)),
                                        __float2bfloat16(v.y - __bfloat162float(h1)));
    ((uint32_t*)(lo + i))[1] = pack_bf2(__float2bfloat16(v.z - __bfloat162float(h2)),
                                        __float2bfloat16(v.w - __bfloat162float(h3)));
}

// ---------------------------------------------------------------------------
// GEMM core (round-8 proven); hi/lo output streams independently nullable.
// ---------------------------------------------------------------------------
#define GSTAGE 65536
#define GSMEM  (3 * GSTAGE)

__device__ __forceinline__ void gemm_core(
    const __nv_bfloat16* __restrict__ Ah, const __nv_bfloat16* __restrict__ Al,
    const __nv_bfloat16* __restrict__ Bh, const __nv_bfloat16* __restrict__ Bl,
    const float* __restrict__ bias, float* __restrict__ C, float alpha,
    __nv_bfloat16* __restrict__ ohi, __nv_bfloat16* __restrict__ olo)
{
    extern __shared__ char smem[];
    const uint32_t sb = smem_to_u32(smem);
    const int tid = threadIdx.x;
    const int wid = tid >> 5, lane = tid & 31;
    const int wm = wid >> 1, wn = wid & 1;
    const int n0 = blockIdx.x * 128, m0 = blockIdx.y * 128;

    float acc[2][8][4];
#pragma unroll
    for (int f = 0; f < 2; f++)
#pragma unroll
        for (int nf = 0; nf < 8; nf++)
#pragma unroll
            for (int e = 0; e < 4; e++) acc[f][nf][e] = 0.f;

    auto issue = [&](int stage, int c) {
        const uint32_t tbs = sb + stage * GSTAGE;
        const int k0 = c * 64;
#pragma unroll
        for (int g = 0; g < 4; g++) {
            const int gi = g * 256 + tid;
            const int row = gi >> 3, gc = gi & 7;
            const uint32_t bo = row * 128 + gc * 16;
            const uint32_t sw = bo ^ ((bo >> 3) & 0x70);
            const size_t aoff = (size_t)(m0 + row) * EDIM + k0 + gc * 8;
            const size_t boff = (size_t)(n0 + row) * EDIM + k0 + gc * 8;
            cpasync16(tbs + sw,         Ah + aoff);
            cpasync16(tbs + 16384 + sw, Al + aoff);
            cpasync16(tbs + 32768 + sw, Bh + boff);
            cpasync16(tbs + 49152 + sw, Bl + boff);
        }
        CP_COMMIT();
    };

    issue(0, 0);
    issue(1, 1);

    const int arow = lane & 15;
    const int achk = lane >> 4;

    uint32_t fah[2][2][4], fal[2][2][4], fbh[2][4][4], fbl[2][4][4];
    auto ldfrag = [&](int buf, int kk, uint32_t st) {
        const int chS = (kk * 2 + achk) ^ (arow & 7);
#pragma unroll
        for (int f = 0; f < 2; f++) {
            const uint32_t ra = st + (uint32_t)(wm * 32 + f * 16 + arow) * 128 + chS * 16;
            ldsm4(fah[buf][f], ra);
            ldsm4(fal[buf][f], ra + 16384);
        }
#pragma unroll
        for (int nb = 0; nb < 4; nb++) {
            const uint32_t rb = st + 32768 + (uint32_t)(wn * 64 + nb * 16 + arow) * 128 + chS * 16;
            ldsm4(fbh[buf][nb], rb);
            ldsm4(fbl[buf][nb], rb + 16384);
        }
    };

    for (int c = 0; c < 16; c++) {
        if (c + 2 < 16) issue((c + 2) % 3, c + 2);
        if (c <= 13)      { CP_WAIT(2); }
        else if (c == 14) { CP_WAIT(1); }
        else              { CP_WAIT(0); }
        __syncthreads();

        const uint32_t st = sb + (c % 3) * GSTAGE;
        ldfrag(0, 0, st);
#pragma unroll
        for (int kk = 0; kk < 4; kk++) {
            const int cur = kk & 1;
            if (kk < 3) ldfrag(cur ^ 1, kk + 1, st);
#pragma unroll
            for (int f = 0; f < 2; f++)
#pragma unroll
                for (int nb = 0; nb < 4; nb++)
#pragma unroll
                    for (int h = 0; h < 2; h++) {
                        float* cc = acc[f][nb * 2 + h];
                        mma16816(cc, fah[cur][f], fbh[cur][nb][h], fbh[cur][nb][h + 2]);
                        mma16816(cc, fah[cur][f], fbl[cur][nb][h], fbl[cur][nb][h + 2]);
                        mma16816(cc, fal[cur][f], fbh[cur][nb][h], fbh[cur][nb][h + 2]);
                    }
        }
        __syncthreads();
    }

    const int gid = lane >> 2, tig = lane & 3;
#pragma unroll
    for (int f = 0; f < 2; f++) {
        const int m = m0 + wm * 32 + f * 16 + gid;
#pragma unroll
        for (int nb = 0; nb < 4; nb++)
#pragma unroll
            for (int h = 0; h < 2; h++) {
                const int n = n0 + wn * 64 + nb * 16 + h * 8 + tig * 2;
                const float* cc = acc[f][nb * 2 + h];
                const float b0 = __ldg(&bias[n]), b1 = __ldg(&bias[n + 1]);
                float2 v0 = make_float2(alpha * (cc[0] + b0), alpha * (cc[1] + b1));
                float2 v1 = make_float2(alpha * (cc[2] + b0), alpha * (cc[3] + b1));
                if (C) {
                    *(float2*)&C[(size_t)m * EDIM + n]       = v0;
                    *(float2*)&C[(size_t)(m + 8) * EDIM + n] = v1;
                }
                __nv_bfloat16 h00 = __float2bfloat16(v0.x), h01 = __float2bfloat16(v0.y);
                __nv_bfloat16 h10 = __float2bfloat16(v1.x), h11 = __float2bfloat16(v1.y);
                if (ohi) {
                    *(uint32_t*)(ohi + (size_t)m * EDIM + n)       = pack_bf2(h00, h01);
                    *(uint32_t*)(ohi + (size_t)(m + 8) * EDIM + n) = pack_bf2(h10, h11);
                }
                if (olo) {
                    *(uint32_t*)(olo + (size_t)m * EDIM + n) =
                        pack_bf2(__float2bfloat16(v0.x - __bfloat162float(h00)),
                                 __float2bfloat16(v0.y - __bfloat162float(h01)));
                    *(uint32_t*)(olo + (size_t)(m + 8) * EDIM + n) =
                        pack_bf2(__float2bfloat16(v1.x - __bfloat162float(h10)),
                                 __float2bfloat16(v1.y - __bfloat162float(h11)));
                }
            }
    }
}

__global__ __launch_bounds__(256, 1)
void mma_gemm(const __nv_bfloat16* __restrict__ Ah, const __nv_bfloat16* __restrict__ Al,
              const __nv_bfloat16* __restrict__ Bh, const __nv_bfloat16* __restrict__ Bl,
              const float* __restrict__ bias, float* __restrict__ C, float alpha,
              __nv_bfloat16* __restrict__ ohi, __nv_bfloat16* __restrict__ olo)
{
    gemm_core(Ah, Al, Bh, Bl, bias, C, alpha, ohi, olo);
}

struct G3Params {
    const __nv_bfloat16* Bh[3]; const __nv_bfloat16* Bl[3];
    const float* bias[3];
    __nv_bfloat16* oh[3]; __nv_bfloat16* ol[3];
    float alpha[3];
};
__global__ __launch_bounds__(256, 1)
void mma_gemm3(const __nv_bfloat16* __restrict__ Ah, const __nv_bfloat16* __restrict__ Al,
               G3Params p)
{
    const int z = blockIdx.z;
    gemm_core(Ah, Al, p.Bh[z], p.Bl[z], p.bias[z], nullptr, p.alpha[z], p.oh[z], p.ol[z]);
}

// ---------------------------------------------------------------------------
// w2_gemm: c2[(b2*1024+q)*1024 + h2*64 + n] = A2[slot*1024+q, :] . Rvt[n, :]
// A2 = (A/l) bf16 split [65536 x 320]; Rvt = relv^T bf16 split [64 x 320].
// CTA tile 128m x 64n; K = 320 (5 chunks of 64). B loaded fully once (80KB);
// A double-buffered (2 x 32KB). 256 threads, warps 4m x 2n (32x32).
// ---------------------------------------------------------------------------
#define W2_BOFF  0
#define W2_AOFF  81920
#define W2_SMEM  (81920 + 2 * 32768)   // 147456

__global__ __launch_bounds__(256, 1)
void w2_gemm(const __nv_bfloat16* __restrict__ A2h, const __nv_bfloat16* __restrict__ A2l,
             const __nv_bfloat16* __restrict__ Rvh, const __nv_bfloat16* __restrict__ Rvl,
             float* __restrict__ c2)
{
    extern __shared__ char smem[];
    const uint32_t sb = smem_to_u32(smem);
    const int tid = threadIdx.x;
    const int wid = tid >> 5, lane = tid & 31;
    const int wm = wid >> 1, wn = wid & 1;
    const int m0 = blockIdx.x * 128;
    const int arow = lane & 15, achk = lane >> 4;

    auto issueA = [&](int stage, int c) {
        const uint32_t base = sb + W2_AOFF + stage * 32768;
#pragma unroll
        for (int g = 0; g < 4; g++) {
            const int gi = g * 256 + tid;           // 0..1023
            const int row = gi >> 3, gc = gi & 7;
            const uint32_t bo = row * 128 + gc * 16;
            const uint32_t sw = bo ^ ((bo >> 3) & 0x70);
            const size_t off = (size_t)(m0 + row) * ASTRIDE + c * 64 + gc * 8;
            cpasync16(base + sw,         A2h + off);
            cpasync16(base + 16384 + sw, A2l + off);
        }
    };

    // B full (5 chunks) + A0 in group 0; A1 in group 1
#pragma unroll
    for (int c = 0; c < 5; c++) {
#pragma unroll
        for (int g = 0; g < 2; g++) {
            const int gi = g * 256 + tid;           // 0..511
            const int row = gi >> 3, gc = gi & 7;
            const uint32_t bo = row * 128 + gc * 16;
            const uint32_t sw = bo ^ ((bo >> 3) & 0x70);
            const size_t off = (size_t)row * ASTRIDE + c * 64 + gc * 8;
            cpasync16(sb + c * 16384 + sw,        Rvh + off);
            cpasync16(sb + c * 16384 + 8192 + sw, Rvl + off);
        }
    }
    issueA(0, 0);
    CP_COMMIT();
    issueA(1, 1);
    CP_COMMIT();

    float acc[2][4][4];
#pragma unroll
    for (int f = 0; f < 2; f++)
#pragma unroll
        for (int nf = 0; nf < 4; nf++)
#pragma unroll
            for (int e = 0; e < 4; e++) acc[f][nf][e] = 0.f;

    for (int c = 0; c < 5; c++) {
        if (c < 4) { CP_WAIT(1); } else { CP_WAIT(0); }
        __syncthreads();
        const uint32_t stA = sb + W2_AOFF + (c & 1) * 32768;
        const uint32_t stB = sb + c * 16384;
#pragma unroll
        for (int kk = 0; kk < 4; kk++) {
            const int chS = (kk * 2 + achk) ^ (arow & 7);
            uint32_t ah[2][4], al[2][4], bh[2][4], bl[2][4];
#pragma unroll
            for (int f = 0; f < 2; f++) {
                const uint32_t ra = stA + (uint32_t)(wm * 32 + f * 16 + arow) * 128 + chS * 16;
                ldsm4(ah[f], ra);
                ldsm4(al[f], ra + 16384);
            }
#pragma unroll
            for (int nb = 0; nb < 2; nb++) {
                const uint32_t rb = stB + (uint32_t)(wn * 32 + nb * 16 + arow) * 128 + chS * 16;
                ldsm4(bh[nb], rb);
                ldsm4(bl[nb], rb + 8192);
            }
#pragma unroll
            for (int f = 0; f < 2; f++)
#pragma unroll
                for (int nb = 0; nb < 2; nb++)
#pragma unroll
                    for (int h = 0; h < 2; h++) {
                        float* cc = acc[f][nb * 2 + h];
                        mma16816(cc, ah[f], bh[nb][h], bh[nb][h + 2]);
                        mma16816(cc, ah[f], bl[nb][h], bl[nb][h + 2]);
                        mma16816(cc, al[f], bh[nb][h], bh[nb][h + 2]);
                    }
        }
        __syncthreads();
        if (c + 2 < 5) { issueA(c & 1, c + 2); CP_COMMIT(); }
    }

    const int gid = lane >> 2, tig = lane & 3;
#pragma unroll
    for (int f = 0; f < 2; f++) {
        const int m = m0 + wm * 32 + f * 16 + gid;
        const int slot = m >> 10, q = m & 1023;
        const int b2 = slot & 3, h2 = slot >> 2;      // sigma^-1(slot)
#pragma unroll
        for (int nb = 0; nb < 2; nb++)
#pragma unroll
            for (int h = 0; h < 2; h++) {
                const int n = wn * 32 + nb * 16 + h * 8 + tig * 2;
                const float* cc = acc[f][nb * 2 + h];
                *(float2*)&c2[((size_t)(b2 * 1024 + q)) * EDIM + h2 * 64 + n] =
                    make_float2(cc[0], cc[1]);
                *(float2*)&c2[((size_t)(b2 * 1024 + q + 8)) * EDIM + h2 * 64 + n] =
                    make_float2(cc[2], cc[3]);
            }
    }
}

// ---------------------------------------------------------------------------
// Bias table via mma, r-tiles looped in-CTA (round 12, unchanged)
// ---------------------------------------------------------------------------
#define BIAS_SMEM 49152
__global__ __launch_bounds__(128, 1)
void bias_mma(const __nv_bfloat16* __restrict__ Qbh, const __nv_bfloat16* __restrict__ Qbl,
              const __nv_bfloat16* __restrict__ Rh, const __nv_bfloat16* __restrict__ Rl,
              float* __restrict__ Bt)
{
    extern __shared__ char smem[];
    const uint32_t sb = smem_to_u32(smem);
    const int jslot = blockIdx.y;
    const int bb = jslot >> 4, hh = jslot & 15;
    const int q0 = blockIdx.x * 64;
    const int tid = threadIdx.x, wid = tid >> 5, lane = tid & 31;
    const int wm = wid >> 1, wn = wid & 1;
    const int arow = lane & 15, ahalf = lane >> 4;

    auto issueR = [&](int stg, int rt) {
        const uint32_t base = sb + 16384 + stg * 16384;
        const int r0 = rt * 64;
#pragma unroll
        for (int g = 0; g < 4; g++) {
            const int i = g * 128 + tid;
            const int row = i >> 3, c = i & 7;
            const uint32_t sw = (uint32_t)row * 128 + (uint32_t)((c ^ (row & 7)) * 16);
            const size_t ro = (size_t)(r0 + row) * 64 + c * 8;
            cpasync16(base + sw,        Rh + ro);
            cpasync16(base + 8192 + sw, Rl + ro);
        }
    };

#pragma unroll
    for (int g = 0; g < 4; g++) {
        const int i = g * 128 + tid;
        const int row = i >> 3, c = i & 7;
        const uint32_t sw = (uint32_t)row * 128 + (uint32_t)((c ^ (row & 7)) * 16);
        const size_t qo = (size_t)(bb * 1024 + q0 + row) * EDIM + hh * 64 + c * 8;
        cpasync16(sb + sw,        Qbh + qo);
        cpasync16(sb + 8192 + sw, Qbl + qo);
    }
    issueR(0, 0);
    CP_COMMIT();

    uint32_t qh[4][2][4], qlr[4][2][4];
    bool qloaded = false;
    const int gid = lane >> 2, tig = lane & 3;
    float* btj = Bt + (size_t)jslot * 1024 * RSTR;

    for (int rt = 0; rt < 5; rt++) {
        if (rt + 1 < 5) { issueR((rt + 1) & 1, rt + 1); CP_COMMIT(); }
        if (rt < 4) { CP_WAIT(1); } else { CP_WAIT(0); }
        __syncthreads();

        if (!qloaded) {
            qloaded = true;
#pragma unroll
            for (int dd = 0; dd < 4; dd++)
#pragma unroll
                for (int mf = 0; mf < 2; mf++) {
                    const int row = wm * 32 + mf * 16 + arow;
                    const uint32_t addr = sb + (uint32_t)row * 128 +
                                          (uint32_t)(((dd * 2 + ahalf) ^ (row & 7)) * 16);
                    ldsm4(qh[dd][mf], addr);
                    ldsm4(qlr[dd][mf], addr + 8192);
                }
        }

        const uint32_t rbuf = sb + 16384 + (rt & 1) * 16384;
        float s[2][4][4];
#pragma unroll
        for (int mf = 0; mf < 2; mf++)
#pragma unroll
            for (int nf = 0; nf < 4; nf++)
#pragma unroll
                for (int e = 0; e < 4; e++) s[mf][nf][e] = 0.f;

#pragma unroll
        for (int dd = 0; dd < 4; dd++) {
            uint32_t bh[2][4], bl[2][4];
#pragma unroll
            for (int ng = 0; ng < 2; ng++) {
                const int row = wn * 32 + ng * 16 + arow;
                const uint32_t addr = rbuf + (uint32_t)row * 128 +
                                      (uint32_t)(((dd * 2 + ahalf) ^ (row & 7)) * 16);
                ldsm4(bh[ng], addr);
                ldsm4(bl[ng], addr + 8192);
            }
#pragma unroll
            for (int mf = 0; mf < 2; mf++)
#pragma unroll
                for (int ng = 0; ng < 2; ng++)
#pragma unroll
                    for (int h = 0; h < 2; h++) {
                        float* cc = s[mf][ng * 2 + h];
                        mma16816(cc, qh[dd][mf], bh[ng][h], bh[ng][h + 2]);
                        mma16816(cc, qh[dd][mf], bl[ng][h], bl[ng][h + 2]);
                        mma16816(cc, qlr[dd][mf], bh[ng][h], bh[ng][h + 2]);
                    }
        }
        __syncthreads();

        const int r0 = rt * 64;
#pragma unroll
        for (int mf = 0; mf < 2; mf++) {
            const int q = q0 + wm * 32 + mf * 16 + gid;
#pragma unroll
            for (int nf = 0; nf < 4; nf++) {
                const int r = r0 + wn * 32 + nf * 8 + tig * 2;
                const float* cc = s[mf][nf];
                if (r < 257) {
                    btj[(size_t)q * RSTR + r]       = cc[0];
                    btj[(size_t)(q + 8) * RSTR + r] = cc[2];
                }
                if (r + 1 < 257) {
                    btj[(size_t)q * RSTR + r + 1]       = cc[1];
                    btj[(size_t)(q + 8) * RSTR + r + 1] = cc[3];
                }
            }
        }
    }
}

// ---------------------------------------------------------------------------
// Fused relative attention, 32-row q-tile, 2 CTAs/SM, K/V single bf16.
// Epilogue writes w1 and the normalized bucket matrix A/l (bf16 split).
// smem: Qh[0,4K) Ql[4K,8K) | 2 stages @8K+s*16K {Kh 8K, Vh 8K} |
//   lsum @40960 | Aa[32][260] @41984 -> total 75264
// ---------------------------------------------------------------------------
#define ASTG 16384
#define ATT_SMEM 75264

__global__ __launch_bounds__(256, 2)
void attn2(const __nv_bfloat16* __restrict__ Qh_, const __nv_bfloat16* __restrict__ Ql_,
           const __nv_bfloat16* __restrict__ Kh_, const __nv_bfloat16* __restrict__ Vh_,
           const float* __restrict__ Bt, float* __restrict__ c1,
           __nv_bfloat16* __restrict__ A2h, __nv_bfloat16* __restrict__ A2l)
{
    extern __shared__ char smem[];
    const uint32_t sb = smem_to_u32(smem);
    float* lsum = (float*)(smem + 40960);
    float* Aa   = (float*)(smem + 41984);

    const int slot = blockIdx.y;
    const int q0 = blockIdx.x * 32;
    const int bb = slot >> 4, hh = slot & 15;
    const int jsrc = ((slot & 15) << 2) | (slot >> 4);   // sigma(slot)
    const int tid = threadIdx.x, wid = tid >> 5, lane = tid & 31;
    const int wm = wid >> 2, wn = wid & 3;               // 2(m) x 4(n)
    const int gid = lane >> 2, tig = lane & 3;
    const int arow = lane & 15, ahalf = lane >> 4;

    for (int f = tid; f < 32 * RSTR; f += 256) Aa[f] = 0.f;
    if (tid < 32) lsum[tid] = 0.f;

    auto issueKV = [&](int stg, int kt) {
        const uint32_t base = sb + 8192 + stg * ASTG;
        const int k0 = kt * 64;
#pragma unroll
        for (int g = 0; g < 2; g++) {
            const int i = g * 256 + tid;        // 0..511
            const int row = i >> 3, c = i & 7;
            const uint32_t sw = (uint32_t)row * 128 + (uint32_t)((c ^ (row & 7)) * 16);
            const size_t go = (size_t)(bb * 1024 + k0 + row) * EDIM + hh * 64 + c * 8;
            cpasync16(base + sw,        Kh_ + go);
            cpasync16(base + 8192 + sw, Vh_ + go);
        }
    };

    // group 0: Q(32 rows, hi+lo) + KV0 ; group 1: KV1
    {
        const int i = tid;                      // 0..255
        const int row = i >> 3, c = i & 7;
        const uint32_t sw = (uint32_t)row * 128 + (uint32_t)((c ^ (row & 7)) * 16);
        const size_t go = (size_t)(bb * 1024 + q0 + row) * EDIM + hh * 64 + c * 8;
        cpasync16(sb + sw,        Qh_ + go);
        cpasync16(sb + 4096 + sw, Ql_ + go);
    }
    issueKV(0, 0);
    CP_COMMIT();
    issueKV(1, 1);
    CP_COMMIT();

    float o[8][4];
#pragma unroll
    for (int nf = 0; nf < 8; nf++)
#pragma unroll
        for (int e = 0; e < 4; e++) o[nf][e] = 0.f;

    const float* btq = Bt + (size_t)jsrc * 1024 * RSTR + (size_t)q0 * RSTR;
    const int row0l = wm * 16 + gid, row1l = row0l + 8;   // 0..31

    const float bc0_lo = __ldg(&btq[(size_t)row0l * RSTR + 0]);
    const float bc0_hi = __ldg(&btq[(size_t)row0l * RSTR + 256]);
    const float bc1_lo = __ldg(&btq[(size_t)row1l * RSTR + 0]);
    const float bc1_hi = __ldg(&btq[(size_t)row1l * RSTR + 256]);
    float ls0 = 0.f, ls1 = 0.f, lo0 = 0.f, lo1 = 0.f, hi0 = 0.f, hi1 = 0.f;

    uint32_t qfh[4][4], qfl[4][4];   // hoisted Q fragments

    for (int kt = 0; kt < 16; kt++) {
        if (kt < 15) { CP_WAIT(1); } else { CP_WAIT(0); }
        __syncthreads();
        if (kt == 0) {
#pragma unroll
            for (int dd = 0; dd < 4; dd++) {
                const int row = wm * 16 + arow;
                const uint32_t qa = sb + (uint32_t)row * 128 +
                                    (uint32_t)(((dd * 2 + ahalf) ^ (row & 7)) * 16);
                ldsm4(qfh[dd], qa);
                ldsm4(qfl[dd], qa + 4096);
            }
        }
        const uint32_t st = sb + 8192 + (kt & 1) * ASTG;
        const int k0 = kt * 64;
        const int delta = q0 - k0;

        // ---- S = (Qh+Ql) K^T  (K single bf16) ----
        float s[2][4];
        s[0][0] = s[0][1] = s[0][2] = s[0][3] = 0.f;
        s[1][0] = s[1][1] = s[1][2] = s[1][3] = 0.f;
#pragma unroll
        for (int dd = 0; dd < 4; dd++) {
            uint32_t kh[4];
            const int row = wn * 16 + arow;
            const uint32_t ka = st + (uint32_t)row * 128 +
                                (uint32_t)(((dd * 2 + ahalf) ^ (row & 7)) * 16);
            ldsm4(kh, ka);
#pragma unroll
            for (int h = 0; h < 2; h++) {
                mma16816(s[h], qfh[dd], kh[h], kh[h + 2]);
                mma16816(s[h], qfl[dd], kh[h], kh[h + 2]);
            }
        }

        // ---- bias + exp2 + row sums (+ buckets) ----
        float rs0 = 0.f, rs1 = 0.f;
        const bool clampHi = (delta >= 192), clampLo = (delta <= -160);
        if (clampHi || clampLo) {
            const float b0 = clampHi ? bc0_hi : bc0_lo;
            const float b1 = clampHi ? bc1_hi : bc1_lo;
#pragma unroll
            for (int h = 0; h < 2; h++)
#pragma unroll
                for (int e = 0; e < 4; e++) {
                    const float p = exp2f(s[h][e] + ((e >= 2) ? b1 : b0));
                    s[h][e] = p;
                    if (e >= 2) rs1 += p; else rs0 += p;
                }
            if (clampHi) { hi0 += rs0; hi1 += rs1; }
            else         { lo0 += rs0; lo1 += rs1; }
        } else {
#pragma unroll
            for (int h = 0; h < 2; h++) {
                const int kg = k0 + wn * 16 + h * 8 + tig * 2;
#pragma unroll
                for (int e = 0; e < 4; e++) {
                    const int ql2 = (e >= 2) ? row1l : row0l;
                    const int dist = (q0 + ql2) - (kg + (e & 1));
                    const int r = dist < -128 ? 0 : (dist > 128 ? 256 : dist + 128);
                    const float p = exp2f(s[h][e] + __ldg(&btq[(size_t)ql2 * RSTR + r]));
                    s[h][e] = p;
                    if (e >= 2) rs1 += p; else rs0 += p;
                }
            }
#pragma unroll
            for (int h = 0; h < 2; h++) {
                const int kg = k0 + wn * 16 + h * 8 + tig * 2;
#pragma unroll
                for (int e = 0; e < 4; e++) {
                    const int ql2 = (e >= 2) ? row1l : row0l;
                    const int dist = (q0 + ql2) - (kg + (e & 1));
                    const int r = dist < -128 ? 0 : (dist > 128 ? 256 : dist + 128);
                    atomicAdd(&Aa[ql2 * RSTR + r], s[h][e]);
                }
            }
        }
        ls0 += rs0; ls1 += rs1;

        // ---- P -> bf16 split A-frag ----
        uint32_t pah[4], pal[4];
#pragma unroll
        for (int a = 0; a < 4; a++) {
            const int h = a >> 1, eb = (a & 1) * 2;
            const float p0 = s[h][eb], p1 = s[h][eb + 1];
            const __nv_bfloat16 h0 = __float2bfloat16(p0), h1 = __float2bfloat16(p1);
            pah[a] = pack_bf2(h0, h1);
            pal[a] = pack_bf2(__float2bfloat16(p0 - __bfloat162float(h0)),
                              __float2bfloat16(p1 - __bfloat162float(h1)));
        }

        // ---- O += (Ph+Pl) V  (V single bf16) ----
#pragma unroll
        for (int g = 0; g < 4; g++) {
            uint32_t vh[4];
            const int krow = wn * 16 + arow;
            const uint32_t va = st + 8192 + (uint32_t)krow * 128 +
                                (uint32_t)(((g * 2 + ahalf) ^ (krow & 7)) * 16);
            ldsm4t(vh, va);
#pragma unroll
            for (int h = 0; h < 2; h++) {
                float* cc = o[g * 2 + h];
                mma16816(cc, pah, vh[h * 2], vh[h * 2 + 1]);
                mma16816(cc, pal, vh[h * 2], vh[h * 2 + 1]);
            }
        }
        __syncthreads();
        if (kt + 2 < 16) { issueKV(kt & 1, kt + 2); CP_COMMIT(); }
    }

    // ---- flush deferred reductions ----
    ls0 += __shfl_xor_sync(0xffffffffu, ls0, 1); ls0 += __shfl_xor_sync(0xffffffffu, ls0, 2);
    ls1 += __shfl_xor_sync(0xffffffffu, ls1, 1); ls1 += __shfl_xor_sync(0xffffffffu, ls1, 2);
    lo0 += __shfl_xor_sync(0xffffffffu, lo0, 1); lo0 += __shfl_xor_sync(0xffffffffu, lo0, 2);
    lo1 += __shfl_xor_sync(0xffffffffu, lo1, 1); lo1 += __shfl_xor_sync(0xffffffffu, lo1, 2);
    hi0 += __shfl_xor_sync(0xffffffffu, hi0, 1); hi0 += __shfl_xor_sync(0xffffffffu, hi0, 2);
    hi1 += __shfl_xor_sync(0xffffffffu, hi1, 1); hi1 += __shfl_xor_sync(0xffffffffu, hi1, 2);
    if (tig == 0) {
        atomicAdd(&lsum[row0l], ls0);
        atomicAdd(&lsum[row1l], ls1);
        atomicAdd(&Aa[row0l * RSTR + 0], lo0);
        atomicAdd(&Aa[row1l * RSTR + 0], lo1);
        atomicAdd(&Aa[row0l * RSTR + 256], hi0);
        atomicAdd(&Aa[row1l * RSTR + 256], hi1);
    }

    // ---- epilogue: O partials to smem; invert lsum ----
    float* red = (float*)(smem + 8192);   // 3 blocks of 32x68 floats (stage area)
    if (wn > 0) {
        float* rb = red + (size_t)(wn - 1) * 32 * 68;
#pragma unroll
        for (int g = 0; g < 8; g++) {
            const int col = g * 8 + tig * 2;
            *(float2*)&rb[row0l * 68 + col] = make_float2(o[g][0], o[g][1]);
            *(float2*)&rb[row1l * 68 + col] = make_float2(o[g][2], o[g][3]);
        }
    }
    __syncthreads();                 // atomics + red writes complete
    if (tid < 32) lsum[tid] = 1.f / lsum[tid];
    __syncthreads();

    // ---- w1: reduce 4 wn partials, normalize, write ----
    if (wn == 0) {
        const float inv0 = lsum[row0l];
        const float inv1 = lsum[row1l];
#pragma unroll
        for (int g = 0; g < 8; g++) {
            const int col = g * 8 + tig * 2;
            float a0 = o[g][0], a1 = o[g][1], a2 = o[g][2], a3 = o[g][3];
#pragma unroll
            for (int wv = 0; wv < 3; wv++) {
                const float* rb = red + (size_t)wv * 32 * 68;
                const float2 r0 = *(const float2*)&rb[row0l * 68 + col];
                const float2 r1 = *(const float2*)&rb[row1l * 68 + col];
                a0 += r0.x; a1 += r0.y; a2 += r1.x; a3 += r1.y;
            }
            float2 v0 = make_float2(a0 * inv0, a1 * inv0);
            float2 v1 = make_float2(a2 * inv1, a3 * inv1);
            *(float2*)&c1[(size_t)(bb * 1024 + q0 + row0l) * EDIM + hh * 64 + col] = v0;
            *(float2*)&c1[(size_t)(bb * 1024 + q0 + row1l) * EDIM + hh * 64 + col] = v1;
        }
    }

    // ---- write A2 = (A/l) bf16 split, rows padded to ASTRIDE ----
    {
        __nv_bfloat16* a2h = A2h + ((size_t)slot * 1024 + q0) * ASTRIDE;
        __nv_bfloat16* a2l = A2l + ((size_t)slot * 1024 + q0) * ASTRIDE;
        for (int i = tid; i < 32 * (ASTRIDE / 2); i += 256) {
            const int row = i / (ASTRIDE / 2);
            const int cp2 = (i % (ASTRIDE / 2)) * 2;
            const float il = lsum[row];
            const float a0 = (cp2     < RSTR) ? Aa[row * RSTR + cp2]     * il : 0.f;
            const float a1 = (cp2 + 1 < RSTR) ? Aa[row * RSTR + cp2 + 1] * il : 0.f;
            const __nv_bfloat16 h0 = __float2bfloat16(a0), h1 = __float2bfloat16(a1);
            *(uint32_t*)(a2h + (size_t)row * ASTRIDE + cp2) = pack_bf2(h0, h1);
            *(uint32_t*)(a2l + (size_t)row * ASTRIDE + cp2) =
                pack_bf2(__float2bfloat16(a0 - __bfloat162float(h0)),
                         __float2bfloat16(a1 - __bfloat162float(h1)));
        }
    }
}

// ---------------------------------------------------------------------------
extern "C" void kernel_launch(void* const* d_in, const int* in_sizes, int n_in,
                              void* d_out, int out_size)
{
    const float* X    = (const float*)d_in[0];
    const float* Wq   = (const float*)d_in[1];
    const float* bq   = (const float*)d_in[2];
    const float* Wk   = (const float*)d_in[3];
    const float* bk   = (const float*)d_in[4];
    const float* Wv   = (const float*)d_in[5];
    const float* bv   = (const float*)d_in[6];
    const float* Wo   = (const float*)d_in[7];
    const float* bo   = (const float*)d_in[8];
    const float* relk = (const float*)d_in[9];
    const float* relv = (const float*)d_in[10];
    float* out = (float*)d_out;

    float *pB, *pc1, *pc2;
    cudaGetSymbolAddress((void**)&pB,  g_B);
    cudaGetSymbolAddress((void**)&pc1, g_c1);
    cudaGetSymbolAddress((void**)&pc2, g_c2);
    __nv_bfloat16 *pXh, *pXl, *pWqh, *pWql, *pWkh, *pWkl, *pWvh, *pWvl, *pWoh, *pWol;
    __nv_bfloat16 *pQbh, *pQbl, *pKbh, *pVbh, *pRkh, *pRkl, *pRvh, *pRvl, *pA2h, *pA2l;
    cudaGetSymbolAddress((void**)&pXh,  g_Xh);
    cudaGetSymbolAddress((void**)&pXl,  g_Xl);
    cudaGetSymbolAddress((void**)&pWqh, g_Wqh);
    cudaGetSymbolAddress((void**)&pWql, g_Wql);
    cudaGetSymbolAddress((void**)&pWkh, g_Wkh);
    cudaGetSymbolAddress((void**)&pWkl, g_Wkl);
    cudaGetSymbolAddress((void**)&pWvh, g_Wvh);
    cudaGetSymbolAddress((void**)&pWvl, g_Wvl);
    cudaGetSymbolAddress((void**)&pWoh, g_Woh);
    cudaGetSymbolAddress((void**)&pWol, g_Wol);
    cudaGetSymbolAddress((void**)&pQbh, g_Qbh);
    cudaGetSymbolAddress((void**)&pQbl, g_Qbl);
    cudaGetSymbolAddress((void**)&pKbh, g_Kbh);
    cudaGetSymbolAddress((void**)&pVbh, g_Vbh);
    cudaGetSymbolAddress((void**)&pRkh, g_Rkh);
    cudaGetSymbolAddress((void**)&pRkl, g_Rkl);
    cudaGetSymbolAddress((void**)&pRvh, g_Rvh);
    cudaGetSymbolAddress((void**)&pRvl, g_Rvl);
    cudaGetSymbolAddress((void**)&pA2h, g_A2h);
    cudaGetSymbolAddress((void**)&pA2l, g_A2l);

    CvtParams cp;
    cp.X = X; cp.Wq = Wq; cp.Wk = Wk; cp.Wv = Wv; cp.Wo = Wo; cp.relk = relk; cp.relv = relv;
    cp.Xh = pXh; cp.Xl = pXl;
    cp.Wqh = pWqh; cp.Wql = pWql; cp.Wkh = pWkh; cp.Wkl = pWkl;
    cp.Wvh = pWvh; cp.Wvl = pWvl; cp.Woh = pWoh; cp.Wol = pWol;
    cp.Rkh = pRkh; cp.Rkl = pRkl; cp.Rvh = pRvh; cp.Rvl = pRvl;
    cvt_all<<<8192 + 20 + 20, 256>>>(cp);

    cudaFuncSetAttribute(mma_gemm,  cudaFuncAttributeMaxDynamicSharedMemorySize, GSMEM);
    cudaFuncSetAttribute(mma_gemm3, cudaFuncAttributeMaxDynamicSharedMemorySize, GSMEM);

    // Q alpha = 0.125/ln2: scores and bias table in log2 units -> exp2f.
    G3Params p;
    p.Bh[0] = pWqh; p.Bl[0] = pWql; p.bias[0] = bq; p.oh[0] = pQbh; p.ol[0] = pQbl;
    p.alpha[0] = 0.125f * 1.4426950408889634f;
    p.Bh[1] = pWkh; p.Bl[1] = pWkl; p.bias[1] = bk; p.oh[1] = pKbh; p.ol[1] = nullptr;
    p.alpha[1] = 1.0f;
    p.Bh[2] = pWvh; p.Bl[2] = pWvl; p.bias[2] = bv; p.oh[2] = pVbh; p.ol[2] = nullptr;
    p.alpha[2] = 1.0f;
    mma_gemm3<<<dim3(EDIM / 128, MROWS / 128, 3), 256, GSMEM>>>(pXh, pXl, p);

    cudaFuncSetAttribute(bias_mma, cudaFuncAttributeMaxDynamicSharedMemorySize, BIAS_SMEM);
    bias_mma<<<dim3(16, 64), 128, BIAS_SMEM>>>(pQbh, pQbl, pRkh, pRkl, pB);

    cudaFuncSetAttribute(attn2, cudaFuncAttributeMaxDynamicSharedMemorySize, ATT_SMEM);
    attn2<<<dim3(32, 64), 256, ATT_SMEM>>>(pQbh, pQbl, pKbh, pVbh,
                                           pB, pc1, pA2h, pA2l);

    cudaFuncSetAttribute(w2_gemm, cudaFuncAttributeMaxDynamicSharedMemorySize, W2_SMEM);
    w2_gemm<<<512, 256, W2_SMEM>>>(pA2h, pA2l, pRvh, pRvl, pc2);

    cvt_add_split<<<MROWS * EDIM / 1024, 256>>>(pc1, pc2, pXh, pXl);
    mma_gemm<<<dim3(EDIM / 128, MROWS / 128), 256, GSMEM>>>(pXh, pXl, pWoh, pWol, bo, out,
                                                            1.0f, nullptr, nullptr);
}